// round 6
// baseline (speedup 1.0000x reference)
#include <cuda_runtime.h>
#include <cuda_bf16.h>
#include <math.h>
#include <stdint.h>

#define B_ 4
#define S_ 2048
#define H_ 16
#define D_ 64
#define E_ 1024
#define E3_ 3072
#define BH_ (B_*H_)
#define M_ (B_*S_)   // 8192

// ---------------- device-global scratch (allocation-free rule) ----------------
__device__ __nv_bfloat16 g_hidh[M_*E_],  g_hidl[M_*E_];
__device__ __nv_bfloat16 g_wqh[E3_*E_],  g_wql[E3_*E_];     // qkv_w^T split [N][K]
__device__ __nv_bfloat16 g_woh[E_*E_],   g_wol[E_*E_];      // wo_w^T split  [N][K]
__device__ __nv_bfloat16 g_qh[BH_*S_*D_], g_ql[BH_*S_*D_];  // q (pre-scaled 0.125)
__device__ __nv_bfloat16 g_kh[BH_*S_*D_], g_kl[BH_*S_*D_];
__device__ __nv_bfloat16 g_vh[BH_*S_*D_], g_vl[BH_*S_*D_];
__device__ __nv_bfloat16 g_ah[M_*E_],    g_al[M_*E_];       // attn out split

// ---------------- helpers ----------------
__device__ __forceinline__ void ldsm4(uint32_t* r, uint32_t addr) {
    asm volatile("ldmatrix.sync.aligned.m8n8.x4.shared.b16 {%0,%1,%2,%3}, [%4];"
                 : "=r"(r[0]), "=r"(r[1]), "=r"(r[2]), "=r"(r[3]) : "r"(addr));
}
__device__ __forceinline__ void ldsm4t(uint32_t* r, uint32_t addr) {
    asm volatile("ldmatrix.sync.aligned.m8n8.x4.trans.shared.b16 {%0,%1,%2,%3}, [%4];"
                 : "=r"(r[0]), "=r"(r[1]), "=r"(r[2]), "=r"(r[3]) : "r"(addr));
}
__device__ __forceinline__ void mma16816(float* c, const uint32_t* a, const uint32_t* b) {
    asm volatile("mma.sync.aligned.m16n8k16.row.col.f32.bf16.bf16.f32 "
                 "{%0,%1,%2,%3}, {%4,%5,%6,%7}, {%8,%9}, {%0,%1,%2,%3};"
                 : "+f"(c[0]), "+f"(c[1]), "+f"(c[2]), "+f"(c[3])
                 : "r"(a[0]), "r"(a[1]), "r"(a[2]), "r"(a[3]),
                   "r"(b[0]), "r"(b[1]));
}
__device__ __forceinline__ void cpasync16(uint32_t dst, const void* src) {
    asm volatile("cp.async.cg.shared.global [%0], [%1], 16;" :: "r"(dst), "l"(src));
}
#define CP_COMMIT() asm volatile("cp.async.commit_group;")
#define CP_WAIT(N)  asm volatile("cp.async.wait_group %0;" :: "n"(N))

__device__ __forceinline__ void fsplit2(float a, float b, uint32_t& hi, uint32_t& lo) {
    __nv_bfloat162 h2 = __float22bfloat162_rn(make_float2(a, b));
    float ra = a - __bfloat162float(h2.x);
    float rb = b - __bfloat162float(h2.y);
    __nv_bfloat162 l2 = __float22bfloat162_rn(make_float2(ra, rb));
    hi = *reinterpret_cast<uint32_t*>(&h2);
    lo = *reinterpret_cast<uint32_t*>(&l2);
}

// ---------------- split kernels ----------------
__global__ void split4(const float* __restrict__ x,
                       __nv_bfloat16* __restrict__ hi, __nv_bfloat16* __restrict__ lo, int n)
{
    int i = (blockIdx.x * blockDim.x + threadIdx.x) * 4;
    if (i >= n) return;
    float4 v = *(const float4*)(x + i);
    uint32_t h0, l0, h1, l1;
    fsplit2(v.x, v.y, h0, l0);
    fsplit2(v.z, v.w, h1, l1);
    uint2 hh; hh.x = h0; hh.y = h1;
    uint2 ll; ll.x = l0; ll.y = l1;
    *(uint2*)(hi + i) = hh;
    *(uint2*)(lo + i) = ll;
}

// W [K][N] f32 -> Th/Tl [N][K] bf16
__global__ void tsplit(const float* __restrict__ W,
                       __nv_bfloat16* __restrict__ Th, __nv_bfloat16* __restrict__ Tl,
                       int K, int N)
{
    __shared__ float t[32][33];
    const int tx = threadIdx.x, ty = threadIdx.y;
    const int n0 = blockIdx.x * 32, k0 = blockIdx.y * 32;
#pragma unroll
    for (int j = 0; j < 4; j++)
        t[ty + j * 8][tx] = W[(size_t)(k0 + ty + j * 8) * N + n0 + tx];
    __syncthreads();
#pragma unroll
    for (int j = 0; j < 4; j++) {
        float v = t[tx][ty + j * 8];
        int n = n0 + ty + j * 8, k = k0 + tx;
        __nv_bfloat16 hv = __float2bfloat16(v);
        Th[(size_t)n * K + k] = hv;
        Tl[(size_t)n * K + k] = __float2bfloat16(v - __bfloat162float(hv));
    }
}

// ---------------- pipelined tensor-core GEMM: C = A @ Bt^T + bias -------------
// 2-stage cp.async double buffer, BK=64.  Stage layout (64KB):
//   Ah +0 | Al +16K | Bh +32K | Bl +48K ; stage 1 at +64K.
#define GSTAGE 65536
#define GEMM_SMEM (2*GSTAGE)

template<int EPI>
__global__ __launch_bounds__(256)
void mma_gemm(const __nv_bfloat16* __restrict__ Ah, const __nv_bfloat16* __restrict__ Al,
              const __nv_bfloat16* __restrict__ Bth, const __nv_bfloat16* __restrict__ Btl,
              const float* __restrict__ bias, float* __restrict__ C,
              int M, int N, int K)
{
    extern __shared__ char sm[];
    const uint32_t sb = (uint32_t)__cvta_generic_to_shared(sm);
    const int tid = threadIdx.x, lane = tid & 31, wid = tid >> 5;
    const int wm = wid >> 1, wn = wid & 1;
    const int bm = blockIdx.y * 128, bn = blockIdx.x * 128;

    float acc[2][8][4];
#pragma unroll
    for (int mi = 0; mi < 2; mi++)
#pragma unroll
        for (int nb = 0; nb < 8; nb++)
#pragma unroll
            for (int q = 0; q < 4; q++) acc[mi][nb][q] = 0.f;

    const int lr = (lane & 7) + ((lane >> 3) & 1) * 8;

    // per-thread load map (fixed across stages)
    const int l_row0 = tid >> 3, l_ch = tid & 7;
    const uint32_t l_soff = ((l_ch ^ (l_row0 & 7)) << 4);

    auto issue_stage = [&](int st, int kt) {
#pragma unroll
        for (int i = 0; i < 4; i++) {
            int row = l_row0 + i * 32;
            uint32_t soff = (uint32_t)st * GSTAGE + row * 128 + ((l_ch ^ (row & 7)) << 4);
            size_t ga = (size_t)(bm + row) * K + kt + l_ch * 8;
            size_t gb = (size_t)(bn + row) * K + kt + l_ch * 8;
            cpasync16(sb + soff,         Ah + ga);
            cpasync16(sb + 16384 + soff, Al + ga);
            cpasync16(sb + 32768 + soff, Bth + gb);
            cpasync16(sb + 49152 + soff, Btl + gb);
        }
        CP_COMMIT();
    };
    (void)l_soff;

    issue_stage(0, 0);

    int t = 0;
    for (int kt = 0; kt < K; kt += 64, t++) {
        const int cur = t & 1;
        const bool more = (kt + 64 < K);
        if (more) { issue_stage(cur ^ 1, kt + 64); CP_WAIT(1); }
        else      { CP_WAIT(0); }
        __syncthreads();

        const uint32_t cb = sb + (uint32_t)cur * GSTAGE;
#pragma unroll
        for (int kk = 0; kk < 4; kk++) {
            const int lc = kk * 2 + (lane >> 4);
            uint32_t afh[2][4], afl[2][4];
#pragma unroll
            for (int mi = 0; mi < 2; mi++) {
                int r = wm * 32 + mi * 16 + lr;
                uint32_t ad = cb + r * 128 + ((lc ^ (r & 7)) << 4);
                ldsm4(afh[mi], ad);
                ldsm4(afl[mi], ad + 16384);
            }
            uint32_t bfh[8][2], bfl[8][2], t4[4];
#pragma unroll
            for (int g = 0; g < 4; g++) {
                int r = wn * 64 + g * 16 + lr;
                uint32_t ad = cb + 32768 + r * 128 + ((lc ^ (r & 7)) << 4);
                ldsm4(t4, ad);
                bfh[2*g][0] = t4[0]; bfh[2*g][1] = t4[2];
                bfh[2*g+1][0] = t4[1]; bfh[2*g+1][1] = t4[3];
                ldsm4(t4, ad + 16384);
                bfl[2*g][0] = t4[0]; bfl[2*g][1] = t4[2];
                bfl[2*g+1][0] = t4[1]; bfl[2*g+1][1] = t4[3];
            }
#pragma unroll
            for (int mi = 0; mi < 2; mi++)
#pragma unroll
                for (int nb = 0; nb < 8; nb++) {
                    mma16816(acc[mi][nb], afh[mi], bfh[nb]);
                    mma16816(acc[mi][nb], afl[mi], bfh[nb]);
                    mma16816(acc[mi][nb], afh[mi], bfl[nb]);
                }
        }
        __syncthreads();
    }

    // epilogue
#pragma unroll
    for (int mi = 0; mi < 2; mi++) {
        const int rbase = bm + wm * 32 + mi * 16 + (lane >> 2);
#pragma unroll
        for (int nb = 0; nb < 8; nb++) {
            const int cc = bn + wn * 64 + nb * 8 + (lane & 3) * 2;
            const float b0 = bias[cc], b1 = bias[cc + 1];
#pragma unroll
            for (int hr = 0; hr < 2; hr++) {
                const int r = rbase + hr * 8;
                float v0 = acc[mi][nb][hr * 2 + 0] + b0;
                float v1 = acc[mi][nb][hr * 2 + 1] + b1;
                if (EPI == 1) {
                    const int bb = r >> 11, si = r & 2047;
                    const int sec = cc >> 10, win = cc & 1023;
                    const int hh = win >> 6, dd = win & 63;
                    __nv_bfloat16 *dh, *dl;
                    if (sec == 0) { v0 *= 0.125f; v1 *= 0.125f; dh = g_qh; dl = g_ql; }
                    else if (sec == 1) { dh = g_kh; dl = g_kl; }
                    else { dh = g_vh; dl = g_vl; }
                    uint32_t hi, lo;
                    fsplit2(v0, v1, hi, lo);
                    size_t off = (((size_t)bb * H_ + hh) * S_ + si) * D_ + dd;
                    *(uint32_t*)(dh + off) = hi;
                    *(uint32_t*)(dl + off) = lo;
                } else {
                    float2 v; v.x = v0; v.y = v1;
                    *(float2*)(C + (size_t)r * N + cc) = v;
                }
            }
        }
    }
}

// ---------------- flash attention, 8 warps / 128 queries, pipelined ----------
// smem: Qh 0 (16K) | Ql 16K | stages at 32K: per stage {Kh 0, Kl 8K, Vh 16K, Vl 24K}
//       (32KB/stage, 2 stages) | Mf[2][64] at 96K
#define ASTAGE 32768
#define A_STG0 32768
#define A_MF   (A_STG0 + 2*ASTAGE)
#define ATTN_SMEM (A_MF + 2*64*4)

__global__ __launch_bounds__(256)
void attn_mma(const int* __restrict__ mask)
{
    extern __shared__ char sm[];
    const uint32_t sb = (uint32_t)__cvta_generic_to_shared(sm);
    float* Mf = (float*)(sm + A_MF);   // [2][64]
    const int tid = threadIdx.x, lane = tid & 31, w = tid >> 5;
    const int qb = blockIdx.x * 128, bh = blockIdx.y;
    const int b = bh >> 4, h = bh & 15;
    const size_t base = (size_t)bh * S_ * D_;
    const int lr = (lane & 7) + ((lane >> 3) & 1) * 8;
    const int* mrow = mask + b * S_;

    auto issue_kv = [&](int st, int kt) {
        for (int i = tid; i < 512; i += 256) {
            int row = i >> 3, ch = i & 7;
            uint32_t soff = A_STG0 + (uint32_t)st * ASTAGE + row * 128 + ((ch ^ (row & 7)) << 4);
            size_t g = base + (size_t)(kt + row) * D_ + ch * 8;
            cpasync16(sb + soff,          g_kh + g);
            cpasync16(sb + soff + 8192,   g_kl + g);
            cpasync16(sb + soff + 16384,  g_vh + g);
            cpasync16(sb + soff + 24576,  g_vl + g);
        }
        if (tid < 64) Mf[st * 64 + tid] = mrow[kt + tid] ? 1.0f : 0.0f;
        CP_COMMIT();
    };

    issue_kv(0, 0);

    // stage Q tile (128 rows, hi/lo)
    for (int i = tid; i < 1024; i += 256) {
        int row = i >> 3, ch = i & 7;
        uint32_t soff = row * 128 + ((ch ^ (row & 7)) << 4);
        size_t g = base + (size_t)(qb + row) * D_ + ch * 8;
        *(uint4*)(sm + soff)         = *(const uint4*)(g_qh + g);
        *(uint4*)(sm + 16384 + soff) = *(const uint4*)(g_ql + g);
    }
    __syncthreads();

    uint32_t qfh[4][4], qfl[4][4];
#pragma unroll
    for (int kk = 0; kk < 4; kk++) {
        int r = w * 16 + lr;
        int c = kk * 2 + (lane >> 4);
        uint32_t ad = sb + r * 128 + ((c ^ (r & 7)) << 4);
        ldsm4(qfh[kk], ad);
        ldsm4(qfl[kk], ad + 16384);
    }

    float O[8][4];
#pragma unroll
    for (int nb = 0; nb < 8; nb++)
#pragma unroll
        for (int q = 0; q < 4; q++) O[nb][q] = 0.f;
    float m0 = -1e30f, m1 = -1e30f, l0 = 0.f, l1 = 0.f;

    for (int t = 0; t < S_ / 64; t++) {
        const int cur = t & 1;
        const bool more = (t + 1 < S_ / 64);
        if (more) { issue_kv(cur ^ 1, (t + 1) * 64); CP_WAIT(1); }
        else      { CP_WAIT(0); }
        __syncthreads();

        const uint32_t kb = sb + A_STG0 + (uint32_t)cur * ASTAGE;
        const float* mf = Mf + cur * 64;

        // S = Q K^T (Q pre-scaled by 0.125)
        float S[8][4];
#pragma unroll
        for (int nb = 0; nb < 8; nb++)
#pragma unroll
            for (int q = 0; q < 4; q++) S[nb][q] = 0.f;
#pragma unroll
        for (int kk = 0; kk < 4; kk++) {
            const int lc = kk * 2 + (lane >> 4);
            uint32_t bfh[8][2], bfl[8][2], t4[4];
#pragma unroll
            for (int g = 0; g < 4; g++) {
                int r = g * 16 + lr;
                uint32_t ad = kb + r * 128 + ((lc ^ (r & 7)) << 4);
                ldsm4(t4, ad);
                bfh[2*g][0] = t4[0]; bfh[2*g][1] = t4[2];
                bfh[2*g+1][0] = t4[1]; bfh[2*g+1][1] = t4[3];
                ldsm4(t4, ad + 8192);
                bfl[2*g][0] = t4[0]; bfl[2*g][1] = t4[2];
                bfl[2*g+1][0] = t4[1]; bfl[2*g+1][1] = t4[3];
            }
#pragma unroll
            for (int nb = 0; nb < 8; nb++) {
                mma16816(S[nb], qfh[kk], bfh[nb]);
                mma16816(S[nb], qfl[kk], bfh[nb]);
                mma16816(S[nb], qfh[kk], bfl[nb]);
            }
        }

        // mask + online softmax
        float mk0[8], mk1[8];
#pragma unroll
        for (int nb = 0; nb < 8; nb++) {
            int c = nb * 8 + (lane & 3) * 2;
            mk0[nb] = mf[c]; mk1[nb] = mf[c + 1];
        }
        float mx0 = -1e30f, mx1 = -1e30f;
#pragma unroll
        for (int nb = 0; nb < 8; nb++) {
            S[nb][0] = (mk0[nb] != 0.f) ? S[nb][0] : -1e30f;
            S[nb][1] = (mk1[nb] != 0.f) ? S[nb][1] : -1e30f;
            S[nb][2] = (mk0[nb] != 0.f) ? S[nb][2] : -1e30f;
            S[nb][3] = (mk1[nb] != 0.f) ? S[nb][3] : -1e30f;
            mx0 = fmaxf(mx0, fmaxf(S[nb][0], S[nb][1]));
            mx1 = fmaxf(mx1, fmaxf(S[nb][2], S[nb][3]));
        }
        mx0 = fmaxf(mx0, __shfl_xor_sync(0xffffffffu, mx0, 1));
        mx0 = fmaxf(mx0, __shfl_xor_sync(0xffffffffu, mx0, 2));
        mx1 = fmaxf(mx1, __shfl_xor_sync(0xffffffffu, mx1, 1));
        mx1 = fmaxf(mx1, __shfl_xor_sync(0xffffffffu, mx1, 2));
        const float mn0 = fmaxf(m0, mx0), mn1 = fmaxf(m1, mx1);
        const float a0 = __expf(m0 - mn0), a1 = __expf(m1 - mn1);
        m0 = mn0; m1 = mn1;
        float s0 = 0.f, s1 = 0.f;
#pragma unroll
        for (int nb = 0; nb < 8; nb++) {
            float p0 = __expf(S[nb][0] - mn0) * mk0[nb];
            float p1 = __expf(S[nb][1] - mn0) * mk1[nb];
            float p2 = __expf(S[nb][2] - mn1) * mk0[nb];
            float p3 = __expf(S[nb][3] - mn1) * mk1[nb];
            S[nb][0] = p0; S[nb][1] = p1; S[nb][2] = p2; S[nb][3] = p3;
            s0 += p0 + p1; s1 += p2 + p3;
        }
        s0 += __shfl_xor_sync(0xffffffffu, s0, 1);
        s0 += __shfl_xor_sync(0xffffffffu, s0, 2);
        s1 += __shfl_xor_sync(0xffffffffu, s1, 1);
        s1 += __shfl_xor_sync(0xffffffffu, s1, 2);
        l0 = l0 * a0 + s0; l1 = l1 * a1 + s1;
#pragma unroll
        for (int nb = 0; nb < 8; nb++) {
            O[nb][0] *= a0; O[nb][1] *= a0; O[nb][2] *= a1; O[nb][3] *= a1;
        }

        // O += P V   (P frags from score accumulators, V via ldmatrix.trans)
#pragma unroll
        for (int kk = 0; kk < 4; kk++) {
            uint32_t ph[4], pl[4];
            fsplit2(S[2*kk][0],   S[2*kk][1],   ph[0], pl[0]);
            fsplit2(S[2*kk][2],   S[2*kk][3],   ph[1], pl[1]);
            fsplit2(S[2*kk+1][0], S[2*kk+1][1], ph[2], pl[2]);
            fsplit2(S[2*kk+1][2], S[2*kk+1][3], ph[3], pl[3]);
            uint32_t vfh[8][2], vfl[8][2], t4[4];
#pragma unroll
            for (int g = 0; g < 4; g++) {
                int r = kk * 16 + lr;
                int c = g * 2 + (lane >> 4);
                uint32_t ad = kb + 16384 + r * 128 + ((c ^ (r & 7)) << 4);
                ldsm4t(t4, ad);
                vfh[2*g][0] = t4[0]; vfh[2*g][1] = t4[1];
                vfh[2*g+1][0] = t4[2]; vfh[2*g+1][1] = t4[3];
                ldsm4t(t4, ad + 8192);
                vfl[2*g][0] = t4[0]; vfl[2*g][1] = t4[1];
                vfl[2*g+1][0] = t4[2]; vfl[2*g+1][1] = t4[3];
            }
#pragma unroll
            for (int nb = 0; nb < 8; nb++) {
                mma16816(O[nb], ph, vfh[nb]);
                mma16816(O[nb], pl, vfh[nb]);
                mma16816(O[nb], ph, vfl[nb]);
            }
        }
        __syncthreads();
    }

    // epilogue: normalize, split, store attn [b,s,e] hi/lo
    const float inv0 = 1.0f / l0, inv1 = 1.0f / l1;
    const int s0r = qb + w * 16 + (lane >> 2);
#pragma unroll
    for (int nb = 0; nb < 8; nb++) {
        const int d = nb * 8 + (lane & 3) * 2;
        uint32_t hi, lo;
        size_t off = ((size_t)b * S_ + s0r) * E_ + h * 64 + d;
        fsplit2(O[nb][0] * inv0, O[nb][1] * inv0, hi, lo);
        *(uint32_t*)(g_ah + off) = hi;
        *(uint32_t*)(g_al + off) = lo;
        off += (size_t)8 * E_;
        fsplit2(O[nb][2] * inv1, O[nb][3] * inv1, hi, lo);
        *(uint32_t*)(g_ah + off) = hi;
        *(uint32_t*)(g_al + off) = lo;
    }
}

// ---------------------------------------------------------------------------
extern "C" void kernel_launch(void* const* d_in, const int* in_sizes, int n_in,
                              void* d_out, int out_size)
{
    const float* hidden = (const float*)d_in[0];
    const float* qkv_w  = (const float*)d_in[1];
    const float* qkv_b  = (const float*)d_in[2];
    const float* wo_w   = (const float*)d_in[3];
    const float* wo_b   = (const float*)d_in[4];
    const int*   mask   = (const int*)d_in[5];
    float* out = (float*)d_out;

    __nv_bfloat16 *hidh, *hidl, *wqh, *wql, *woh, *wol, *ah, *al;
    cudaGetSymbolAddress((void**)&hidh, g_hidh);
    cudaGetSymbolAddress((void**)&hidl, g_hidl);
    cudaGetSymbolAddress((void**)&wqh,  g_wqh);
    cudaGetSymbolAddress((void**)&wql,  g_wql);
    cudaGetSymbolAddress((void**)&woh,  g_woh);
    cudaGetSymbolAddress((void**)&wol,  g_wol);
    cudaGetSymbolAddress((void**)&ah,   g_ah);
    cudaGetSymbolAddress((void**)&al,   g_al);

    cudaFuncSetAttribute(mma_gemm<1>, cudaFuncAttributeMaxDynamicSharedMemorySize, GEMM_SMEM);
    cudaFuncSetAttribute(mma_gemm<0>, cudaFuncAttributeMaxDynamicSharedMemorySize, GEMM_SMEM);
    cudaFuncSetAttribute(attn_mma,    cudaFuncAttributeMaxDynamicSharedMemorySize, ATTN_SMEM);

    // 1) splits
    split4<<<(M_ * E_) / 4 / 256, 256>>>(hidden, hidh, hidl, M_ * E_);
    tsplit<<<dim3(E3_ / 32, E_ / 32), dim3(32, 8)>>>(qkv_w, wqh, wql, E_, E3_);
    tsplit<<<dim3(E_ / 32, E_ / 32),  dim3(32, 8)>>>(wo_w,  woh, wol, E_, E_);

    // 2) QKV projection -> split q/k/v [b,h,s,d]
    mma_gemm<1><<<dim3(E3_ / 128, M_ / 128), 256, GEMM_SMEM>>>(
        hidh, hidl, wqh, wql, qkv_b, nullptr, M_, E3_, E_);

    // 3) attention -> split attn [b,s,e]
    attn_mma<<<dim3(S_ / 128, BH_), 256, ATTN_SMEM>>>(mask);

    // 4) output projection -> fp32 out
    mma_gemm<0><<<dim3(E_ / 128, M_ / 128), 256, GEMM_SMEM>>>(
        ah, al, woh, wol, wo_b, out, M_, E_, E_);
}

// round 8
// speedup vs baseline: 1.0017x; 1.0017x over previous
#include <cuda_runtime.h>
#include <cuda_fp16.h>
#include <math.h>
#include <stdint.h>

#define B_ 4
#define S_ 2048
#define H_ 16
#define D_ 64
#define E_ 1024
#define E3_ 3072
#define BH_ (B_*H_)
#define M_ (B_*S_)   // 8192

// ---------------- device-global scratch (allocation-free rule) ----------------
__device__ __half g_hidh[M_*E_],  g_hidl[M_*E_];
__device__ __half g_wqh[E3_*E_],  g_wql[E3_*E_];     // qkv_w^T split [N][K]
__device__ __half g_woh[E_*E_],   g_wol[E_*E_];      // wo_w^T split  [N][K]
__device__ __half g_qh[BH_*S_*D_], g_ql[BH_*S_*D_];  // q (pre-scaled 0.125)
__device__ __half g_kh[BH_*S_*D_], g_kl[BH_*S_*D_];
__device__ __half g_vh[BH_*S_*D_], g_vl[BH_*S_*D_];
__device__ __half g_ah[M_*E_],    g_al[M_*E_];       // attn out split

// ---------------- helpers ----------------
__device__ __forceinline__ void ldsm4(uint32_t* r, uint32_t addr) {
    asm volatile("ldmatrix.sync.aligned.m8n8.x4.shared.b16 {%0,%1,%2,%3}, [%4];"
                 : "=r"(r[0]), "=r"(r[1]), "=r"(r[2]), "=r"(r[3]) : "r"(addr));
}
__device__ __forceinline__ void ldsm4t(uint32_t* r, uint32_t addr) {
    asm volatile("ldmatrix.sync.aligned.m8n8.x4.trans.shared.b16 {%0,%1,%2,%3}, [%4];"
                 : "=r"(r[0]), "=r"(r[1]), "=r"(r[2]), "=r"(r[3]) : "r"(addr));
}
// f16 inputs, f32 accumulator (full precision term)
__device__ __forceinline__ void mma16816(float* c, const uint32_t* a, const uint32_t* b) {
    asm volatile("mma.sync.aligned.m16n8k16.row.col.f32.f16.f16.f32 "
                 "{%0,%1,%2,%3}, {%4,%5,%6,%7}, {%8,%9}, {%0,%1,%2,%3};"
                 : "+f"(c[0]), "+f"(c[1]), "+f"(c[2]), "+f"(c[3])
                 : "r"(a[0]), "r"(a[1]), "r"(a[2]), "r"(a[3]),
                   "r"(b[0]), "r"(b[1]));
}
// f16 inputs, f16 accumulator (2x rate; used for small cross-correction terms)
__device__ __forceinline__ void mma16816h(uint32_t* c, const uint32_t* a, const uint32_t* b) {
    asm volatile("mma.sync.aligned.m16n8k16.row.col.f16.f16.f16.f16 "
                 "{%0,%1}, {%2,%3,%4,%5}, {%6,%7}, {%0,%1};"
                 : "+r"(c[0]), "+r"(c[1])
                 : "r"(a[0]), "r"(a[1]), "r"(a[2]), "r"(a[3]),
                   "r"(b[0]), "r"(b[1]));
}
// fold f16x2 pair accumulator into f32[4] and rezero
__device__ __forceinline__ void foldh(float* c, uint32_t* h) {
    float2 f01 = __half22float2(*reinterpret_cast<__half2*>(&h[0]));
    float2 f23 = __half22float2(*reinterpret_cast<__half2*>(&h[1]));
    c[0] += f01.x; c[1] += f01.y; c[2] += f23.x; c[3] += f23.y;
    h[0] = 0u; h[1] = 0u;
}
__device__ __forceinline__ void cpasync16(uint32_t dst, const void* src) {
    asm volatile("cp.async.cg.shared.global [%0], [%1], 16;" :: "r"(dst), "l"(src));
}
#define CP_COMMIT() asm volatile("cp.async.commit_group;")
#define CP_WAIT(N)  asm volatile("cp.async.wait_group %0;" :: "n"(N))

__device__ __forceinline__ void fsplit2(float a, float b, uint32_t& hi, uint32_t& lo) {
    __half2 h2 = __floats2half2_rn(a, b);
    float2 hf = __half22float2(h2);
    __half2 l2 = __floats2half2_rn(a - hf.x, b - hf.y);
    hi = *reinterpret_cast<uint32_t*>(&h2);
    lo = *reinterpret_cast<uint32_t*>(&l2);
}

// ---------------- split kernels ----------------
__global__ void split4(const float* __restrict__ x,
                       __half* __restrict__ hi, __half* __restrict__ lo, int n)
{
    int i = (blockIdx.x * blockDim.x + threadIdx.x) * 4;
    if (i >= n) return;
    float4 v = *(const float4*)(x + i);
    uint32_t h0, l0, h1, l1;
    fsplit2(v.x, v.y, h0, l0);
    fsplit2(v.z, v.w, h1, l1);
    uint2 hh; hh.x = h0; hh.y = h1;
    uint2 ll; ll.x = l0; ll.y = l1;
    *(uint2*)(hi + i) = hh;
    *(uint2*)(lo + i) = ll;
}

// W [K][N] f32 -> Th/Tl [N][K] f16
__global__ void tsplit(const float* __restrict__ W,
                       __half* __restrict__ Th, __half* __restrict__ Tl,
                       int K, int N)
{
    __shared__ float t[32][33];
    const int tx = threadIdx.x, ty = threadIdx.y;
    const int n0 = blockIdx.x * 32, k0 = blockIdx.y * 32;
#pragma unroll
    for (int j = 0; j < 4; j++)
        t[ty + j * 8][tx] = W[(size_t)(k0 + ty + j * 8) * N + n0 + tx];
    __syncthreads();
#pragma unroll
    for (int j = 0; j < 4; j++) {
        float v = t[tx][ty + j * 8];
        int n = n0 + ty + j * 8, k = k0 + tx;
        __half hv = __float2half_rn(v);
        Th[(size_t)n * K + k] = hv;
        Tl[(size_t)n * K + k] = __float2half_rn(v - __half2float(hv));
    }
}

// ---------------- pipelined tensor-core GEMM: C = A @ Bt^T + bias -------------
// 2-stage cp.async double buffer, BK=64.  Stage layout (64KB):
//   Ah +0 | Al +16K | Bh +32K | Bl +48K ; stage 1 at +64K.
// hi*hi term -> f32 acc; cross terms (lo*hi, hi*lo) -> shared f16 acc (2x rate).
#define GSTAGE 65536
#define GEMM_SMEM (2*GSTAGE)

template<int EPI>
__global__ __launch_bounds__(256)
void mma_gemm(const __half* __restrict__ Ah, const __half* __restrict__ Al,
              const __half* __restrict__ Bth, const __half* __restrict__ Btl,
              const float* __restrict__ bias, float* __restrict__ C,
              int M, int N, int K)
{
    extern __shared__ char sm[];
    const uint32_t sb = (uint32_t)__cvta_generic_to_shared(sm);
    const int tid = threadIdx.x, lane = tid & 31, wid = tid >> 5;
    const int wm = wid >> 1, wn = wid & 1;
    const int bm = blockIdx.y * 128, bn = blockIdx.x * 128;

    float acc[2][8][4];
    uint32_t hacc[2][8][2];
#pragma unroll
    for (int mi = 0; mi < 2; mi++)
#pragma unroll
        for (int nb = 0; nb < 8; nb++) {
#pragma unroll
            for (int q = 0; q < 4; q++) acc[mi][nb][q] = 0.f;
            hacc[mi][nb][0] = 0u; hacc[mi][nb][1] = 0u;
        }

    const int lr = (lane & 7) + ((lane >> 3) & 1) * 8;
    const int l_row0 = tid >> 3, l_ch = tid & 7;

    auto issue_stage = [&](int st, int kt) {
#pragma unroll
        for (int i = 0; i < 4; i++) {
            int row = l_row0 + i * 32;
            uint32_t soff = (uint32_t)st * GSTAGE + row * 128 + ((l_ch ^ (row & 7)) << 4);
            size_t ga = (size_t)(bm + row) * K + kt + l_ch * 8;
            size_t gb = (size_t)(bn + row) * K + kt + l_ch * 8;
            cpasync16(sb + soff,         Ah + ga);
            cpasync16(sb + 16384 + soff, Al + ga);
            cpasync16(sb + 32768 + soff, Bth + gb);
            cpasync16(sb + 49152 + soff, Btl + gb);
        }
        CP_COMMIT();
    };

    issue_stage(0, 0);

    int t = 0;
    for (int kt = 0; kt < K; kt += 64, t++) {
        const int cur = t & 1;
        const bool more = (kt + 64 < K);
        if (more) { issue_stage(cur ^ 1, kt + 64); CP_WAIT(1); }
        else      { CP_WAIT(0); }
        __syncthreads();

        const uint32_t cb = sb + (uint32_t)cur * GSTAGE;
#pragma unroll
        for (int kk = 0; kk < 4; kk++) {
            const int lc = kk * 2 + (lane >> 4);
            uint32_t afh[2][4], afl[2][4];
#pragma unroll
            for (int mi = 0; mi < 2; mi++) {
                int r = wm * 32 + mi * 16 + lr;
                uint32_t ad = cb + r * 128 + ((lc ^ (r & 7)) << 4);
                ldsm4(afh[mi], ad);
                ldsm4(afl[mi], ad + 16384);
            }
            uint32_t bfh[8][2], bfl[8][2], t4[4];
#pragma unroll
            for (int g = 0; g < 4; g++) {
                int r = wn * 64 + g * 16 + lr;
                uint32_t ad = cb + 32768 + r * 128 + ((lc ^ (r & 7)) << 4);
                ldsm4(t4, ad);
                bfh[2*g][0] = t4[0]; bfh[2*g][1] = t4[2];
                bfh[2*g+1][0] = t4[1]; bfh[2*g+1][1] = t4[3];
                ldsm4(t4, ad + 16384);
                bfl[2*g][0] = t4[0]; bfl[2*g][1] = t4[2];
                bfl[2*g+1][0] = t4[1]; bfl[2*g+1][1] = t4[3];
            }
#pragma unroll
            for (int mi = 0; mi < 2; mi++)
#pragma unroll
                for (int nb = 0; nb < 8; nb++) {
                    mma16816(acc[mi][nb], afh[mi], bfh[nb]);
                    mma16816h(hacc[mi][nb], afl[mi], bfh[nb]);
                    mma16816h(hacc[mi][nb], afh[mi], bfl[nb]);
                }
        }
        __syncthreads();
    }

    // fold cross-term f16 accumulators, then epilogue
#pragma unroll
    for (int mi = 0; mi < 2; mi++)
#pragma unroll
        for (int nb = 0; nb < 8; nb++) foldh(acc[mi][nb], hacc[mi][nb]);

#pragma unroll
    for (int mi = 0; mi < 2; mi++) {
        const int rbase = bm + wm * 32 + mi * 16 + (lane >> 2);
#pragma unroll
        for (int nb = 0; nb < 8; nb++) {
            const int cc = bn + wn * 64 + nb * 8 + (lane & 3) * 2;
            const float b0 = bias[cc], b1 = bias[cc + 1];
#pragma unroll
            for (int hr = 0; hr < 2; hr++) {
                const int r = rbase + hr * 8;
                float v0 = acc[mi][nb][hr * 2 + 0] + b0;
                float v1 = acc[mi][nb][hr * 2 + 1] + b1;
                if (EPI == 1) {
                    const int bb = r >> 11, si = r & 2047;
                    const int sec = cc >> 10, win = cc & 1023;
                    const int hh = win >> 6, dd = win & 63;
                    __half *dh, *dl;
                    if (sec == 0) { v0 *= 0.125f; v1 *= 0.125f; dh = g_qh; dl = g_ql; }
                    else if (sec == 1) { dh = g_kh; dl = g_kl; }
                    else { dh = g_vh; dl = g_vl; }
                    uint32_t hi, lo;
                    fsplit2(v0, v1, hi, lo);
                    size_t off = (((size_t)bb * H_ + hh) * S_ + si) * D_ + dd;
                    *(uint32_t*)(dh + off) = hi;
                    *(uint32_t*)(dl + off) = lo;
                } else {
                    float2 v; v.x = v0; v.y = v1;
                    *(float2*)(C + (size_t)r * N + cc) = v;
                }
            }
        }
    }
}

// ---------------- flash attention, 8 warps / 128 queries, pipelined ----------
// smem: Qh 0 (16K) | Ql 16K | stages at 32K: per stage {Kh 0, Kl 8K, Vh 16K, Vl 24K}
//       (32KB/stage, 2 stages) | Mf[2][64] at 96K
#define ASTAGE 32768
#define A_STG0 32768
#define A_MF   (A_STG0 + 2*ASTAGE)
#define ATTN_SMEM (A_MF + 2*64*4)

__global__ __launch_bounds__(256)
void attn_mma(const int* __restrict__ mask)
{
    extern __shared__ char sm[];
    const uint32_t sb = (uint32_t)__cvta_generic_to_shared(sm);
    float* Mf = (float*)(sm + A_MF);   // [2][64]
    const int tid = threadIdx.x, lane = tid & 31, w = tid >> 5;
    const int qb = blockIdx.x * 128, bh = blockIdx.y;
    const int b = bh >> 4, h = bh & 15;
    const size_t base = (size_t)bh * S_ * D_;
    const int lr = (lane & 7) + ((lane >> 3) & 1) * 8;
    const int* mrow = mask + b * S_;

    auto issue_kv = [&](int st, int kt) {
        for (int i = tid; i < 512; i += 256) {
            int row = i >> 3, ch = i & 7;
            uint32_t soff = A_STG0 + (uint32_t)st * ASTAGE + row * 128 + ((ch ^ (row & 7)) << 4);
            size_t g = base + (size_t)(kt + row) * D_ + ch * 8;
            cpasync16(sb + soff,          g_kh + g);
            cpasync16(sb + soff + 8192,   g_kl + g);
            cpasync16(sb + soff + 16384,  g_vh + g);
            cpasync16(sb + soff + 24576,  g_vl + g);
        }
        if (tid < 64) Mf[st * 64 + tid] = mrow[kt + tid] ? 1.0f : 0.0f;
        CP_COMMIT();
    };

    issue_kv(0, 0);

    for (int i = tid; i < 1024; i += 256) {
        int row = i >> 3, ch = i & 7;
        uint32_t soff = row * 128 + ((ch ^ (row & 7)) << 4);
        size_t g = base + (size_t)(qb + row) * D_ + ch * 8;
        *(uint4*)(sm + soff)         = *(const uint4*)(g_qh + g);
        *(uint4*)(sm + 16384 + soff) = *(const uint4*)(g_ql + g);
    }
    __syncthreads();

    uint32_t qfh[4][4], qfl[4][4];
#pragma unroll
    for (int kk = 0; kk < 4; kk++) {
        int r = w * 16 + lr;
        int c = kk * 2 + (lane >> 4);
        uint32_t ad = sb + r * 128 + ((c ^ (r & 7)) << 4);
        ldsm4(qfh[kk], ad);
        ldsm4(qfl[kk], ad + 16384);
    }

    float O[8][4];
    uint32_t hx[8][2];
#pragma unroll
    for (int nb = 0; nb < 8; nb++) {
#pragma unroll
        for (int q = 0; q < 4; q++) O[nb][q] = 0.f;
        hx[nb][0] = 0u; hx[nb][1] = 0u;
    }
    float m0 = -1e30f, m1 = -1e30f, l0 = 0.f, l1 = 0.f;

    for (int t = 0; t < S_ / 64; t++) {
        const int cur = t & 1;
        const bool more = (t + 1 < S_ / 64);
        if (more) { issue_kv(cur ^ 1, (t + 1) * 64); CP_WAIT(1); }
        else      { CP_WAIT(0); }
        __syncthreads();

        const uint32_t kb = sb + A_STG0 + (uint32_t)cur * ASTAGE;
        const float* mf = Mf + cur * 64;

        // S = Q K^T (Q pre-scaled by 0.125): hi*hi f32, cross f16
        float S[8][4];
#pragma unroll
        for (int nb = 0; nb < 8; nb++)
#pragma unroll
            for (int q = 0; q < 4; q++) S[nb][q] = 0.f;
#pragma unroll
        for (int kk = 0; kk < 4; kk++) {
            const int lc = kk * 2 + (lane >> 4);
            uint32_t bfh[8][2], bfl[8][2], t4[4];
#pragma unroll
            for (int g = 0; g < 4; g++) {
                int r = g * 16 + lr;
                uint32_t ad = kb + r * 128 + ((lc ^ (r & 7)) << 4);
                ldsm4(t4, ad);
                bfh[2*g][0] = t4[0]; bfh[2*g][1] = t4[2];
                bfh[2*g+1][0] = t4[1]; bfh[2*g+1][1] = t4[3];
                ldsm4(t4, ad + 8192);
                bfl[2*g][0] = t4[0]; bfl[2*g][1] = t4[2];
                bfl[2*g+1][0] = t4[1]; bfl[2*g+1][1] = t4[3];
            }
#pragma unroll
            for (int nb = 0; nb < 8; nb++) {
                mma16816(S[nb], qfh[kk], bfh[nb]);
                mma16816h(hx[nb], qfl[kk], bfh[nb]);
                mma16816h(hx[nb], qfh[kk], bfl[nb]);
            }
        }
#pragma unroll
        for (int nb = 0; nb < 8; nb++) foldh(S[nb], hx[nb]);

        // mask + online softmax
        float mk0[8], mk1[8];
#pragma unroll
        for (int nb = 0; nb < 8; nb++) {
            int c = nb * 8 + (lane & 3) * 2;
            mk0[nb] = mf[c]; mk1[nb] = mf[c + 1];
        }
        float mx0 = -1e30f, mx1 = -1e30f;
#pragma unroll
        for (int nb = 0; nb < 8; nb++) {
            S[nb][0] = (mk0[nb] != 0.f) ? S[nb][0] : -1e30f;
            S[nb][1] = (mk1[nb] != 0.f) ? S[nb][1] : -1e30f;
            S[nb][2] = (mk0[nb] != 0.f) ? S[nb][2] : -1e30f;
            S[nb][3] = (mk1[nb] != 0.f) ? S[nb][3] : -1e30f;
            mx0 = fmaxf(mx0, fmaxf(S[nb][0], S[nb][1]));
            mx1 = fmaxf(mx1, fmaxf(S[nb][2], S[nb][3]));
        }
        mx0 = fmaxf(mx0, __shfl_xor_sync(0xffffffffu, mx0, 1));
        mx0 = fmaxf(mx0, __shfl_xor_sync(0xffffffffu, mx0, 2));
        mx1 = fmaxf(mx1, __shfl_xor_sync(0xffffffffu, mx1, 1));
        mx1 = fmaxf(mx1, __shfl_xor_sync(0xffffffffu, mx1, 2));
        const float mn0 = fmaxf(m0, mx0), mn1 = fmaxf(m1, mx1);
        const float a0 = __expf(m0 - mn0), a1 = __expf(m1 - mn1);
        m0 = mn0; m1 = mn1;
        float s0 = 0.f, s1 = 0.f;
#pragma unroll
        for (int nb = 0; nb < 8; nb++) {
            float p0 = __expf(S[nb][0] - mn0) * mk0[nb];
            float p1 = __expf(S[nb][1] - mn0) * mk1[nb];
            float p2 = __expf(S[nb][2] - mn1) * mk0[nb];
            float p3 = __expf(S[nb][3] - mn1) * mk1[nb];
            S[nb][0] = p0; S[nb][1] = p1; S[nb][2] = p2; S[nb][3] = p3;
            s0 += p0 + p1; s1 += p2 + p3;
        }
        s0 += __shfl_xor_sync(0xffffffffu, s0, 1);
        s0 += __shfl_xor_sync(0xffffffffu, s0, 2);
        s1 += __shfl_xor_sync(0xffffffffu, s1, 1);
        s1 += __shfl_xor_sync(0xffffffffu, s1, 2);
        l0 = l0 * a0 + s0; l1 = l1 * a1 + s1;
#pragma unroll
        for (int nb = 0; nb < 8; nb++) {
            O[nb][0] *= a0; O[nb][1] *= a0; O[nb][2] *= a1; O[nb][3] *= a1;
        }

        // O += P V: hi*hi f32, cross f16 (hx folded after loop, pre-rescale safe)
#pragma unroll
        for (int kk = 0; kk < 4; kk++) {
            uint32_t ph[4], pl[4];
            fsplit2(S[2*kk][0],   S[2*kk][1],   ph[0], pl[0]);
            fsplit2(S[2*kk][2],   S[2*kk][3],   ph[1], pl[1]);
            fsplit2(S[2*kk+1][0], S[2*kk+1][1], ph[2], pl[2]);
            fsplit2(S[2*kk+1][2], S[2*kk+1][3], ph[3], pl[3]);
            uint32_t vfh[8][2], vfl[8][2], t4[4];
#pragma unroll
            for (int g = 0; g < 4; g++) {
                int r = kk * 16 + lr;
                int c = g * 2 + (lane >> 4);
                uint32_t ad = kb + 16384 + r * 128 + ((c ^ (r & 7)) << 4);
                ldsm4t(t4, ad);
                vfh[2*g][0] = t4[0]; vfh[2*g][1] = t4[1];
                vfh[2*g+1][0] = t4[2]; vfh[2*g+1][1] = t4[3];
                ldsm4t(t4, ad + 8192);
                vfl[2*g][0] = t4[0]; vfl[2*g][1] = t4[1];
                vfl[2*g+1][0] = t4[2]; vfl[2*g+1][1] = t4[3];
            }
#pragma unroll
            for (int nb = 0; nb < 8; nb++) {
                mma16816(O[nb], ph, vfh[nb]);
                mma16816h(hx[nb], pl, vfh[nb]);
                mma16816h(hx[nb], ph, vfl[nb]);
            }
        }
#pragma unroll
        for (int nb = 0; nb < 8; nb++) foldh(O[nb], hx[nb]);
        __syncthreads();
    }

    const float inv0 = 1.0f / l0, inv1 = 1.0f / l1;
    const int s0r = qb + w * 16 + (lane >> 2);
#pragma unroll
    for (int nb = 0; nb < 8; nb++) {
        const int d = nb * 8 + (lane & 3) * 2;
        uint32_t hi, lo;
        size_t off = ((size_t)b * S_ + s0r) * E_ + h * 64 + d;
        fsplit2(O[nb][0] * inv0, O[nb][1] * inv0, hi, lo);
        *(uint32_t*)(g_ah + off) = hi;
        *(uint32_t*)(g_al + off) = lo;
        off += (size_t)8 * E_;
        fsplit2(O[nb][2] * inv1, O[nb][3] * inv1, hi, lo);
        *(uint32_t*)(g_ah + off) = hi;
        *(uint32_t*)(g_al + off) = lo;
    }
}

// ---------------------------------------------------------------------------
extern "C" void kernel_launch(void* const* d_in, const int* in_sizes, int n_in,
                              void* d_out, int out_size)
{
    const float* hidden = (const float*)d_in[0];
    const float* qkv_w  = (const float*)d_in[1];
    const float* qkv_b  = (const float*)d_in[2];
    const float* wo_w   = (const float*)d_in[3];
    const float* wo_b   = (const float*)d_in[4];
    const int*   mask   = (const int*)d_in[5];
    float* out = (float*)d_out;

    __half *hidh, *hidl, *wqh, *wql, *woh, *wol, *ah, *al;
    cudaGetSymbolAddress((void**)&hidh, g_hidh);
    cudaGetSymbolAddress((void**)&hidl, g_hidl);
    cudaGetSymbolAddress((void**)&wqh,  g_wqh);
    cudaGetSymbolAddress((void**)&wql,  g_wql);
    cudaGetSymbolAddress((void**)&woh,  g_woh);
    cudaGetSymbolAddress((void**)&wol,  g_wol);
    cudaGetSymbolAddress((void**)&ah,   g_ah);
    cudaGetSymbolAddress((void**)&al,   g_al);

    cudaFuncSetAttribute(mma_gemm<1>, cudaFuncAttributeMaxDynamicSharedMemorySize, GEMM_SMEM);
    cudaFuncSetAttribute(mma_gemm<0>, cudaFuncAttributeMaxDynamicSharedMemorySize, GEMM_SMEM);
    cudaFuncSetAttribute(attn_mma,    cudaFuncAttributeMaxDynamicSharedMemorySize, ATTN_SMEM);

    // 1) splits
    split4<<<(M_ * E_) / 4 / 256, 256>>>(hidden, hidh, hidl, M_ * E_);
    tsplit<<<dim3(E3_ / 32, E_ / 32), dim3(32, 8)>>>(qkv_w, wqh, wql, E_, E3_);
    tsplit<<<dim3(E_ / 32, E_ / 32),  dim3(32, 8)>>>(wo_w,  woh, wol, E_, E_);

    // 2) QKV projection -> split q/k/v [b,h,s,d]
    mma_gemm<1><<<dim3(E3_ / 128, M_ / 128), 256, GEMM_SMEM>>>(
        hidh, hidl, wqh, wql, qkv_b, nullptr, M_, E3_, E_);

    // 3) attention -> split attn [b,s,e]
    attn_mma<<<dim3(S_ / 128, BH_), 256, ATTN_SMEM>>>(mask);

    // 4) output projection -> fp32 out
    mma_gemm<0><<<dim3(E_ / 128, M_ / 128), 256, GEMM_SMEM>>>(
        ah, al, woh, wol, wo_b, out, M_, E_, E_);
}

// round 9
// speedup vs baseline: 1.3960x; 1.3936x over previous
#include <cuda_runtime.h>
#include <cuda_fp16.h>
#include <math.h>
#include <stdint.h>

#define B_ 4
#define S_ 2048
#define H_ 16
#define D_ 64
#define E_ 1024
#define E3_ 3072
#define BH_ (B_*H_)
#define M_ (B_*S_)   // 8192

// ---------------- device-global scratch (allocation-free rule) ----------------
__device__ __half g_hidh[M_*E_],  g_hidl[M_*E_];     // hidden split (A-side exact)
__device__ __half g_wqh[E3_*E_],  g_wql[E3_*E_];     // qkv_w^T split [N][K] (lo unused)
__device__ __half g_woh[E_*E_],   g_wol[E_*E_];      // wo_w^T split  [N][K]
__device__ __half g_qh[BH_*S_*D_], g_ql[BH_*S_*D_];  // q exact split (pre-scaled 0.125)
__device__ __half g_kh[BH_*S_*D_];                   // k rounded once (B-side)
__device__ __half g_vh[BH_*S_*D_];                   // v rounded once (B-side)
__device__ __half g_ah[M_*E_],    g_al[M_*E_];       // attn out split (A-side exact)

// ---------------- helpers ----------------
__device__ __forceinline__ void ldsm4(uint32_t* r, uint32_t addr) {
    asm volatile("ldmatrix.sync.aligned.m8n8.x4.shared.b16 {%0,%1,%2,%3}, [%4];"
                 : "=r"(r[0]), "=r"(r[1]), "=r"(r[2]), "=r"(r[3]) : "r"(addr));
}
__device__ __forceinline__ void ldsm4t(uint32_t* r, uint32_t addr) {
    asm volatile("ldmatrix.sync.aligned.m8n8.x4.trans.shared.b16 {%0,%1,%2,%3}, [%4];"
                 : "=r"(r[0]), "=r"(r[1]), "=r"(r[2]), "=r"(r[3]) : "r"(addr));
}
__device__ __forceinline__ void mma16816(float* c, const uint32_t* a, const uint32_t* b) {
    asm volatile("mma.sync.aligned.m16n8k16.row.col.f32.f16.f16.f32 "
                 "{%0,%1,%2,%3}, {%4,%5,%6,%7}, {%8,%9}, {%0,%1,%2,%3};"
                 : "+f"(c[0]), "+f"(c[1]), "+f"(c[2]), "+f"(c[3])
                 : "r"(a[0]), "r"(a[1]), "r"(a[2]), "r"(a[3]),
                   "r"(b[0]), "r"(b[1]));
}
__device__ __forceinline__ void cpasync16(uint32_t dst, const void* src) {
    asm volatile("cp.async.cg.shared.global [%0], [%1], 16;" :: "r"(dst), "l"(src));
}
#define CP_COMMIT() asm volatile("cp.async.commit_group;")
#define CP_WAIT(N)  asm volatile("cp.async.wait_group %0;" :: "n"(N))

__device__ __forceinline__ void fsplit2(float a, float b, uint32_t& hi, uint32_t& lo) {
    __half2 h2 = __floats2half2_rn(a, b);
    float2 hf = __half22float2(h2);
    __half2 l2 = __floats2half2_rn(a - hf.x, b - hf.y);
    hi = *reinterpret_cast<uint32_t*>(&h2);
    lo = *reinterpret_cast<uint32_t*>(&l2);
}

// ---------------- split kernels ----------------
__global__ void split4(const float* __restrict__ x,
                       __half* __restrict__ hi, __half* __restrict__ lo, int n)
{
    int i = (blockIdx.x * blockDim.x + threadIdx.x) * 4;
    if (i >= n) return;
    float4 v = *(const float4*)(x + i);
    uint32_t h0, l0, h1, l1;
    fsplit2(v.x, v.y, h0, l0);
    fsplit2(v.z, v.w, h1, l1);
    uint2 hh; hh.x = h0; hh.y = h1;
    uint2 ll; ll.x = l0; ll.y = l1;
    *(uint2*)(hi + i) = hh;
    *(uint2*)(lo + i) = ll;
}

// W [K][N] f32 -> Th/Tl [N][K] f16
__global__ void tsplit(const float* __restrict__ W,
                       __half* __restrict__ Th, __half* __restrict__ Tl,
                       int K, int N)
{
    __shared__ float t[32][33];
    const int tx = threadIdx.x, ty = threadIdx.y;
    const int n0 = blockIdx.x * 32, k0 = blockIdx.y * 32;
#pragma unroll
    for (int j = 0; j < 4; j++)
        t[ty + j * 8][tx] = W[(size_t)(k0 + ty + j * 8) * N + n0 + tx];
    __syncthreads();
#pragma unroll
    for (int j = 0; j < 4; j++) {
        float v = t[tx][ty + j * 8];
        int n = n0 + ty + j * 8, k = k0 + tx;
        __half hv = __float2half_rn(v);
        Th[(size_t)n * K + k] = hv;
        Tl[(size_t)n * K + k] = __float2half_rn(v - __half2float(hv));
    }
}

// ---------------- pipelined tensor-core GEMM: C = A @ Bt^T + bias -------------
// TERMS=2: (Ah+Al)@Bh  (A exact, B rounded once)       stage 48KB
// TERMS=3: Ah@Bh + Al@Bh + Ah@Bl                        stage 64KB
// Stage layout: Ah +0 | Al +16K | Bh +32K | (Bl +48K).
// EPI=1: scatter q (split) / k,v (hi only) [b,h,s,d].  EPI=0: fp32 C.
template<int EPI, int TERMS>
__global__ __launch_bounds__(256, TERMS == 2 ? 2 : 1)
void mma_gemm(const __half* __restrict__ Ah, const __half* __restrict__ Al,
              const __half* __restrict__ Bth, const __half* __restrict__ Btl,
              const float* __restrict__ bias, float* __restrict__ C,
              int M, int N, int K)
{
    constexpr uint32_t STG = (TERMS == 3) ? 65536u : 49152u;
    extern __shared__ char sm[];
    const uint32_t sb = (uint32_t)__cvta_generic_to_shared(sm);
    const int tid = threadIdx.x, lane = tid & 31, wid = tid >> 5;
    const int wm = wid >> 1, wn = wid & 1;
    const int bm = blockIdx.y * 128, bn = blockIdx.x * 128;

    float acc[2][8][4];
#pragma unroll
    for (int mi = 0; mi < 2; mi++)
#pragma unroll
        for (int nb = 0; nb < 8; nb++)
#pragma unroll
            for (int q = 0; q < 4; q++) acc[mi][nb][q] = 0.f;

    const int lr = (lane & 7) + ((lane >> 3) & 1) * 8;
    const int l_row0 = tid >> 3, l_ch = tid & 7;

    auto issue_stage = [&](int st, int kt) {
#pragma unroll
        for (int i = 0; i < 4; i++) {
            int row = l_row0 + i * 32;
            uint32_t soff = (uint32_t)st * STG + row * 128 + ((l_ch ^ (row & 7)) << 4);
            size_t ga = (size_t)(bm + row) * K + kt + l_ch * 8;
            size_t gb = (size_t)(bn + row) * K + kt + l_ch * 8;
            cpasync16(sb + soff,         Ah + ga);
            cpasync16(sb + 16384 + soff, Al + ga);
            cpasync16(sb + 32768 + soff, Bth + gb);
            if (TERMS == 3) cpasync16(sb + 49152 + soff, Btl + gb);
        }
        CP_COMMIT();
    };

    issue_stage(0, 0);

    int t = 0;
    for (int kt = 0; kt < K; kt += 64, t++) {
        const int cur = t & 1;
        const bool more = (kt + 64 < K);
        if (more) { issue_stage(cur ^ 1, kt + 64); CP_WAIT(1); }
        else      { CP_WAIT(0); }
        __syncthreads();

        const uint32_t cb = sb + (uint32_t)cur * STG;
#pragma unroll
        for (int kk = 0; kk < 4; kk++) {
            const int lc = kk * 2 + (lane >> 4);
            uint32_t afh[2][4], afl[2][4];
#pragma unroll
            for (int mi = 0; mi < 2; mi++) {
                int r = wm * 32 + mi * 16 + lr;
                uint32_t ad = cb + r * 128 + ((lc ^ (r & 7)) << 4);
                ldsm4(afh[mi], ad);
                ldsm4(afl[mi], ad + 16384);
            }
            uint32_t bfh[8][2], bfl[8][2], t4[4];
#pragma unroll
            for (int g = 0; g < 4; g++) {
                int r = wn * 64 + g * 16 + lr;
                uint32_t ad = cb + 32768 + r * 128 + ((lc ^ (r & 7)) << 4);
                ldsm4(t4, ad);
                bfh[2*g][0] = t4[0]; bfh[2*g][1] = t4[2];
                bfh[2*g+1][0] = t4[1]; bfh[2*g+1][1] = t4[3];
                if (TERMS == 3) {
                    ldsm4(t4, ad + 16384);
                    bfl[2*g][0] = t4[0]; bfl[2*g][1] = t4[2];
                    bfl[2*g+1][0] = t4[1]; bfl[2*g+1][1] = t4[3];
                }
            }
#pragma unroll
            for (int mi = 0; mi < 2; mi++)
#pragma unroll
                for (int nb = 0; nb < 8; nb++) {
                    mma16816(acc[mi][nb], afh[mi], bfh[nb]);
                    mma16816(acc[mi][nb], afl[mi], bfh[nb]);
                    if (TERMS == 3) mma16816(acc[mi][nb], afh[mi], bfl[nb]);
                }
        }
        __syncthreads();
    }

    // epilogue
#pragma unroll
    for (int mi = 0; mi < 2; mi++) {
        const int rbase = bm + wm * 32 + mi * 16 + (lane >> 2);
#pragma unroll
        for (int nb = 0; nb < 8; nb++) {
            const int cc = bn + wn * 64 + nb * 8 + (lane & 3) * 2;
            const float b0 = bias[cc], b1 = bias[cc + 1];
#pragma unroll
            for (int hr = 0; hr < 2; hr++) {
                const int r = rbase + hr * 8;
                float v0 = acc[mi][nb][hr * 2 + 0] + b0;
                float v1 = acc[mi][nb][hr * 2 + 1] + b1;
                if (EPI == 1) {
                    const int bb = r >> 11, si = r & 2047;
                    const int sec = cc >> 10, win = cc & 1023;
                    const int hh = win >> 6, dd = win & 63;
                    size_t off = (((size_t)bb * H_ + hh) * S_ + si) * D_ + dd;
                    if (sec == 0) {
                        v0 *= 0.125f; v1 *= 0.125f;
                        uint32_t hi, lo;
                        fsplit2(v0, v1, hi, lo);
                        *(uint32_t*)(g_qh + off) = hi;
                        *(uint32_t*)(g_ql + off) = lo;
                    } else {
                        __half2 h2 = __floats2half2_rn(v0, v1);
                        __half* dst = (sec == 1) ? g_kh : g_vh;
                        *(__half2*)(dst + off) = h2;
                    }
                } else {
                    float2 v; v.x = v0; v.y = v1;
                    *(float2*)(C + (size_t)r * N + cc) = v;
                }
            }
        }
    }
}

// ---------------- flash attention, 8 warps / 128 queries, 2-term -------------
// S = (Qh+Ql) @ Kh^T ; O += (Ph+Pl) @ Vh.  K/V rounded once.
// smem: Qh 0 (16K) | Ql 16K | stages at 32K: {Kh 0..8K, Vh 8K..16K} x2 | Mf at 64K
#define ASTAGE 16384
#define A_STG0 32768
#define A_MF   (A_STG0 + 2*ASTAGE)
#define ATTN_SMEM (A_MF + 2*64*4)

__global__ __launch_bounds__(256)
void attn_mma(const int* __restrict__ mask)
{
    extern __shared__ char sm[];
    const uint32_t sb = (uint32_t)__cvta_generic_to_shared(sm);
    float* Mf = (float*)(sm + A_MF);   // [2][64]
    const int tid = threadIdx.x, lane = tid & 31, w = tid >> 5;
    const int qb = blockIdx.x * 128, bh = blockIdx.y;
    const int b = bh >> 4, h = bh & 15;
    const size_t base = (size_t)bh * S_ * D_;
    const int lr = (lane & 7) + ((lane >> 3) & 1) * 8;
    const int* mrow = mask + b * S_;

    auto issue_kv = [&](int st, int kt) {
        for (int i = tid; i < 512; i += 256) {
            int row = i >> 3, ch = i & 7;
            uint32_t soff = A_STG0 + (uint32_t)st * ASTAGE + row * 128 + ((ch ^ (row & 7)) << 4);
            size_t g = base + (size_t)(kt + row) * D_ + ch * 8;
            cpasync16(sb + soff,         g_kh + g);
            cpasync16(sb + soff + 8192,  g_vh + g);
        }
        if (tid < 64) Mf[st * 64 + tid] = mrow[kt + tid] ? 1.0f : 0.0f;
        CP_COMMIT();
    };

    issue_kv(0, 0);

    for (int i = tid; i < 1024; i += 256) {
        int row = i >> 3, ch = i & 7;
        uint32_t soff = row * 128 + ((ch ^ (row & 7)) << 4);
        size_t g = base + (size_t)(qb + row) * D_ + ch * 8;
        *(uint4*)(sm + soff)         = *(const uint4*)(g_qh + g);
        *(uint4*)(sm + 16384 + soff) = *(const uint4*)(g_ql + g);
    }
    __syncthreads();

    uint32_t qfh[4][4], qfl[4][4];
#pragma unroll
    for (int kk = 0; kk < 4; kk++) {
        int r = w * 16 + lr;
        int c = kk * 2 + (lane >> 4);
        uint32_t ad = sb + r * 128 + ((c ^ (r & 7)) << 4);
        ldsm4(qfh[kk], ad);
        ldsm4(qfl[kk], ad + 16384);
    }

    float O[8][4];
#pragma unroll
    for (int nb = 0; nb < 8; nb++)
#pragma unroll
        for (int q = 0; q < 4; q++) O[nb][q] = 0.f;
    float m0 = -1e30f, m1 = -1e30f, l0 = 0.f, l1 = 0.f;

    for (int t = 0; t < S_ / 64; t++) {
        const int cur = t & 1;
        const bool more = (t + 1 < S_ / 64);
        if (more) { issue_kv(cur ^ 1, (t + 1) * 64); CP_WAIT(1); }
        else      { CP_WAIT(0); }
        __syncthreads();

        const uint32_t kb = sb + A_STG0 + (uint32_t)cur * ASTAGE;
        const float* mf = Mf + cur * 64;

        // S = (Qh+Ql) Kh^T   (Q pre-scaled by 0.125)
        float S[8][4];
#pragma unroll
        for (int nb = 0; nb < 8; nb++)
#pragma unroll
            for (int q = 0; q < 4; q++) S[nb][q] = 0.f;
#pragma unroll
        for (int kk = 0; kk < 4; kk++) {
            const int lc = kk * 2 + (lane >> 4);
            uint32_t bfh[8][2], t4[4];
#pragma unroll
            for (int g = 0; g < 4; g++) {
                int r = g * 16 + lr;
                uint32_t ad = kb + r * 128 + ((lc ^ (r & 7)) << 4);
                ldsm4(t4, ad);
                bfh[2*g][0] = t4[0]; bfh[2*g][1] = t4[2];
                bfh[2*g+1][0] = t4[1]; bfh[2*g+1][1] = t4[3];
            }
#pragma unroll
            for (int nb = 0; nb < 8; nb++) {
                mma16816(S[nb], qfh[kk], bfh[nb]);
                mma16816(S[nb], qfl[kk], bfh[nb]);
            }
        }

        // mask + online softmax
        float mk0[8], mk1[8];
#pragma unroll
        for (int nb = 0; nb < 8; nb++) {
            int c = nb * 8 + (lane & 3) * 2;
            mk0[nb] = mf[c]; mk1[nb] = mf[c + 1];
        }
        float mx0 = -1e30f, mx1 = -1e30f;
#pragma unroll
        for (int nb = 0; nb < 8; nb++) {
            S[nb][0] = (mk0[nb] != 0.f) ? S[nb][0] : -1e30f;
            S[nb][1] = (mk1[nb] != 0.f) ? S[nb][1] : -1e30f;
            S[nb][2] = (mk0[nb] != 0.f) ? S[nb][2] : -1e30f;
            S[nb][3] = (mk1[nb] != 0.f) ? S[nb][3] : -1e30f;
            mx0 = fmaxf(mx0, fmaxf(S[nb][0], S[nb][1]));
            mx1 = fmaxf(mx1, fmaxf(S[nb][2], S[nb][3]));
        }
        mx0 = fmaxf(mx0, __shfl_xor_sync(0xffffffffu, mx0, 1));
        mx0 = fmaxf(mx0, __shfl_xor_sync(0xffffffffu, mx0, 2));
        mx1 = fmaxf(mx1, __shfl_xor_sync(0xffffffffu, mx1, 1));
        mx1 = fmaxf(mx1, __shfl_xor_sync(0xffffffffu, mx1, 2));
        const float mn0 = fmaxf(m0, mx0), mn1 = fmaxf(m1, mx1);
        const float a0 = __expf(m0 - mn0), a1 = __expf(m1 - mn1);
        m0 = mn0; m1 = mn1;
        float s0 = 0.f, s1 = 0.f;
#pragma unroll
        for (int nb = 0; nb < 8; nb++) {
            float p0 = __expf(S[nb][0] - mn0) * mk0[nb];
            float p1 = __expf(S[nb][1] - mn0) * mk1[nb];
            float p2 = __expf(S[nb][2] - mn1) * mk0[nb];
            float p3 = __expf(S[nb][3] - mn1) * mk1[nb];
            S[nb][0] = p0; S[nb][1] = p1; S[nb][2] = p2; S[nb][3] = p3;
            s0 += p0 + p1; s1 += p2 + p3;
        }
        s0 += __shfl_xor_sync(0xffffffffu, s0, 1);
        s0 += __shfl_xor_sync(0xffffffffu, s0, 2);
        s1 += __shfl_xor_sync(0xffffffffu, s1, 1);
        s1 += __shfl_xor_sync(0xffffffffu, s1, 2);
        l0 = l0 * a0 + s0; l1 = l1 * a1 + s1;
#pragma unroll
        for (int nb = 0; nb < 8; nb++) {
            O[nb][0] *= a0; O[nb][1] *= a0; O[nb][2] *= a1; O[nb][3] *= a1;
        }

        // O += (Ph+Pl) Vh
#pragma unroll
        for (int kk = 0; kk < 4; kk++) {
            uint32_t ph[4], pl[4];
            fsplit2(S[2*kk][0],   S[2*kk][1],   ph[0], pl[0]);
            fsplit2(S[2*kk][2],   S[2*kk][3],   ph[1], pl[1]);
            fsplit2(S[2*kk+1][0], S[2*kk+1][1], ph[2], pl[2]);
            fsplit2(S[2*kk+1][2], S[2*kk+1][3], ph[3], pl[3]);
            uint32_t vfh[8][2], t4[4];
#pragma unroll
            for (int g = 0; g < 4; g++) {
                int r = kk * 16 + lr;
                int c = g * 2 + (lane >> 4);
                uint32_t ad = kb + 8192 + r * 128 + ((c ^ (r & 7)) << 4);
                ldsm4t(t4, ad);
                vfh[2*g][0] = t4[0]; vfh[2*g][1] = t4[1];
                vfh[2*g+1][0] = t4[2]; vfh[2*g+1][1] = t4[3];
            }
#pragma unroll
            for (int nb = 0; nb < 8; nb++) {
                mma16816(O[nb], ph, vfh[nb]);
                mma16816(O[nb], pl, vfh[nb]);
            }
        }
        __syncthreads();
    }

    // epilogue: normalize, split, store attn [b,s,e] hi/lo (A-side exact for out-proj)
    const float inv0 = 1.0f / l0, inv1 = 1.0f / l1;
    const int s0r = qb + w * 16 + (lane >> 2);
#pragma unroll
    for (int nb = 0; nb < 8; nb++) {
        const int d = nb * 8 + (lane & 3) * 2;
        uint32_t hi, lo;
        size_t off = ((size_t)b * S_ + s0r) * E_ + h * 64 + d;
        fsplit2(O[nb][0] * inv0, O[nb][1] * inv0, hi, lo);
        *(uint32_t*)(g_ah + off) = hi;
        *(uint32_t*)(g_al + off) = lo;
        off += (size_t)8 * E_;
        fsplit2(O[nb][2] * inv1, O[nb][3] * inv1, hi, lo);
        *(uint32_t*)(g_ah + off) = hi;
        *(uint32_t*)(g_al + off) = lo;
    }
}

// ---------------------------------------------------------------------------
extern "C" void kernel_launch(void* const* d_in, const int* in_sizes, int n_in,
                              void* d_out, int out_size)
{
    const float* hidden = (const float*)d_in[0];
    const float* qkv_w  = (const float*)d_in[1];
    const float* qkv_b  = (const float*)d_in[2];
    const float* wo_w   = (const float*)d_in[3];
    const float* wo_b   = (const float*)d_in[4];
    const int*   mask   = (const int*)d_in[5];
    float* out = (float*)d_out;

    __half *hidh, *hidl, *wqh, *wql, *woh, *wol, *ah, *al;
    cudaGetSymbolAddress((void**)&hidh, g_hidh);
    cudaGetSymbolAddress((void**)&hidl, g_hidl);
    cudaGetSymbolAddress((void**)&wqh,  g_wqh);
    cudaGetSymbolAddress((void**)&wql,  g_wql);
    cudaGetSymbolAddress((void**)&woh,  g_woh);
    cudaGetSymbolAddress((void**)&wol,  g_wol);
    cudaGetSymbolAddress((void**)&ah,   g_ah);
    cudaGetSymbolAddress((void**)&al,   g_al);

    cudaFuncSetAttribute(mma_gemm<1,2>, cudaFuncAttributeMaxDynamicSharedMemorySize, 2*49152);
    cudaFuncSetAttribute(mma_gemm<0,3>, cudaFuncAttributeMaxDynamicSharedMemorySize, 2*65536);
    cudaFuncSetAttribute(attn_mma,      cudaFuncAttributeMaxDynamicSharedMemorySize, ATTN_SMEM);

    // 1) splits
    split4<<<(M_ * E_) / 4 / 256, 256>>>(hidden, hidh, hidl, M_ * E_);
    tsplit<<<dim3(E3_ / 32, E_ / 32), dim3(32, 8)>>>(qkv_w, wqh, wql, E_, E3_);
    tsplit<<<dim3(E_ / 32, E_ / 32),  dim3(32, 8)>>>(wo_w,  woh, wol, E_, E_);

    // 2) QKV projection (2-term: hidden exact, weights rounded)
    mma_gemm<1,2><<<dim3(E3_ / 128, M_ / 128), 256, 2*49152>>>(
        hidh, hidl, wqh, nullptr, qkv_b, nullptr, M_, E3_, E_);

    // 3) attention (2-term: Q,P exact, K,V rounded)
    attn_mma<<<dim3(S_ / 128, BH_), 256, ATTN_SMEM>>>(mask);

    // 4) output projection (3-term for margin)
    mma_gemm<0,3><<<dim3(E_ / 128, M_ / 128), 256, 2*65536>>>(
        ah, al, woh, wol, wo_b, out, M_, E_, E_);
}

// round 10
// speedup vs baseline: 1.5579x; 1.1159x over previous
#include <cuda_runtime.h>
#include <cuda_fp16.h>
#include <math.h>
#include <stdint.h>

#define B_ 4
#define S_ 2048
#define H_ 16
#define D_ 64
#define E_ 1024
#define E3_ 3072
#define BH_ (B_*H_)
#define M_ (B_*S_)   // 8192

// ---------------- device-global scratch (allocation-free rule) ----------------
__device__ __half g_hidh[M_*E_],  g_hidl[M_*E_];     // hidden split (A-side exact)
__device__ __half g_wqh[E3_*E_];                     // qkv_w^T rounded [N][K]
__device__ __half g_woh[E_*E_];                      // wo_w^T rounded  [N][K]
__device__ __half g_qh[BH_*S_*D_], g_ql[BH_*S_*D_];  // q exact split (pre-scaled 0.125)
__device__ __half g_kh[BH_*S_*D_];                   // k rounded once (B-side)
__device__ __half g_vh[BH_*S_*D_];                   // v rounded once (B-side)
__device__ __half g_ah[M_*E_],    g_al[M_*E_];       // attn out split (A-side exact)

// ---------------- helpers ----------------
__device__ __forceinline__ void ldsm4(uint32_t* r, uint32_t addr) {
    asm volatile("ldmatrix.sync.aligned.m8n8.x4.shared.b16 {%0,%1,%2,%3}, [%4];"
                 : "=r"(r[0]), "=r"(r[1]), "=r"(r[2]), "=r"(r[3]) : "r"(addr));
}
__device__ __forceinline__ void ldsm4t(uint32_t* r, uint32_t addr) {
    asm volatile("ldmatrix.sync.aligned.m8n8.x4.trans.shared.b16 {%0,%1,%2,%3}, [%4];"
                 : "=r"(r[0]), "=r"(r[1]), "=r"(r[2]), "=r"(r[3]) : "r"(addr));
}
__device__ __forceinline__ void mma16816(float* c, const uint32_t* a, const uint32_t* b) {
    asm volatile("mma.sync.aligned.m16n8k16.row.col.f32.f16.f16.f32 "
                 "{%0,%1,%2,%3}, {%4,%5,%6,%7}, {%8,%9}, {%0,%1,%2,%3};"
                 : "+f"(c[0]), "+f"(c[1]), "+f"(c[2]), "+f"(c[3])
                 : "r"(a[0]), "r"(a[1]), "r"(a[2]), "r"(a[3]),
                   "r"(b[0]), "r"(b[1]));
}
__device__ __forceinline__ void cpasync16(uint32_t dst, const void* src) {
    asm volatile("cp.async.cg.shared.global [%0], [%1], 16;" :: "r"(dst), "l"(src));
}
#define CP_COMMIT() asm volatile("cp.async.commit_group;")
#define CP_WAIT(N)  asm volatile("cp.async.wait_group %0;" :: "n"(N))

__device__ __forceinline__ void fsplit2(float a, float b, uint32_t& hi, uint32_t& lo) {
    __half2 h2 = __floats2half2_rn(a, b);
    float2 hf = __half22float2(h2);
    __half2 l2 = __floats2half2_rn(a - hf.x, b - hf.y);
    hi = *reinterpret_cast<uint32_t*>(&h2);
    lo = *reinterpret_cast<uint32_t*>(&l2);
}

// ---------------- split kernels ----------------
__global__ void split4(const float* __restrict__ x,
                       __half* __restrict__ hi, __half* __restrict__ lo, int n)
{
    int i = (blockIdx.x * blockDim.x + threadIdx.x) * 4;
    if (i >= n) return;
    float4 v = *(const float4*)(x + i);
    uint32_t h0, l0, h1, l1;
    fsplit2(v.x, v.y, h0, l0);
    fsplit2(v.z, v.w, h1, l1);
    uint2 hh; hh.x = h0; hh.y = h1;
    uint2 ll; ll.x = l0; ll.y = l1;
    *(uint2*)(hi + i) = hh;
    *(uint2*)(lo + i) = ll;
}

// W [K][N] f32 -> Th [N][K] f16 (rounded once)
__global__ void tround(const float* __restrict__ W,
                       __half* __restrict__ Th, int K, int N)
{
    __shared__ float t[32][33];
    const int tx = threadIdx.x, ty = threadIdx.y;
    const int n0 = blockIdx.x * 32, k0 = blockIdx.y * 32;
#pragma unroll
    for (int j = 0; j < 4; j++)
        t[ty + j * 8][tx] = W[(size_t)(k0 + ty + j * 8) * N + n0 + tx];
    __syncthreads();
#pragma unroll
    for (int j = 0; j < 4; j++) {
        float v = t[tx][ty + j * 8];
        int n = n0 + ty + j * 8, k = k0 + tx;
        Th[(size_t)n * K + k] = __float2half_rn(v);
    }
}

// ---------------- pipelined tensor-core GEMM: C = (Ah+Al) @ Bh^T + bias ------
// 2-term: A exact split, B rounded once.  Stage 48KB: Ah +0 | Al +16K | Bh +32K.
// EPI=1: scatter q (split) / k,v (hi only) [b,h,s,d].  EPI=0: fp32 C.
#define GSTG 49152u
template<int EPI>
__global__ __launch_bounds__(256, 2)
void mma_gemm(const __half* __restrict__ Ah, const __half* __restrict__ Al,
              const __half* __restrict__ Bth,
              const float* __restrict__ bias, float* __restrict__ C,
              int M, int N, int K)
{
    extern __shared__ char sm[];
    const uint32_t sb = (uint32_t)__cvta_generic_to_shared(sm);
    const int tid = threadIdx.x, lane = tid & 31, wid = tid >> 5;
    const int wm = wid >> 1, wn = wid & 1;
    const int bm = blockIdx.y * 128, bn = blockIdx.x * 128;

    float acc[2][8][4];
#pragma unroll
    for (int mi = 0; mi < 2; mi++)
#pragma unroll
        for (int nb = 0; nb < 8; nb++)
#pragma unroll
            for (int q = 0; q < 4; q++) acc[mi][nb][q] = 0.f;

    const int lr = (lane & 7) + ((lane >> 3) & 1) * 8;
    const int l_row0 = tid >> 3, l_ch = tid & 7;

    auto issue_stage = [&](int st, int kt) {
#pragma unroll
        for (int i = 0; i < 4; i++) {
            int row = l_row0 + i * 32;
            uint32_t soff = (uint32_t)st * GSTG + row * 128 + ((l_ch ^ (row & 7)) << 4);
            size_t ga = (size_t)(bm + row) * K + kt + l_ch * 8;
            size_t gb = (size_t)(bn + row) * K + kt + l_ch * 8;
            cpasync16(sb + soff,         Ah + ga);
            cpasync16(sb + 16384 + soff, Al + ga);
            cpasync16(sb + 32768 + soff, Bth + gb);
        }
        CP_COMMIT();
    };

    issue_stage(0, 0);

    int t = 0;
    for (int kt = 0; kt < K; kt += 64, t++) {
        const int cur = t & 1;
        const bool more = (kt + 64 < K);
        if (more) { issue_stage(cur ^ 1, kt + 64); CP_WAIT(1); }
        else      { CP_WAIT(0); }
        __syncthreads();

        const uint32_t cb = sb + (uint32_t)cur * GSTG;
#pragma unroll
        for (int kk = 0; kk < 4; kk++) {
            const int lc = kk * 2 + (lane >> 4);
            uint32_t afh[2][4], afl[2][4];
#pragma unroll
            for (int mi = 0; mi < 2; mi++) {
                int r = wm * 32 + mi * 16 + lr;
                uint32_t ad = cb + r * 128 + ((lc ^ (r & 7)) << 4);
                ldsm4(afh[mi], ad);
                ldsm4(afl[mi], ad + 16384);
            }
            uint32_t bfh[8][2], t4[4];
#pragma unroll
            for (int g = 0; g < 4; g++) {
                int r = wn * 64 + g * 16 + lr;
                uint32_t ad = cb + 32768 + r * 128 + ((lc ^ (r & 7)) << 4);
                ldsm4(t4, ad);
                bfh[2*g][0] = t4[0]; bfh[2*g][1] = t4[2];
                bfh[2*g+1][0] = t4[1]; bfh[2*g+1][1] = t4[3];
            }
#pragma unroll
            for (int mi = 0; mi < 2; mi++)
#pragma unroll
                for (int nb = 0; nb < 8; nb++) {
                    mma16816(acc[mi][nb], afh[mi], bfh[nb]);
                    mma16816(acc[mi][nb], afl[mi], bfh[nb]);
                }
        }
        __syncthreads();
    }

    // epilogue
#pragma unroll
    for (int mi = 0; mi < 2; mi++) {
        const int rbase = bm + wm * 32 + mi * 16 + (lane >> 2);
#pragma unroll
        for (int nb = 0; nb < 8; nb++) {
            const int cc = bn + wn * 64 + nb * 8 + (lane & 3) * 2;
            const float b0 = bias[cc], b1 = bias[cc + 1];
#pragma unroll
            for (int hr = 0; hr < 2; hr++) {
                const int r = rbase + hr * 8;
                float v0 = acc[mi][nb][hr * 2 + 0] + b0;
                float v1 = acc[mi][nb][hr * 2 + 1] + b1;
                if (EPI == 1) {
                    const int bb = r >> 11, si = r & 2047;
                    const int sec = cc >> 10, win = cc & 1023;
                    const int hh = win >> 6, dd = win & 63;
                    size_t off = (((size_t)bb * H_ + hh) * S_ + si) * D_ + dd;
                    if (sec == 0) {
                        v0 *= 0.125f; v1 *= 0.125f;
                        uint32_t hi, lo;
                        fsplit2(v0, v1, hi, lo);
                        *(uint32_t*)(g_qh + off) = hi;
                        *(uint32_t*)(g_ql + off) = lo;
                    } else {
                        __half2 h2 = __floats2half2_rn(v0, v1);
                        __half* dst = (sec == 1) ? g_kh : g_vh;
                        *(__half2*)(dst + off) = h2;
                    }
                } else {
                    float2 v; v.x = v0; v.y = v1;
                    *(float2*)(C + (size_t)r * N + cc) = v;
                }
            }
        }
    }
}

// ---------------- flash attention, 8 warps / 128 queries ---------------------
// S = (Qh+Ql) @ Kh^T (2 mma) ; O += Ph @ Vh (1 mma, P rounded once).
// smem: Qh 0 (16K) | Ql 16K | stages at 32K: {Kh 0..8K, Vh 8K..16K} x2 | Mf at 64K
#define ASTAGE 16384
#define A_STG0 32768
#define A_MF   (A_STG0 + 2*ASTAGE)
#define ATTN_SMEM (A_MF + 2*64*4)

__global__ __launch_bounds__(256)
void attn_mma(const int* __restrict__ mask)
{
    extern __shared__ char sm[];
    const uint32_t sb = (uint32_t)__cvta_generic_to_shared(sm);
    float* Mf = (float*)(sm + A_MF);   // [2][64]
    const int tid = threadIdx.x, lane = tid & 31, w = tid >> 5;
    const int qb = blockIdx.x * 128, bh = blockIdx.y;
    const int b = bh >> 4, h = bh & 15;
    const size_t base = (size_t)bh * S_ * D_;
    const int lr = (lane & 7) + ((lane >> 3) & 1) * 8;
    const int* mrow = mask + b * S_;

    auto issue_kv = [&](int st, int kt) {
        for (int i = tid; i < 512; i += 256) {
            int row = i >> 3, ch = i & 7;
            uint32_t soff = A_STG0 + (uint32_t)st * ASTAGE + row * 128 + ((ch ^ (row & 7)) << 4);
            size_t g = base + (size_t)(kt + row) * D_ + ch * 8;
            cpasync16(sb + soff,         g_kh + g);
            cpasync16(sb + soff + 8192,  g_vh + g);
        }
        if (tid < 64) Mf[st * 64 + tid] = mrow[kt + tid] ? 1.0f : 0.0f;
        CP_COMMIT();
    };

    issue_kv(0, 0);

    for (int i = tid; i < 1024; i += 256) {
        int row = i >> 3, ch = i & 7;
        uint32_t soff = row * 128 + ((ch ^ (row & 7)) << 4);
        size_t g = base + (size_t)(qb + row) * D_ + ch * 8;
        *(uint4*)(sm + soff)         = *(const uint4*)(g_qh + g);
        *(uint4*)(sm + 16384 + soff) = *(const uint4*)(g_ql + g);
    }
    __syncthreads();

    uint32_t qfh[4][4], qfl[4][4];
#pragma unroll
    for (int kk = 0; kk < 4; kk++) {
        int r = w * 16 + lr;
        int c = kk * 2 + (lane >> 4);
        uint32_t ad = sb + r * 128 + ((c ^ (r & 7)) << 4);
        ldsm4(qfh[kk], ad);
        ldsm4(qfl[kk], ad + 16384);
    }

    float O[8][4];
#pragma unroll
    for (int nb = 0; nb < 8; nb++)
#pragma unroll
        for (int q = 0; q < 4; q++) O[nb][q] = 0.f;
    float m0 = -1e30f, m1 = -1e30f, l0 = 0.f, l1 = 0.f;

    for (int t = 0; t < S_ / 64; t++) {
        const int cur = t & 1;
        const bool more = (t + 1 < S_ / 64);
        if (more) { issue_kv(cur ^ 1, (t + 1) * 64); CP_WAIT(1); }
        else      { CP_WAIT(0); }
        __syncthreads();

        const uint32_t kb = sb + A_STG0 + (uint32_t)cur * ASTAGE;
        const float* mf = Mf + cur * 64;

        // S = (Qh+Ql) Kh^T   (Q pre-scaled by 0.125)
        float S[8][4];
#pragma unroll
        for (int nb = 0; nb < 8; nb++)
#pragma unroll
            for (int q = 0; q < 4; q++) S[nb][q] = 0.f;
#pragma unroll
        for (int kk = 0; kk < 4; kk++) {
            const int lc = kk * 2 + (lane >> 4);
            uint32_t bfh[8][2], t4[4];
#pragma unroll
            for (int g = 0; g < 4; g++) {
                int r = g * 16 + lr;
                uint32_t ad = kb + r * 128 + ((lc ^ (r & 7)) << 4);
                ldsm4(t4, ad);
                bfh[2*g][0] = t4[0]; bfh[2*g][1] = t4[2];
                bfh[2*g+1][0] = t4[1]; bfh[2*g+1][1] = t4[3];
            }
#pragma unroll
            for (int nb = 0; nb < 8; nb++) {
                mma16816(S[nb], qfh[kk], bfh[nb]);
                mma16816(S[nb], qfl[kk], bfh[nb]);
            }
        }

        // mask + online softmax
        float mk0[8], mk1[8];
#pragma unroll
        for (int nb = 0; nb < 8; nb++) {
            int c = nb * 8 + (lane & 3) * 2;
            mk0[nb] = mf[c]; mk1[nb] = mf[c + 1];
        }
        float mx0 = -1e30f, mx1 = -1e30f;
#pragma unroll
        for (int nb = 0; nb < 8; nb++) {
            S[nb][0] = (mk0[nb] != 0.f) ? S[nb][0] : -1e30f;
            S[nb][1] = (mk1[nb] != 0.f) ? S[nb][1] : -1e30f;
            S[nb][2] = (mk0[nb] != 0.f) ? S[nb][2] : -1e30f;
            S[nb][3] = (mk1[nb] != 0.f) ? S[nb][3] : -1e30f;
            mx0 = fmaxf(mx0, fmaxf(S[nb][0], S[nb][1]));
            mx1 = fmaxf(mx1, fmaxf(S[nb][2], S[nb][3]));
        }
        mx0 = fmaxf(mx0, __shfl_xor_sync(0xffffffffu, mx0, 1));
        mx0 = fmaxf(mx0, __shfl_xor_sync(0xffffffffu, mx0, 2));
        mx1 = fmaxf(mx1, __shfl_xor_sync(0xffffffffu, mx1, 1));
        mx1 = fmaxf(mx1, __shfl_xor_sync(0xffffffffu, mx1, 2));
        const float mn0 = fmaxf(m0, mx0), mn1 = fmaxf(m1, mx1);
        const float a0 = __expf(m0 - mn0), a1 = __expf(m1 - mn1);
        m0 = mn0; m1 = mn1;
        float s0 = 0.f, s1 = 0.f;
#pragma unroll
        for (int nb = 0; nb < 8; nb++) {
            float p0 = __expf(S[nb][0] - mn0) * mk0[nb];
            float p1 = __expf(S[nb][1] - mn0) * mk1[nb];
            float p2 = __expf(S[nb][2] - mn1) * mk0[nb];
            float p3 = __expf(S[nb][3] - mn1) * mk1[nb];
            S[nb][0] = p0; S[nb][1] = p1; S[nb][2] = p2; S[nb][3] = p3;
            s0 += p0 + p1; s1 += p2 + p3;
        }
        s0 += __shfl_xor_sync(0xffffffffu, s0, 1);
        s0 += __shfl_xor_sync(0xffffffffu, s0, 2);
        s1 += __shfl_xor_sync(0xffffffffu, s1, 1);
        s1 += __shfl_xor_sync(0xffffffffu, s1, 2);
        l0 = l0 * a0 + s0; l1 = l1 * a1 + s1;
#pragma unroll
        for (int nb = 0; nb < 8; nb++) {
            O[nb][0] *= a0; O[nb][1] *= a0; O[nb][2] *= a1; O[nb][3] *= a1;
        }

        // O += Ph Vh   (P rounded once to f16)
#pragma unroll
        for (int kk = 0; kk < 4; kk++) {
            uint32_t ph[4];
            {
                __half2 t0 = __floats2half2_rn(S[2*kk][0],   S[2*kk][1]);
                __half2 t1 = __floats2half2_rn(S[2*kk][2],   S[2*kk][3]);
                __half2 t2 = __floats2half2_rn(S[2*kk+1][0], S[2*kk+1][1]);
                __half2 t3 = __floats2half2_rn(S[2*kk+1][2], S[2*kk+1][3]);
                ph[0] = *reinterpret_cast<uint32_t*>(&t0);
                ph[1] = *reinterpret_cast<uint32_t*>(&t1);
                ph[2] = *reinterpret_cast<uint32_t*>(&t2);
                ph[3] = *reinterpret_cast<uint32_t*>(&t3);
            }
            uint32_t vfh[8][2], t4[4];
#pragma unroll
            for (int g = 0; g < 4; g++) {
                int r = kk * 16 + lr;
                int c = g * 2 + (lane >> 4);
                uint32_t ad = kb + 8192 + r * 128 + ((c ^ (r & 7)) << 4);
                ldsm4t(t4, ad);
                vfh[2*g][0] = t4[0]; vfh[2*g][1] = t4[1];
                vfh[2*g+1][0] = t4[2]; vfh[2*g+1][1] = t4[3];
            }
#pragma unroll
            for (int nb = 0; nb < 8; nb++)
                mma16816(O[nb], ph, vfh[nb]);
        }
        __syncthreads();
    }

    // epilogue: normalize, split, store attn [b,s,e] hi/lo (A-side exact for out-proj)
    const float inv0 = 1.0f / l0, inv1 = 1.0f / l1;
    const int s0r = qb + w * 16 + (lane >> 2);
#pragma unroll
    for (int nb = 0; nb < 8; nb++) {
        const int d = nb * 8 + (lane & 3) * 2;
        uint32_t hi, lo;
        size_t off = ((size_t)b * S_ + s0r) * E_ + h * 64 + d;
        fsplit2(O[nb][0] * inv0, O[nb][1] * inv0, hi, lo);
        *(uint32_t*)(g_ah + off) = hi;
        *(uint32_t*)(g_al + off) = lo;
        off += (size_t)8 * E_;
        fsplit2(O[nb][2] * inv1, O[nb][3] * inv1, hi, lo);
        *(uint32_t*)(g_ah + off) = hi;
        *(uint32_t*)(g_al + off) = lo;
    }
}

// ---------------------------------------------------------------------------
extern "C" void kernel_launch(void* const* d_in, const int* in_sizes, int n_in,
                              void* d_out, int out_size)
{
    const float* hidden = (const float*)d_in[0];
    const float* qkv_w  = (const float*)d_in[1];
    const float* qkv_b  = (const float*)d_in[2];
    const float* wo_w   = (const float*)d_in[3];
    const float* wo_b   = (const float*)d_in[4];
    const int*   mask   = (const int*)d_in[5];
    float* out = (float*)d_out;

    __half *hidh, *hidl, *wqh, *woh, *ah, *al;
    cudaGetSymbolAddress((void**)&hidh, g_hidh);
    cudaGetSymbolAddress((void**)&hidl, g_hidl);
    cudaGetSymbolAddress((void**)&wqh,  g_wqh);
    cudaGetSymbolAddress((void**)&woh,  g_woh);
    cudaGetSymbolAddress((void**)&ah,   g_ah);
    cudaGetSymbolAddress((void**)&al,   g_al);

    cudaFuncSetAttribute(mma_gemm<1>, cudaFuncAttributeMaxDynamicSharedMemorySize, (int)(2*GSTG));
    cudaFuncSetAttribute(mma_gemm<0>, cudaFuncAttributeMaxDynamicSharedMemorySize, (int)(2*GSTG));
    cudaFuncSetAttribute(attn_mma,    cudaFuncAttributeMaxDynamicSharedMemorySize, ATTN_SMEM);

    // 1) splits / roundings
    split4<<<(M_ * E_) / 4 / 256, 256>>>(hidden, hidh, hidl, M_ * E_);
    tround<<<dim3(E3_ / 32, E_ / 32), dim3(32, 8)>>>(qkv_w, wqh, E_, E3_);
    tround<<<dim3(E_ / 32, E_ / 32),  dim3(32, 8)>>>(wo_w,  woh, E_, E_);

    // 2) QKV projection (2-term: hidden exact, weights rounded)
    mma_gemm<1><<<dim3(E3_ / 128, M_ / 128), 256, 2*GSTG>>>(
        hidh, hidl, wqh, qkv_b, nullptr, M_, E3_, E_);

    // 3) attention (QK 2-term; PV 1-term, P rounded)
    attn_mma<<<dim3(S_ / 128, BH_), 256, ATTN_SMEM>>>(mask);

    // 4) output projection (2-term: attn exact, wo rounded)
    mma_gemm<0><<<dim3(E_ / 128, M_ / 128), 256, 2*GSTG>>>(
        ah, al, woh, wo_b, out, M_, E_, E_);
}

// round 11
// speedup vs baseline: 2.0985x; 1.3471x over previous
#include <cuda_runtime.h>
#include <cuda_fp16.h>
#include <math.h>
#include <stdint.h>

#define B_ 4
#define S_ 2048
#define H_ 16
#define D_ 64
#define E_ 1024
#define E3_ 3072
#define BH_ (B_*H_)
#define M_ (B_*S_)   // 8192

// ---------------- device-global scratch (allocation-free rule) ----------------
__device__ __half g_hidh[M_*E_],  g_hidl[M_*E_];     // hidden split (A-side exact)
__device__ __half g_wqh[E3_*E_];                     // qkv_w^T rounded [N][K]
__device__ __half g_woh[E_*E_];                      // wo_w^T rounded  [N][K]
__device__ __half g_qh[BH_*S_*D_];                   // q rounded (pre-scaled 0.125)
__device__ __half g_kh[BH_*S_*D_];                   // k rounded
__device__ __half g_vh[BH_*S_*D_];                   // v rounded
__device__ __half g_ah[M_*E_];                       // attn out rounded

// ---------------- helpers ----------------
__device__ __forceinline__ void ldsm4(uint32_t* r, uint32_t addr) {
    asm volatile("ldmatrix.sync.aligned.m8n8.x4.shared.b16 {%0,%1,%2,%3}, [%4];"
                 : "=r"(r[0]), "=r"(r[1]), "=r"(r[2]), "=r"(r[3]) : "r"(addr));
}
__device__ __forceinline__ void ldsm4t(uint32_t* r, uint32_t addr) {
    asm volatile("ldmatrix.sync.aligned.m8n8.x4.trans.shared.b16 {%0,%1,%2,%3}, [%4];"
                 : "=r"(r[0]), "=r"(r[1]), "=r"(r[2]), "=r"(r[3]) : "r"(addr));
}
__device__ __forceinline__ void mma16816(float* c, const uint32_t* a, const uint32_t* b) {
    asm volatile("mma.sync.aligned.m16n8k16.row.col.f32.f16.f16.f32 "
                 "{%0,%1,%2,%3}, {%4,%5,%6,%7}, {%8,%9}, {%0,%1,%2,%3};"
                 : "+f"(c[0]), "+f"(c[1]), "+f"(c[2]), "+f"(c[3])
                 : "r"(a[0]), "r"(a[1]), "r"(a[2]), "r"(a[3]),
                   "r"(b[0]), "r"(b[1]));
}
__device__ __forceinline__ void cpasync16(uint32_t dst, const void* src) {
    asm volatile("cp.async.cg.shared.global [%0], [%1], 16;" :: "r"(dst), "l"(src));
}
#define CP_COMMIT() asm volatile("cp.async.commit_group;")
#define CP_WAIT(N)  asm volatile("cp.async.wait_group %0;" :: "n"(N))

__device__ __forceinline__ void fsplit2(float a, float b, uint32_t& hi, uint32_t& lo) {
    __half2 h2 = __floats2half2_rn(a, b);
    float2 hf = __half22float2(h2);
    __half2 l2 = __floats2half2_rn(a - hf.x, b - hf.y);
    hi = *reinterpret_cast<uint32_t*>(&h2);
    lo = *reinterpret_cast<uint32_t*>(&l2);
}

// ---------------- split / round kernels ----------------
__global__ void split4(const float* __restrict__ x,
                       __half* __restrict__ hi, __half* __restrict__ lo, int n)
{
    int i = (blockIdx.x * blockDim.x + threadIdx.x) * 4;
    if (i >= n) return;
    float4 v = *(const float4*)(x + i);
    uint32_t h0, l0, h1, l1;
    fsplit2(v.x, v.y, h0, l0);
    fsplit2(v.z, v.w, h1, l1);
    uint2 hh; hh.x = h0; hh.y = h1;
    uint2 ll; ll.x = l0; ll.y = l1;
    *(uint2*)(hi + i) = hh;
    *(uint2*)(lo + i) = ll;
}

// W [K][N] f32 -> Th [N][K] f16 (rounded once)
__global__ void tround(const float* __restrict__ W,
                       __half* __restrict__ Th, int K, int N)
{
    __shared__ float t[32][33];
    const int tx = threadIdx.x, ty = threadIdx.y;
    const int n0 = blockIdx.x * 32, k0 = blockIdx.y * 32;
#pragma unroll
    for (int j = 0; j < 4; j++)
        t[ty + j * 8][tx] = W[(size_t)(k0 + ty + j * 8) * N + n0 + tx];
    __syncthreads();
#pragma unroll
    for (int j = 0; j < 4; j++) {
        float v = t[tx][ty + j * 8];
        int n = n0 + ty + j * 8, k = k0 + tx;
        Th[(size_t)n * K + k] = __float2half_rn(v);
    }
}

// ---------------- pipelined tensor-core GEMM ---------------------------------
// ATERMS=2: C = (Ah+Al) @ Bh^T + bias   stage 48KB: Ah | Al +16K | Bh +32K
// ATERMS=1: C =  Ah     @ Bh^T + bias   stage 32KB: Ah | Bh +16K
// EPI=1: scatter q/k/v rounded [b,h,s,d] (q scaled 0.125).  EPI=0: fp32 C.
template<int EPI, int ATERMS>
__global__ __launch_bounds__(256, 2)
void mma_gemm(const __half* __restrict__ Ah, const __half* __restrict__ Al,
              const __half* __restrict__ Bth,
              const float* __restrict__ bias, float* __restrict__ C,
              int M, int N, int K)
{
    constexpr uint32_t STG = (ATERMS + 1) * 16384u;
    constexpr uint32_t BOFF = ATERMS * 16384u;
    extern __shared__ char sm[];
    const uint32_t sb = (uint32_t)__cvta_generic_to_shared(sm);
    const int tid = threadIdx.x, lane = tid & 31, wid = tid >> 5;
    const int wm = wid >> 1, wn = wid & 1;
    const int bm = blockIdx.y * 128, bn = blockIdx.x * 128;

    float acc[2][8][4];
#pragma unroll
    for (int mi = 0; mi < 2; mi++)
#pragma unroll
        for (int nb = 0; nb < 8; nb++)
#pragma unroll
            for (int q = 0; q < 4; q++) acc[mi][nb][q] = 0.f;

    const int lr = (lane & 7) + ((lane >> 3) & 1) * 8;
    const int l_row0 = tid >> 3, l_ch = tid & 7;

    auto issue_stage = [&](int st, int kt) {
#pragma unroll
        for (int i = 0; i < 4; i++) {
            int row = l_row0 + i * 32;
            uint32_t soff = (uint32_t)st * STG + row * 128 + ((l_ch ^ (row & 7)) << 4);
            size_t ga = (size_t)(bm + row) * K + kt + l_ch * 8;
            size_t gb = (size_t)(bn + row) * K + kt + l_ch * 8;
            cpasync16(sb + soff, Ah + ga);
            if (ATERMS == 2) cpasync16(sb + 16384 + soff, Al + ga);
            cpasync16(sb + BOFF + soff, Bth + gb);
        }
        CP_COMMIT();
    };

    issue_stage(0, 0);

    int t = 0;
    for (int kt = 0; kt < K; kt += 64, t++) {
        const int cur = t & 1;
        const bool more = (kt + 64 < K);
        if (more) { issue_stage(cur ^ 1, kt + 64); CP_WAIT(1); }
        else      { CP_WAIT(0); }
        __syncthreads();

        const uint32_t cb = sb + (uint32_t)cur * STG;
#pragma unroll
        for (int kk = 0; kk < 4; kk++) {
            const int lc = kk * 2 + (lane >> 4);
            uint32_t afh[2][4], afl[2][4];
#pragma unroll
            for (int mi = 0; mi < 2; mi++) {
                int r = wm * 32 + mi * 16 + lr;
                uint32_t ad = cb + r * 128 + ((lc ^ (r & 7)) << 4);
                ldsm4(afh[mi], ad);
                if (ATERMS == 2) ldsm4(afl[mi], ad + 16384);
            }
            uint32_t bfh[8][2], t4[4];
#pragma unroll
            for (int g = 0; g < 4; g++) {
                int r = wn * 64 + g * 16 + lr;
                uint32_t ad = cb + BOFF + r * 128 + ((lc ^ (r & 7)) << 4);
                ldsm4(t4, ad);
                bfh[2*g][0] = t4[0]; bfh[2*g][1] = t4[2];
                bfh[2*g+1][0] = t4[1]; bfh[2*g+1][1] = t4[3];
            }
#pragma unroll
            for (int mi = 0; mi < 2; mi++)
#pragma unroll
                for (int nb = 0; nb < 8; nb++) {
                    mma16816(acc[mi][nb], afh[mi], bfh[nb]);
                    if (ATERMS == 2) mma16816(acc[mi][nb], afl[mi], bfh[nb]);
                }
        }
        __syncthreads();
    }

    // epilogue
#pragma unroll
    for (int mi = 0; mi < 2; mi++) {
        const int rbase = bm + wm * 32 + mi * 16 + (lane >> 2);
#pragma unroll
        for (int nb = 0; nb < 8; nb++) {
            const int cc = bn + wn * 64 + nb * 8 + (lane & 3) * 2;
            const float b0 = bias[cc], b1 = bias[cc + 1];
#pragma unroll
            for (int hr = 0; hr < 2; hr++) {
                const int r = rbase + hr * 8;
                float v0 = acc[mi][nb][hr * 2 + 0] + b0;
                float v1 = acc[mi][nb][hr * 2 + 1] + b1;
                if (EPI == 1) {
                    const int bb = r >> 11, si = r & 2047;
                    const int sec = cc >> 10, win = cc & 1023;
                    const int hh = win >> 6, dd = win & 63;
                    size_t off = (((size_t)bb * H_ + hh) * S_ + si) * D_ + dd;
                    __half* dst;
                    if (sec == 0) { v0 *= 0.125f; v1 *= 0.125f; dst = g_qh; }
                    else if (sec == 1) dst = g_kh;
                    else dst = g_vh;
                    __half2 h2 = __floats2half2_rn(v0, v1);
                    *(__half2*)(dst + off) = h2;
                } else {
                    float2 v; v.x = v0; v.y = v1;
                    *(float2*)(C + (size_t)r * N + cc) = v;
                }
            }
        }
    }
}

// ---------------- flash attention, 8 warps / 128 queries ---------------------
// S = Qh @ Kh^T (1 mma) ; O += Ph @ Vh (1 mma).  Q/K/V/P each rounded once.
// smem: Qh 0 (16K) | stages at 16K: {Kh 0..8K, Vh 8K..16K} x2 | Mf at 48K
#define ASTAGE 16384
#define A_STG0 16384
#define A_MF   (A_STG0 + 2*ASTAGE)
#define ATTN_SMEM (A_MF + 2*64*4)

__global__ __launch_bounds__(256)
void attn_mma(const int* __restrict__ mask)
{
    extern __shared__ char sm[];
    const uint32_t sb = (uint32_t)__cvta_generic_to_shared(sm);
    float* Mf = (float*)(sm + A_MF);   // [2][64]
    const int tid = threadIdx.x, lane = tid & 31, w = tid >> 5;
    const int qb = blockIdx.x * 128, bh = blockIdx.y;
    const int b = bh >> 4, h = bh & 15;
    const size_t base = (size_t)bh * S_ * D_;
    const int lr = (lane & 7) + ((lane >> 3) & 1) * 8;
    const int* mrow = mask + b * S_;

    auto issue_kv = [&](int st, int kt) {
        for (int i = tid; i < 512; i += 256) {
            int row = i >> 3, ch = i & 7;
            uint32_t soff = A_STG0 + (uint32_t)st * ASTAGE + row * 128 + ((ch ^ (row & 7)) << 4);
            size_t g = base + (size_t)(kt + row) * D_ + ch * 8;
            cpasync16(sb + soff,         g_kh + g);
            cpasync16(sb + soff + 8192,  g_vh + g);
        }
        if (tid < 64) Mf[st * 64 + tid] = mrow[kt + tid] ? 1.0f : 0.0f;
        CP_COMMIT();
    };

    issue_kv(0, 0);

    // stage Q tile (128 rows, rounded)
    for (int i = tid; i < 1024; i += 256) {
        int row = i >> 3, ch = i & 7;
        uint32_t soff = row * 128 + ((ch ^ (row & 7)) << 4);
        size_t g = base + (size_t)(qb + row) * D_ + ch * 8;
        *(uint4*)(sm + soff) = *(const uint4*)(g_qh + g);
    }
    __syncthreads();

    uint32_t qfh[4][4];
#pragma unroll
    for (int kk = 0; kk < 4; kk++) {
        int r = w * 16 + lr;
        int c = kk * 2 + (lane >> 4);
        uint32_t ad = sb + r * 128 + ((c ^ (r & 7)) << 4);
        ldsm4(qfh[kk], ad);
    }

    float O[8][4];
#pragma unroll
    for (int nb = 0; nb < 8; nb++)
#pragma unroll
        for (int q = 0; q < 4; q++) O[nb][q] = 0.f;
    float m0 = -1e30f, m1 = -1e30f, l0 = 0.f, l1 = 0.f;

    for (int t = 0; t < S_ / 64; t++) {
        const int cur = t & 1;
        const bool more = (t + 1 < S_ / 64);
        if (more) { issue_kv(cur ^ 1, (t + 1) * 64); CP_WAIT(1); }
        else      { CP_WAIT(0); }
        __syncthreads();

        const uint32_t kb = sb + A_STG0 + (uint32_t)cur * ASTAGE;
        const float* mf = Mf + cur * 64;

        // S = Qh Kh^T   (Q pre-scaled by 0.125)
        float S[8][4];
#pragma unroll
        for (int nb = 0; nb < 8; nb++)
#pragma unroll
            for (int q = 0; q < 4; q++) S[nb][q] = 0.f;
#pragma unroll
        for (int kk = 0; kk < 4; kk++) {
            const int lc = kk * 2 + (lane >> 4);
            uint32_t bfh[8][2], t4[4];
#pragma unroll
            for (int g = 0; g < 4; g++) {
                int r = g * 16 + lr;
                uint32_t ad = kb + r * 128 + ((lc ^ (r & 7)) << 4);
                ldsm4(t4, ad);
                bfh[2*g][0] = t4[0]; bfh[2*g][1] = t4[2];
                bfh[2*g+1][0] = t4[1]; bfh[2*g+1][1] = t4[3];
            }
#pragma unroll
            for (int nb = 0; nb < 8; nb++)
                mma16816(S[nb], qfh[kk], bfh[nb]);
        }

        // mask + online softmax
        float mk0[8], mk1[8];
#pragma unroll
        for (int nb = 0; nb < 8; nb++) {
            int c = nb * 8 + (lane & 3) * 2;
            mk0[nb] = mf[c]; mk1[nb] = mf[c + 1];
        }
        float mx0 = -1e30f, mx1 = -1e30f;
#pragma unroll
        for (int nb = 0; nb < 8; nb++) {
            S[nb][0] = (mk0[nb] != 0.f) ? S[nb][0] : -1e30f;
            S[nb][1] = (mk1[nb] != 0.f) ? S[nb][1] : -1e30f;
            S[nb][2] = (mk0[nb] != 0.f) ? S[nb][2] : -1e30f;
            S[nb][3] = (mk1[nb] != 0.f) ? S[nb][3] : -1e30f;
            mx0 = fmaxf(mx0, fmaxf(S[nb][0], S[nb][1]));
            mx1 = fmaxf(mx1, fmaxf(S[nb][2], S[nb][3]));
        }
        mx0 = fmaxf(mx0, __shfl_xor_sync(0xffffffffu, mx0, 1));
        mx0 = fmaxf(mx0, __shfl_xor_sync(0xffffffffu, mx0, 2));
        mx1 = fmaxf(mx1, __shfl_xor_sync(0xffffffffu, mx1, 1));
        mx1 = fmaxf(mx1, __shfl_xor_sync(0xffffffffu, mx1, 2));
        const float mn0 = fmaxf(m0, mx0), mn1 = fmaxf(m1, mx1);
        const float a0 = __expf(m0 - mn0), a1 = __expf(m1 - mn1);
        m0 = mn0; m1 = mn1;
        float s0 = 0.f, s1 = 0.f;
#pragma unroll
        for (int nb = 0; nb < 8; nb++) {
            float p0 = __expf(S[nb][0] - mn0) * mk0[nb];
            float p1 = __expf(S[nb][1] - mn0) * mk1[nb];
            float p2 = __expf(S[nb][2] - mn1) * mk0[nb];
            float p3 = __expf(S[nb][3] - mn1) * mk1[nb];
            S[nb][0] = p0; S[nb][1] = p1; S[nb][2] = p2; S[nb][3] = p3;
            s0 += p0 + p1; s1 += p2 + p3;
        }
        s0 += __shfl_xor_sync(0xffffffffu, s0, 1);
        s0 += __shfl_xor_sync(0xffffffffu, s0, 2);
        s1 += __shfl_xor_sync(0xffffffffu, s1, 1);
        s1 += __shfl_xor_sync(0xffffffffu, s1, 2);
        l0 = l0 * a0 + s0; l1 = l1 * a1 + s1;
#pragma unroll
        for (int nb = 0; nb < 8; nb++) {
            O[nb][0] *= a0; O[nb][1] *= a0; O[nb][2] *= a1; O[nb][3] *= a1;
        }

        // O += Ph Vh   (P rounded once to f16)
#pragma unroll
        for (int kk = 0; kk < 4; kk++) {
            uint32_t ph[4];
            {
                __half2 t0 = __floats2half2_rn(S[2*kk][0],   S[2*kk][1]);
                __half2 t1 = __floats2half2_rn(S[2*kk][2],   S[2*kk][3]);
                __half2 t2 = __floats2half2_rn(S[2*kk+1][0], S[2*kk+1][1]);
                __half2 t3 = __floats2half2_rn(S[2*kk+1][2], S[2*kk+1][3]);
                ph[0] = *reinterpret_cast<uint32_t*>(&t0);
                ph[1] = *reinterpret_cast<uint32_t*>(&t1);
                ph[2] = *reinterpret_cast<uint32_t*>(&t2);
                ph[3] = *reinterpret_cast<uint32_t*>(&t3);
            }
            uint32_t vfh[8][2], t4[4];
#pragma unroll
            for (int g = 0; g < 4; g++) {
                int r = kk * 16 + lr;
                int c = g * 2 + (lane >> 4);
                uint32_t ad = kb + 8192 + r * 128 + ((c ^ (r & 7)) << 4);
                ldsm4t(t4, ad);
                vfh[2*g][0] = t4[0]; vfh[2*g][1] = t4[1];
                vfh[2*g+1][0] = t4[2]; vfh[2*g+1][1] = t4[3];
            }
#pragma unroll
            for (int nb = 0; nb < 8; nb++)
                mma16816(O[nb], ph, vfh[nb]);
        }
        __syncthreads();
    }

    // epilogue: normalize, round once, store attn [b,s,e]
    const float inv0 = 1.0f / l0, inv1 = 1.0f / l1;
    const int s0r = qb + w * 16 + (lane >> 2);
#pragma unroll
    for (int nb = 0; nb < 8; nb++) {
        const int d = nb * 8 + (lane & 3) * 2;
        size_t off = ((size_t)b * S_ + s0r) * E_ + h * 64 + d;
        __half2 h2 = __floats2half2_rn(O[nb][0] * inv0, O[nb][1] * inv0);
        *(__half2*)(g_ah + off) = h2;
        off += (size_t)8 * E_;
        h2 = __floats2half2_rn(O[nb][2] * inv1, O[nb][3] * inv1);
        *(__half2*)(g_ah + off) = h2;
    }
}

// ---------------------------------------------------------------------------
extern "C" void kernel_launch(void* const* d_in, const int* in_sizes, int n_in,
                              void* d_out, int out_size)
{
    const float* hidden = (const float*)d_in[0];
    const float* qkv_w  = (const float*)d_in[1];
    const float* qkv_b  = (const float*)d_in[2];
    const float* wo_w   = (const float*)d_in[3];
    const float* wo_b   = (const float*)d_in[4];
    const int*   mask   = (const int*)d_in[5];
    float* out = (float*)d_out;

    __half *hidh, *hidl, *wqh, *woh, *ah;
    cudaGetSymbolAddress((void**)&hidh, g_hidh);
    cudaGetSymbolAddress((void**)&hidl, g_hidl);
    cudaGetSymbolAddress((void**)&wqh,  g_wqh);
    cudaGetSymbolAddress((void**)&woh,  g_woh);
    cudaGetSymbolAddress((void**)&ah,   g_ah);

    cudaFuncSetAttribute(mma_gemm<1,2>, cudaFuncAttributeMaxDynamicSharedMemorySize, 2*49152);
    cudaFuncSetAttribute(mma_gemm<0,1>, cudaFuncAttributeMaxDynamicSharedMemorySize, 2*32768);
    cudaFuncSetAttribute(attn_mma,      cudaFuncAttributeMaxDynamicSharedMemorySize, ATTN_SMEM);

    // 1) splits / roundings
    split4<<<(M_ * E_) / 4 / 256, 256>>>(hidden, hidh, hidl, M_ * E_);
    tround<<<dim3(E3_ / 32, E_ / 32), dim3(32, 8)>>>(qkv_w, wqh, E_, E3_);
    tround<<<dim3(E_ / 32, E_ / 32),  dim3(32, 8)>>>(wo_w,  woh, E_, E_);

    // 2) QKV projection (2-term: hidden exact, weights rounded; q/k/v stored f16)
    mma_gemm<1,2><<<dim3(E3_ / 128, M_ / 128), 256, 2*49152>>>(
        hidh, hidl, wqh, qkv_b, nullptr, M_, E3_, E_);

    // 3) attention (QK 1-term, PV 1-term)
    attn_mma<<<dim3(S_ / 128, BH_), 256, ATTN_SMEM>>>(mask);

    // 4) output projection (1-term: attn rounded, wo rounded)
    mma_gemm<0,1><<<dim3(E_ / 128, M_ / 128), 256, 2*32768>>>(
        ah, nullptr, woh, wo_b, out, M_, E_, E_);
}

// round 12
// speedup vs baseline: 2.6085x; 1.2430x over previous
#include <cuda_runtime.h>
#include <cuda_fp16.h>
#include <math.h>
#include <stdint.h>

#define B_ 4
#define S_ 2048
#define H_ 16
#define D_ 64
#define E_ 1024
#define E3_ 3072
#define BH_ (B_*H_)
#define M_ (B_*S_)   // 8192

// ---------------- device-global scratch (allocation-free rule) ----------------
__device__ __half g_hidh[M_*E_];                     // hidden rounded once
__device__ __half g_wqh[E3_*E_];                     // qkv_w^T rounded [N][K]
__device__ __half g_woh[E_*E_];                      // wo_w^T rounded  [N][K]
__device__ __half g_qh[BH_*S_*D_];                   // q rounded (pre-scaled 0.125)
__device__ __half g_kh[BH_*S_*D_];                   // k rounded
__device__ __half g_vh[BH_*S_*D_];                   // v rounded
__device__ __half g_ah[M_*E_];                       // attn out rounded

// ---------------- helpers ----------------
__device__ __forceinline__ void ldsm4(uint32_t* r, uint32_t addr) {
    asm volatile("ldmatrix.sync.aligned.m8n8.x4.shared.b16 {%0,%1,%2,%3}, [%4];"
                 : "=r"(r[0]), "=r"(r[1]), "=r"(r[2]), "=r"(r[3]) : "r"(addr));
}
__device__ __forceinline__ void ldsm4t(uint32_t* r, uint32_t addr) {
    asm volatile("ldmatrix.sync.aligned.m8n8.x4.trans.shared.b16 {%0,%1,%2,%3}, [%4];"
                 : "=r"(r[0]), "=r"(r[1]), "=r"(r[2]), "=r"(r[3]) : "r"(addr));
}
__device__ __forceinline__ void mma16816(float* c, const uint32_t* a, const uint32_t* b) {
    asm volatile("mma.sync.aligned.m16n8k16.row.col.f32.f16.f16.f32 "
                 "{%0,%1,%2,%3}, {%4,%5,%6,%7}, {%8,%9}, {%0,%1,%2,%3};"
                 : "+f"(c[0]), "+f"(c[1]), "+f"(c[2]), "+f"(c[3])
                 : "r"(a[0]), "r"(a[1]), "r"(a[2]), "r"(a[3]),
                   "r"(b[0]), "r"(b[1]));
}
__device__ __forceinline__ void cpasync16(uint32_t dst, const void* src) {
    asm volatile("cp.async.cg.shared.global [%0], [%1], 16;" :: "r"(dst), "l"(src));
}
#define CP_COMMIT() asm volatile("cp.async.commit_group;")
#define CP_WAIT(N)  asm volatile("cp.async.wait_group %0;" :: "n"(N))

// ---------------- round kernels ----------------
__global__ void round4(const float* __restrict__ x, __half* __restrict__ hi, int n)
{
    int i = (blockIdx.x * blockDim.x + threadIdx.x) * 4;
    if (i >= n) return;
    float4 v = *(const float4*)(x + i);
    __half2 h0 = __floats2half2_rn(v.x, v.y);
    __half2 h1 = __floats2half2_rn(v.z, v.w);
    uint2 hh;
    hh.x = *reinterpret_cast<uint32_t*>(&h0);
    hh.y = *reinterpret_cast<uint32_t*>(&h1);
    *(uint2*)(hi + i) = hh;
}

// W [K][N] f32 -> Th [N][K] f16 (rounded once)
__global__ void tround(const float* __restrict__ W,
                       __half* __restrict__ Th, int K, int N)
{
    __shared__ float t[32][33];
    const int tx = threadIdx.x, ty = threadIdx.y;
    const int n0 = blockIdx.x * 32, k0 = blockIdx.y * 32;
#pragma unroll
    for (int j = 0; j < 4; j++)
        t[ty + j * 8][tx] = W[(size_t)(k0 + ty + j * 8) * N + n0 + tx];
    __syncthreads();
#pragma unroll
    for (int j = 0; j < 4; j++) {
        float v = t[tx][ty + j * 8];
        int n = n0 + ty + j * 8, k = k0 + tx;
        Th[(size_t)n * K + k] = __float2half_rn(v);
    }
}

// ---------------- pipelined tensor-core GEMM: C = Ah @ Bh^T + bias -----------
// 1-term pure f16.  Stage 32KB: Ah +0 | Bh +16K.
// EPI=1: scatter q/k/v rounded [b,h,s,d] (q scaled 0.125).  EPI=0: fp32 C.
#define GSTG 32768u
template<int EPI>
__global__ __launch_bounds__(256, 2)
void mma_gemm(const __half* __restrict__ Ah, const __half* __restrict__ Bth,
              const float* __restrict__ bias, float* __restrict__ C,
              int M, int N, int K)
{
    extern __shared__ char sm[];
    const uint32_t sb = (uint32_t)__cvta_generic_to_shared(sm);
    const int tid = threadIdx.x, lane = tid & 31, wid = tid >> 5;
    const int wm = wid >> 1, wn = wid & 1;
    const int bm = blockIdx.y * 128, bn = blockIdx.x * 128;

    float acc[2][8][4];
#pragma unroll
    for (int mi = 0; mi < 2; mi++)
#pragma unroll
        for (int nb = 0; nb < 8; nb++)
#pragma unroll
            for (int q = 0; q < 4; q++) acc[mi][nb][q] = 0.f;

    const int lr = (lane & 7) + ((lane >> 3) & 1) * 8;
    const int l_row0 = tid >> 3, l_ch = tid & 7;

    auto issue_stage = [&](int st, int kt) {
#pragma unroll
        for (int i = 0; i < 4; i++) {
            int row = l_row0 + i * 32;
            uint32_t soff = (uint32_t)st * GSTG + row * 128 + ((l_ch ^ (row & 7)) << 4);
            size_t ga = (size_t)(bm + row) * K + kt + l_ch * 8;
            size_t gb = (size_t)(bn + row) * K + kt + l_ch * 8;
            cpasync16(sb + soff,         Ah + ga);
            cpasync16(sb + 16384 + soff, Bth + gb);
        }
        CP_COMMIT();
    };

    issue_stage(0, 0);

    int t = 0;
    for (int kt = 0; kt < K; kt += 64, t++) {
        const int cur = t & 1;
        const bool more = (kt + 64 < K);
        if (more) { issue_stage(cur ^ 1, kt + 64); CP_WAIT(1); }
        else      { CP_WAIT(0); }
        __syncthreads();

        const uint32_t cb = sb + (uint32_t)cur * GSTG;
#pragma unroll
        for (int kk = 0; kk < 4; kk++) {
            const int lc = kk * 2 + (lane >> 4);
            uint32_t afh[2][4];
#pragma unroll
            for (int mi = 0; mi < 2; mi++) {
                int r = wm * 32 + mi * 16 + lr;
                uint32_t ad = cb + r * 128 + ((lc ^ (r & 7)) << 4);
                ldsm4(afh[mi], ad);
            }
            uint32_t bfh[8][2], t4[4];
#pragma unroll
            for (int g = 0; g < 4; g++) {
                int r = wn * 64 + g * 16 + lr;
                uint32_t ad = cb + 16384 + r * 128 + ((lc ^ (r & 7)) << 4);
                ldsm4(t4, ad);
                bfh[2*g][0] = t4[0]; bfh[2*g][1] = t4[2];
                bfh[2*g+1][0] = t4[1]; bfh[2*g+1][1] = t4[3];
            }
#pragma unroll
            for (int mi = 0; mi < 2; mi++)
#pragma unroll
                for (int nb = 0; nb < 8; nb++)
                    mma16816(acc[mi][nb], afh[mi], bfh[nb]);
        }
        __syncthreads();
    }

    // epilogue
#pragma unroll
    for (int mi = 0; mi < 2; mi++) {
        const int rbase = bm + wm * 32 + mi * 16 + (lane >> 2);
#pragma unroll
        for (int nb = 0; nb < 8; nb++) {
            const int cc = bn + wn * 64 + nb * 8 + (lane & 3) * 2;
            const float b0 = bias[cc], b1 = bias[cc + 1];
#pragma unroll
            for (int hr = 0; hr < 2; hr++) {
                const int r = rbase + hr * 8;
                float v0 = acc[mi][nb][hr * 2 + 0] + b0;
                float v1 = acc[mi][nb][hr * 2 + 1] + b1;
                if (EPI == 1) {
                    const int bb = r >> 11, si = r & 2047;
                    const int sec = cc >> 10, win = cc & 1023;
                    const int hh = win >> 6, dd = win & 63;
                    size_t off = (((size_t)bb * H_ + hh) * S_ + si) * D_ + dd;
                    __half* dst;
                    if (sec == 0) { v0 *= 0.125f; v1 *= 0.125f; dst = g_qh; }
                    else if (sec == 1) dst = g_kh;
                    else dst = g_vh;
                    __half2 h2 = __floats2half2_rn(v0, v1);
                    *(__half2*)(dst + off) = h2;
                } else {
                    float2 v; v.x = v0; v.y = v1;
                    *(float2*)(C + (size_t)r * N + cc) = v;
                }
            }
        }
    }
}

// ---------------- flash attention, 8 warps / 128 queries ---------------------
// S = Qh @ Kh^T (1 mma) ; O += Ph @ Vh (1 mma).  Q/K/V/P each rounded once.
// smem: Qh 0 (16K) | stages at 16K: {Kh 0..8K, Vh 8K..16K} x2 | Mf at 48K
#define ASTAGE 16384
#define A_STG0 16384
#define A_MF   (A_STG0 + 2*ASTAGE)
#define ATTN_SMEM (A_MF + 2*64*4)

__global__ __launch_bounds__(256)
void attn_mma(const int* __restrict__ mask)
{
    extern __shared__ char sm[];
    const uint32_t sb = (uint32_t)__cvta_generic_to_shared(sm);
    float* Mf = (float*)(sm + A_MF);   // [2][64]
    const int tid = threadIdx.x, lane = tid & 31, w = tid >> 5;
    const int qb = blockIdx.x * 128, bh = blockIdx.y;
    const int b = bh >> 4, h = bh & 15;
    const size_t base = (size_t)bh * S_ * D_;
    const int lr = (lane & 7) + ((lane >> 3) & 1) * 8;
    const int* mrow = mask + b * S_;

    auto issue_kv = [&](int st, int kt) {
        for (int i = tid; i < 512; i += 256) {
            int row = i >> 3, ch = i & 7;
            uint32_t soff = A_STG0 + (uint32_t)st * ASTAGE + row * 128 + ((ch ^ (row & 7)) << 4);
            size_t g = base + (size_t)(kt + row) * D_ + ch * 8;
            cpasync16(sb + soff,         g_kh + g);
            cpasync16(sb + soff + 8192,  g_vh + g);
        }
        if (tid < 64) Mf[st * 64 + tid] = mrow[kt + tid] ? 1.0f : 0.0f;
        CP_COMMIT();
    };

    issue_kv(0, 0);

    // stage Q tile (128 rows, rounded)
    for (int i = tid; i < 1024; i += 256) {
        int row = i >> 3, ch = i & 7;
        uint32_t soff = row * 128 + ((ch ^ (row & 7)) << 4);
        size_t g = base + (size_t)(qb + row) * D_ + ch * 8;
        *(uint4*)(sm + soff) = *(const uint4*)(g_qh + g);
    }
    __syncthreads();

    uint32_t qfh[4][4];
#pragma unroll
    for (int kk = 0; kk < 4; kk++) {
        int r = w * 16 + lr;
        int c = kk * 2 + (lane >> 4);
        uint32_t ad = sb + r * 128 + ((c ^ (r & 7)) << 4);
        ldsm4(qfh[kk], ad);
    }

    float O[8][4];
#pragma unroll
    for (int nb = 0; nb < 8; nb++)
#pragma unroll
        for (int q = 0; q < 4; q++) O[nb][q] = 0.f;
    float m0 = -1e30f, m1 = -1e30f, l0 = 0.f, l1 = 0.f;

    for (int t = 0; t < S_ / 64; t++) {
        const int cur = t & 1;
        const bool more = (t + 1 < S_ / 64);
        if (more) { issue_kv(cur ^ 1, (t + 1) * 64); CP_WAIT(1); }
        else      { CP_WAIT(0); }
        __syncthreads();

        const uint32_t kb = sb + A_STG0 + (uint32_t)cur * ASTAGE;
        const float* mf = Mf + cur * 64;

        // S = Qh Kh^T   (Q pre-scaled by 0.125)
        float S[8][4];
#pragma unroll
        for (int nb = 0; nb < 8; nb++)
#pragma unroll
            for (int q = 0; q < 4; q++) S[nb][q] = 0.f;
#pragma unroll
        for (int kk = 0; kk < 4; kk++) {
            const int lc = kk * 2 + (lane >> 4);
            uint32_t bfh[8][2], t4[4];
#pragma unroll
            for (int g = 0; g < 4; g++) {
                int r = g * 16 + lr;
                uint32_t ad = kb + r * 128 + ((lc ^ (r & 7)) << 4);
                ldsm4(t4, ad);
                bfh[2*g][0] = t4[0]; bfh[2*g][1] = t4[2];
                bfh[2*g+1][0] = t4[1]; bfh[2*g+1][1] = t4[3];
            }
#pragma unroll
            for (int nb = 0; nb < 8; nb++)
                mma16816(S[nb], qfh[kk], bfh[nb]);
        }

        // mask + online softmax
        float mk0[8], mk1[8];
#pragma unroll
        for (int nb = 0; nb < 8; nb++) {
            int c = nb * 8 + (lane & 3) * 2;
            mk0[nb] = mf[c]; mk1[nb] = mf[c + 1];
        }
        float mx0 = -1e30f, mx1 = -1e30f;
#pragma unroll
        for (int nb = 0; nb < 8; nb++) {
            S[nb][0] = (mk0[nb] != 0.f) ? S[nb][0] : -1e30f;
            S[nb][1] = (mk1[nb] != 0.f) ? S[nb][1] : -1e30f;
            S[nb][2] = (mk0[nb] != 0.f) ? S[nb][2] : -1e30f;
            S[nb][3] = (mk1[nb] != 0.f) ? S[nb][3] : -1e30f;
            mx0 = fmaxf(mx0, fmaxf(S[nb][0], S[nb][1]));
            mx1 = fmaxf(mx1, fmaxf(S[nb][2], S[nb][3]));
        }
        mx0 = fmaxf(mx0, __shfl_xor_sync(0xffffffffu, mx0, 1));
        mx0 = fmaxf(mx0, __shfl_xor_sync(0xffffffffu, mx0, 2));
        mx1 = fmaxf(mx1, __shfl_xor_sync(0xffffffffu, mx1, 1));
        mx1 = fmaxf(mx1, __shfl_xor_sync(0xffffffffu, mx1, 2));
        const float mn0 = fmaxf(m0, mx0), mn1 = fmaxf(m1, mx1);
        const float a0 = __expf(m0 - mn0), a1 = __expf(m1 - mn1);
        m0 = mn0; m1 = mn1;
        float s0 = 0.f, s1 = 0.f;
#pragma unroll
        for (int nb = 0; nb < 8; nb++) {
            float p0 = __expf(S[nb][0] - mn0) * mk0[nb];
            float p1 = __expf(S[nb][1] - mn0) * mk1[nb];
            float p2 = __expf(S[nb][2] - mn1) * mk0[nb];
            float p3 = __expf(S[nb][3] - mn1) * mk1[nb];
            S[nb][0] = p0; S[nb][1] = p1; S[nb][2] = p2; S[nb][3] = p3;
            s0 += p0 + p1; s1 += p2 + p3;
        }
        s0 += __shfl_xor_sync(0xffffffffu, s0, 1);
        s0 += __shfl_xor_sync(0xffffffffu, s0, 2);
        s1 += __shfl_xor_sync(0xffffffffu, s1, 1);
        s1 += __shfl_xor_sync(0xffffffffu, s1, 2);
        l0 = l0 * a0 + s0; l1 = l1 * a1 + s1;
#pragma unroll
        for (int nb = 0; nb < 8; nb++) {
            O[nb][0] *= a0; O[nb][1] *= a0; O[nb][2] *= a1; O[nb][3] *= a1;
        }

        // O += Ph Vh   (P rounded once to f16)
#pragma unroll
        for (int kk = 0; kk < 4; kk++) {
            uint32_t ph[4];
            {
                __half2 t0 = __floats2half2_rn(S[2*kk][0],   S[2*kk][1]);
                __half2 t1 = __floats2half2_rn(S[2*kk][2],   S[2*kk][3]);
                __half2 t2 = __floats2half2_rn(S[2*kk+1][0], S[2*kk+1][1]);
                __half2 t3 = __floats2half2_rn(S[2*kk+1][2], S[2*kk+1][3]);
                ph[0] = *reinterpret_cast<uint32_t*>(&t0);
                ph[1] = *reinterpret_cast<uint32_t*>(&t1);
                ph[2] = *reinterpret_cast<uint32_t*>(&t2);
                ph[3] = *reinterpret_cast<uint32_t*>(&t3);
            }
            uint32_t vfh[8][2], t4[4];
#pragma unroll
            for (int g = 0; g < 4; g++) {
                int r = kk * 16 + lr;
                int c = g * 2 + (lane >> 4);
                uint32_t ad = kb + 8192 + r * 128 + ((c ^ (r & 7)) << 4);
                ldsm4t(t4, ad);
                vfh[2*g][0] = t4[0]; vfh[2*g][1] = t4[1];
                vfh[2*g+1][0] = t4[2]; vfh[2*g+1][1] = t4[3];
            }
#pragma unroll
            for (int nb = 0; nb < 8; nb++)
                mma16816(O[nb], ph, vfh[nb]);
        }
        __syncthreads();
    }

    // epilogue: normalize, round once, store attn [b,s,e]
    const float inv0 = 1.0f / l0, inv1 = 1.0f / l1;
    const int s0r = qb + w * 16 + (lane >> 2);
#pragma unroll
    for (int nb = 0; nb < 8; nb++) {
        const int d = nb * 8 + (lane & 3) * 2;
        size_t off = ((size_t)b * S_ + s0r) * E_ + h * 64 + d;
        __half2 h2 = __floats2half2_rn(O[nb][0] * inv0, O[nb][1] * inv0);
        *(__half2*)(g_ah + off) = h2;
        off += (size_t)8 * E_;
        h2 = __floats2half2_rn(O[nb][2] * inv1, O[nb][3] * inv1);
        *(__half2*)(g_ah + off) = h2;
    }
}

// ---------------------------------------------------------------------------
extern "C" void kernel_launch(void* const* d_in, const int* in_sizes, int n_in,
                              void* d_out, int out_size)
{
    const float* hidden = (const float*)d_in[0];
    const float* qkv_w  = (const float*)d_in[1];
    const float* qkv_b  = (const float*)d_in[2];
    const float* wo_w   = (const float*)d_in[3];
    const float* wo_b   = (const float*)d_in[4];
    const int*   mask   = (const int*)d_in[5];
    float* out = (float*)d_out;

    __half *hidh, *wqh, *woh, *ah;
    cudaGetSymbolAddress((void**)&hidh, g_hidh);
    cudaGetSymbolAddress((void**)&wqh,  g_wqh);
    cudaGetSymbolAddress((void**)&woh,  g_woh);
    cudaGetSymbolAddress((void**)&ah,   g_ah);

    cudaFuncSetAttribute(mma_gemm<1>, cudaFuncAttributeMaxDynamicSharedMemorySize, (int)(2*GSTG));
    cudaFuncSetAttribute(mma_gemm<0>, cudaFuncAttributeMaxDynamicSharedMemorySize, (int)(2*GSTG));
    cudaFuncSetAttribute(attn_mma,    cudaFuncAttributeMaxDynamicSharedMemorySize, ATTN_SMEM);

    // 1) roundings
    round4<<<(M_ * E_) / 4 / 256, 256>>>(hidden, hidh, M_ * E_);
    tround<<<dim3(E3_ / 32, E_ / 32), dim3(32, 8)>>>(qkv_w, wqh, E_, E3_);
    tround<<<dim3(E_ / 32, E_ / 32),  dim3(32, 8)>>>(wo_w,  woh, E_, E_);

    // 2) QKV projection (1-term f16)
    mma_gemm<1><<<dim3(E3_ / 128, M_ / 128), 256, 2*GSTG>>>(
        hidh, wqh, qkv_b, nullptr, M_, E3_, E_);

    // 3) attention (QK 1-term, PV 1-term)
    attn_mma<<<dim3(S_ / 128, BH_), 256, ATTN_SMEM>>>(mask);

    // 4) output projection (1-term f16)
    mma_gemm<0><<<dim3(E_ / 128, M_ / 128), 256, 2*GSTG>>>(
        ah, woh, wo_b, out, M_, E_, E_);
}

// round 13
// speedup vs baseline: 2.6794x; 1.0272x over previous
#include <cuda_runtime.h>
#include <cuda_fp16.h>
#include <math.h>
#include <stdint.h>

#define B_ 4
#define S_ 2048
#define H_ 16
#define D_ 64
#define E_ 1024
#define E3_ 3072
#define BH_ (B_*H_)
#define M_ (B_*S_)   // 8192

// ---------------- device-global scratch (allocation-free rule) ----------------
__device__ __half g_hidh[M_*E_];                     // hidden rounded once
__device__ __half g_wqh[E3_*E_];                     // qkv_w^T rounded [N][K]
__device__ __half g_woh[E_*E_];                      // wo_w^T rounded  [N][K]
__device__ __half g_qh[BH_*S_*D_];                   // q rounded (pre-scaled 0.125)
__device__ __half g_kh[BH_*S_*D_];                   // k rounded
__device__ __half g_vh[BH_*S_*D_];                   // v rounded
__device__ __half g_ah[M_*E_];                       // attn out rounded

// ---------------- helpers ----------------
__device__ __forceinline__ void ldsm4(uint32_t* r, uint32_t addr) {
    asm volatile("ldmatrix.sync.aligned.m8n8.x4.shared.b16 {%0,%1,%2,%3}, [%4];"
                 : "=r"(r[0]), "=r"(r[1]), "=r"(r[2]), "=r"(r[3]) : "r"(addr));
}
__device__ __forceinline__ void ldsm4t(uint32_t* r, uint32_t addr) {
    asm volatile("ldmatrix.sync.aligned.m8n8.x4.trans.shared.b16 {%0,%1,%2,%3}, [%4];"
                 : "=r"(r[0]), "=r"(r[1]), "=r"(r[2]), "=r"(r[3]) : "r"(addr));
}
__device__ __forceinline__ void mma16816(float* c, const uint32_t* a, const uint32_t* b) {
    asm volatile("mma.sync.aligned.m16n8k16.row.col.f32.f16.f16.f32 "
                 "{%0,%1,%2,%3}, {%4,%5,%6,%7}, {%8,%9}, {%0,%1,%2,%3};"
                 : "+f"(c[0]), "+f"(c[1]), "+f"(c[2]), "+f"(c[3])
                 : "r"(a[0]), "r"(a[1]), "r"(a[2]), "r"(a[3]),
                   "r"(b[0]), "r"(b[1]));
}
__device__ __forceinline__ void cpasync16(uint32_t dst, const void* src) {
    asm volatile("cp.async.cg.shared.global [%0], [%1], 16;" :: "r"(dst), "l"(src));
}
#define CP_COMMIT() asm volatile("cp.async.commit_group;")
#define CP_WAIT(N)  asm volatile("cp.async.wait_group %0;" :: "n"(N))

// ---------------- round kernels ----------------
__global__ void round4(const float* __restrict__ x, __half* __restrict__ hi, int n)
{
    int i = (blockIdx.x * blockDim.x + threadIdx.x) * 4;
    if (i >= n) return;
    float4 v = *(const float4*)(x + i);
    __half2 h0 = __floats2half2_rn(v.x, v.y);
    __half2 h1 = __floats2half2_rn(v.z, v.w);
    uint2 hh;
    hh.x = *reinterpret_cast<uint32_t*>(&h0);
    hh.y = *reinterpret_cast<uint32_t*>(&h1);
    *(uint2*)(hi + i) = hh;
}

// W [K][N] f32 -> Th [N][K] f16 (rounded once)
__global__ void tround(const float* __restrict__ W,
                       __half* __restrict__ Th, int K, int N)
{
    __shared__ float t[32][33];
    const int tx = threadIdx.x, ty = threadIdx.y;
    const int n0 = blockIdx.x * 32, k0 = blockIdx.y * 32;
#pragma unroll
    for (int j = 0; j < 4; j++)
        t[ty + j * 8][tx] = W[(size_t)(k0 + ty + j * 8) * N + n0 + tx];
    __syncthreads();
#pragma unroll
    for (int j = 0; j < 4; j++) {
        float v = t[tx][ty + j * 8];
        int n = n0 + ty + j * 8, k = k0 + tx;
        Th[(size_t)n * K + k] = __float2half_rn(v);
    }
}

// ---------------- pipelined tensor-core GEMM: C = Ah @ Bh^T + bias -----------
// 128 threads / 4 warps, 64x64 warp tiles (128x128 block).  Stage 32KB.
// Per k16: 4 A-ldsm + 4 B-ldsm feed 32 mma (128 B smem per mma).
// EPI=1: scatter q/k/v rounded [b,h,s,d] (q scaled 0.125).  EPI=0: fp32 C.
#define GSTG 32768u
template<int EPI>
__global__ __launch_bounds__(128, 2)
void mma_gemm(const __half* __restrict__ Ah, const __half* __restrict__ Bth,
              const float* __restrict__ bias, float* __restrict__ C,
              int M, int N, int K)
{
    extern __shared__ char sm[];
    const uint32_t sb = (uint32_t)__cvta_generic_to_shared(sm);
    const int tid = threadIdx.x, lane = tid & 31, wid = tid >> 5;
    const int wm = wid >> 1, wn = wid & 1;
    const int bm = blockIdx.y * 128, bn = blockIdx.x * 128;

    float acc[4][8][4];
#pragma unroll
    for (int mi = 0; mi < 4; mi++)
#pragma unroll
        for (int nb = 0; nb < 8; nb++)
#pragma unroll
            for (int q = 0; q < 4; q++) acc[mi][nb][q] = 0.f;

    const int lr = (lane & 7) + ((lane >> 3) & 1) * 8;
    const int l_row0 = tid >> 3, l_ch = tid & 7;   // 16 rows per pass of 128 thr

    auto issue_stage = [&](int st, int kt) {
#pragma unroll
        for (int i = 0; i < 8; i++) {
            int row = l_row0 + i * 16;
            uint32_t soff = (uint32_t)st * GSTG + row * 128 + ((l_ch ^ (row & 7)) << 4);
            size_t ga = (size_t)(bm + row) * K + kt + l_ch * 8;
            size_t gb = (size_t)(bn + row) * K + kt + l_ch * 8;
            cpasync16(sb + soff,         Ah + ga);
            cpasync16(sb + 16384 + soff, Bth + gb);
        }
        CP_COMMIT();
    };

    issue_stage(0, 0);

    int t = 0;
    for (int kt = 0; kt < K; kt += 64, t++) {
        const int cur = t & 1;
        const bool more = (kt + 64 < K);
        if (more) { issue_stage(cur ^ 1, kt + 64); CP_WAIT(1); }
        else      { CP_WAIT(0); }
        __syncthreads();

        const uint32_t cb = sb + (uint32_t)cur * GSTG;
#pragma unroll
        for (int kk = 0; kk < 4; kk++) {
            const int lc = kk * 2 + (lane >> 4);
            uint32_t afh[4][4];
#pragma unroll
            for (int mi = 0; mi < 4; mi++) {
                int r = wm * 64 + mi * 16 + lr;
                uint32_t ad = cb + r * 128 + ((lc ^ (r & 7)) << 4);
                ldsm4(afh[mi], ad);
            }
            uint32_t bfh[8][2], t4[4];
#pragma unroll
            for (int g = 0; g < 4; g++) {
                int r = wn * 64 + g * 16 + lr;
                uint32_t ad = cb + 16384 + r * 128 + ((lc ^ (r & 7)) << 4);
                ldsm4(t4, ad);
                bfh[2*g][0] = t4[0]; bfh[2*g][1] = t4[2];
                bfh[2*g+1][0] = t4[1]; bfh[2*g+1][1] = t4[3];
            }
#pragma unroll
            for (int mi = 0; mi < 4; mi++)
#pragma unroll
                for (int nb = 0; nb < 8; nb++)
                    mma16816(acc[mi][nb], afh[mi], bfh[nb]);
        }
        __syncthreads();
    }

    // epilogue
#pragma unroll
    for (int mi = 0; mi < 4; mi++) {
        const int rbase = bm + wm * 64 + mi * 16 + (lane >> 2);
#pragma unroll
        for (int nb = 0; nb < 8; nb++) {
            const int cc = bn + wn * 64 + nb * 8 + (lane & 3) * 2;
            const float b0 = bias[cc], b1 = bias[cc + 1];
#pragma unroll
            for (int hr = 0; hr < 2; hr++) {
                const int r = rbase + hr * 8;
                float v0 = acc[mi][nb][hr * 2 + 0] + b0;
                float v1 = acc[mi][nb][hr * 2 + 1] + b1;
                if (EPI == 1) {
                    const int bb = r >> 11, si = r & 2047;
                    const int sec = cc >> 10, win = cc & 1023;
                    const int hh = win >> 6, dd = win & 63;
                    size_t off = (((size_t)bb * H_ + hh) * S_ + si) * D_ + dd;
                    __half* dst;
                    if (sec == 0) { v0 *= 0.125f; v1 *= 0.125f; dst = g_qh; }
                    else if (sec == 1) dst = g_kh;
                    else dst = g_vh;
                    __half2 h2 = __floats2half2_rn(v0, v1);
                    *(__half2*)(dst + off) = h2;
                } else {
                    float2 v; v.x = v0; v.y = v1;
                    *(float2*)(C + (size_t)r * N + cc) = v;
                }
            }
        }
    }
}

// ---------------- flash attention: 4 warps / 128 queries, 32 q per warp ------
// Per k16: 4 K-ldsm feed 16 mma (QK); 4 V-ldsmt feed 16 mma (PV).
// smem: Qh 0 (16K) | stages at 16K: {Kh 0..8K, Vh 8K..16K} x2 | Mf at 48K
#define ASTAGE 16384
#define A_STG0 16384
#define A_MF   (A_STG0 + 2*ASTAGE)
#define ATTN_SMEM (A_MF + 2*64*4)

__global__ __launch_bounds__(128, 2)
void attn_mma(const int* __restrict__ mask)
{
    extern __shared__ char sm[];
    const uint32_t sb = (uint32_t)__cvta_generic_to_shared(sm);
    float* Mf = (float*)(sm + A_MF);   // [2][64]
    const int tid = threadIdx.x, lane = tid & 31, w = tid >> 5;
    const int qb = blockIdx.x * 128, bh = blockIdx.y;
    const int b = bh >> 4, h = bh & 15;
    const size_t base = (size_t)bh * S_ * D_;
    const int lr = (lane & 7) + ((lane >> 3) & 1) * 8;
    const int* mrow = mask + b * S_;

    auto issue_kv = [&](int st, int kt) {
        for (int i = tid; i < 512; i += 128) {
            int row = i >> 3, ch = i & 7;
            uint32_t soff = A_STG0 + (uint32_t)st * ASTAGE + row * 128 + ((ch ^ (row & 7)) << 4);
            size_t g = base + (size_t)(kt + row) * D_ + ch * 8;
            cpasync16(sb + soff,         g_kh + g);
            cpasync16(sb + soff + 8192,  g_vh + g);
        }
        if (tid < 64) Mf[st * 64 + tid] = mrow[kt + tid] ? 1.0f : 0.0f;
        CP_COMMIT();
    };

    issue_kv(0, 0);

    // stage Q tile (128 rows, rounded)
    for (int i = tid; i < 1024; i += 128) {
        int row = i >> 3, ch = i & 7;
        uint32_t soff = row * 128 + ((ch ^ (row & 7)) << 4);
        size_t g = base + (size_t)(qb + row) * D_ + ch * 8;
        *(uint4*)(sm + soff) = *(const uint4*)(g_qh + g);
    }
    __syncthreads();

    uint32_t qfh[2][4][4];   // [mi][kk]
#pragma unroll
    for (int mi = 0; mi < 2; mi++)
#pragma unroll
        for (int kk = 0; kk < 4; kk++) {
            int r = w * 32 + mi * 16 + lr;
            int c = kk * 2 + (lane >> 4);
            uint32_t ad = sb + r * 128 + ((c ^ (r & 7)) << 4);
            ldsm4(qfh[mi][kk], ad);
        }

    float O[2][8][4];
    float m_[2][2], l_[2][2];
#pragma unroll
    for (int mi = 0; mi < 2; mi++) {
#pragma unroll
        for (int nb = 0; nb < 8; nb++)
#pragma unroll
            for (int q = 0; q < 4; q++) O[mi][nb][q] = 0.f;
        m_[mi][0] = -1e30f; m_[mi][1] = -1e30f;
        l_[mi][0] = 0.f;    l_[mi][1] = 0.f;
    }

    for (int t = 0; t < S_ / 64; t++) {
        const int cur = t & 1;
        const bool more = (t + 1 < S_ / 64);
        if (more) { issue_kv(cur ^ 1, (t + 1) * 64); CP_WAIT(1); }
        else      { CP_WAIT(0); }
        __syncthreads();

        const uint32_t kb = sb + A_STG0 + (uint32_t)cur * ASTAGE;
        const float* mf = Mf + cur * 64;

        // S = Qh Kh^T   (Q pre-scaled by 0.125)
        float S[2][8][4];
#pragma unroll
        for (int mi = 0; mi < 2; mi++)
#pragma unroll
            for (int nb = 0; nb < 8; nb++)
#pragma unroll
                for (int q = 0; q < 4; q++) S[mi][nb][q] = 0.f;
#pragma unroll
        for (int kk = 0; kk < 4; kk++) {
            const int lc = kk * 2 + (lane >> 4);
            uint32_t bfh[8][2], t4[4];
#pragma unroll
            for (int g = 0; g < 4; g++) {
                int r = g * 16 + lr;
                uint32_t ad = kb + r * 128 + ((lc ^ (r & 7)) << 4);
                ldsm4(t4, ad);
                bfh[2*g][0] = t4[0]; bfh[2*g][1] = t4[2];
                bfh[2*g+1][0] = t4[1]; bfh[2*g+1][1] = t4[3];
            }
#pragma unroll
            for (int mi = 0; mi < 2; mi++)
#pragma unroll
                for (int nb = 0; nb < 8; nb++)
                    mma16816(S[mi][nb], qfh[mi][kk], bfh[nb]);
        }

        // mask + online softmax (column masks shared across mi)
        float mk0[8], mk1[8];
#pragma unroll
        for (int nb = 0; nb < 8; nb++) {
            int c = nb * 8 + (lane & 3) * 2;
            mk0[nb] = mf[c]; mk1[nb] = mf[c + 1];
        }
#pragma unroll
        for (int mi = 0; mi < 2; mi++) {
            float mx0 = -1e30f, mx1 = -1e30f;
#pragma unroll
            for (int nb = 0; nb < 8; nb++) {
                S[mi][nb][0] = (mk0[nb] != 0.f) ? S[mi][nb][0] : -1e30f;
                S[mi][nb][1] = (mk1[nb] != 0.f) ? S[mi][nb][1] : -1e30f;
                S[mi][nb][2] = (mk0[nb] != 0.f) ? S[mi][nb][2] : -1e30f;
                S[mi][nb][3] = (mk1[nb] != 0.f) ? S[mi][nb][3] : -1e30f;
                mx0 = fmaxf(mx0, fmaxf(S[mi][nb][0], S[mi][nb][1]));
                mx1 = fmaxf(mx1, fmaxf(S[mi][nb][2], S[mi][nb][3]));
            }
            mx0 = fmaxf(mx0, __shfl_xor_sync(0xffffffffu, mx0, 1));
            mx0 = fmaxf(mx0, __shfl_xor_sync(0xffffffffu, mx0, 2));
            mx1 = fmaxf(mx1, __shfl_xor_sync(0xffffffffu, mx1, 1));
            mx1 = fmaxf(mx1, __shfl_xor_sync(0xffffffffu, mx1, 2));
            const float mn0 = fmaxf(m_[mi][0], mx0), mn1 = fmaxf(m_[mi][1], mx1);
            const float a0 = __expf(m_[mi][0] - mn0), a1 = __expf(m_[mi][1] - mn1);
            m_[mi][0] = mn0; m_[mi][1] = mn1;
            float s0 = 0.f, s1 = 0.f;
#pragma unroll
            for (int nb = 0; nb < 8; nb++) {
                float p0 = __expf(S[mi][nb][0] - mn0) * mk0[nb];
                float p1 = __expf(S[mi][nb][1] - mn0) * mk1[nb];
                float p2 = __expf(S[mi][nb][2] - mn1) * mk0[nb];
                float p3 = __expf(S[mi][nb][3] - mn1) * mk1[nb];
                S[mi][nb][0] = p0; S[mi][nb][1] = p1; S[mi][nb][2] = p2; S[mi][nb][3] = p3;
                s0 += p0 + p1; s1 += p2 + p3;
            }
            s0 += __shfl_xor_sync(0xffffffffu, s0, 1);
            s0 += __shfl_xor_sync(0xffffffffu, s0, 2);
            s1 += __shfl_xor_sync(0xffffffffu, s1, 1);
            s1 += __shfl_xor_sync(0xffffffffu, s1, 2);
            l_[mi][0] = l_[mi][0] * a0 + s0;
            l_[mi][1] = l_[mi][1] * a1 + s1;
#pragma unroll
            for (int nb = 0; nb < 8; nb++) {
                O[mi][nb][0] *= a0; O[mi][nb][1] *= a0;
                O[mi][nb][2] *= a1; O[mi][nb][3] *= a1;
            }
        }

        // O += Ph Vh   (P rounded once to f16; V frags shared across mi)
#pragma unroll
        for (int kk = 0; kk < 4; kk++) {
            uint32_t ph[2][4];
#pragma unroll
            for (int mi = 0; mi < 2; mi++) {
                __half2 t0 = __floats2half2_rn(S[mi][2*kk][0],   S[mi][2*kk][1]);
                __half2 t1 = __floats2half2_rn(S[mi][2*kk][2],   S[mi][2*kk][3]);
                __half2 t2 = __floats2half2_rn(S[mi][2*kk+1][0], S[mi][2*kk+1][1]);
                __half2 t3 = __floats2half2_rn(S[mi][2*kk+1][2], S[mi][2*kk+1][3]);
                ph[mi][0] = *reinterpret_cast<uint32_t*>(&t0);
                ph[mi][1] = *reinterpret_cast<uint32_t*>(&t1);
                ph[mi][2] = *reinterpret_cast<uint32_t*>(&t2);
                ph[mi][3] = *reinterpret_cast<uint32_t*>(&t3);
            }
            uint32_t vfh[8][2], t4[4];
#pragma unroll
            for (int g = 0; g < 4; g++) {
                int r = kk * 16 + lr;
                int c = g * 2 + (lane >> 4);
                uint32_t ad = kb + 8192 + r * 128 + ((c ^ (r & 7)) << 4);
                ldsm4t(t4, ad);
                vfh[2*g][0] = t4[0]; vfh[2*g][1] = t4[1];
                vfh[2*g+1][0] = t4[2]; vfh[2*g+1][1] = t4[3];
            }
#pragma unroll
            for (int mi = 0; mi < 2; mi++)
#pragma unroll
                for (int nb = 0; nb < 8; nb++)
                    mma16816(O[mi][nb], ph[mi], vfh[nb]);
        }
        __syncthreads();
    }

    // epilogue: normalize, round once, store attn [b,s,e]
#pragma unroll
    for (int mi = 0; mi < 2; mi++) {
        const float inv0 = 1.0f / l_[mi][0], inv1 = 1.0f / l_[mi][1];
        const int s0r = qb + w * 32 + mi * 16 + (lane >> 2);
#pragma unroll
        for (int nb = 0; nb < 8; nb++) {
            const int d = nb * 8 + (lane & 3) * 2;
            size_t off = ((size_t)b * S_ + s0r) * E_ + h * 64 + d;
            __half2 h2 = __floats2half2_rn(O[mi][nb][0] * inv0, O[mi][nb][1] * inv0);
            *(__half2*)(g_ah + off) = h2;
            off += (size_t)8 * E_;
            h2 = __floats2half2_rn(O[mi][nb][2] * inv1, O[mi][nb][3] * inv1);
            *(__half2*)(g_ah + off) = h2;
        }
    }
}

// ---------------------------------------------------------------------------
extern "C" void kernel_launch(void* const* d_in, const int* in_sizes, int n_in,
                              void* d_out, int out_size)
{
    const float* hidden = (const float*)d_in[0];
    const float* qkv_w  = (const float*)d_in[1];
    const float* qkv_b  = (const float*)d_in[2];
    const float* wo_w   = (const float*)d_in[3];
    const float* wo_b   = (const float*)d_in[4];
    const int*   mask   = (const int*)d_in[5];
    float* out = (float*)d_out;

    __half *hidh, *wqh, *woh, *ah;
    cudaGetSymbolAddress((void**)&hidh, g_hidh);
    cudaGetSymbolAddress((void**)&wqh,  g_wqh);
    cudaGetSymbolAddress((void**)&woh,  g_woh);
    cudaGetSymbolAddress((void**)&ah,   g_ah);

    cudaFuncSetAttribute(mma_gemm<1>, cudaFuncAttributeMaxDynamicSharedMemorySize, (int)(2*GSTG));
    cudaFuncSetAttribute(mma_gemm<0>, cudaFuncAttributeMaxDynamicSharedMemorySize, (int)(2*GSTG));
    cudaFuncSetAttribute(attn_mma,    cudaFuncAttributeMaxDynamicSharedMemorySize, ATTN_SMEM);

    // 1) roundings
    round4<<<(M_ * E_) / 4 / 256, 256>>>(hidden, hidh, M_ * E_);
    tround<<<dim3(E3_ / 32, E_ / 32), dim3(32, 8)>>>(qkv_w, wqh, E_, E3_);
    tround<<<dim3(E_ / 32, E_ / 32),  dim3(32, 8)>>>(wo_w,  woh, E_, E_);

    // 2) QKV projection (1-term f16, 64x64 warp tiles)
    mma_gemm<1><<<dim3(E3_ / 128, M_ / 128), 128, 2*GSTG>>>(
        hidh, wqh, qkv_b, nullptr, M_, E3_, E_);

    // 3) attention (32 q per warp)
    attn_mma<<<dim3(S_ / 128, BH_), 128, ATTN_SMEM>>>(mask);

    // 4) output projection (1-term f16, 64x64 warp tiles)
    mma_gemm<0><<<dim3(E_ / 128, M_ / 128), 128, 2*GSTG>>>(
        ah, woh, wo_b, out, M_, E_, E_);
}

// round 14
// speedup vs baseline: 2.7324x; 1.0198x over previous
#include <cuda_runtime.h>
#include <cuda_fp16.h>
#include <math.h>
#include <stdint.h>

#define B_ 4
#define S_ 2048
#define H_ 16
#define D_ 64
#define E_ 1024
#define E3_ 3072
#define BH_ (B_*H_)
#define M_ (B_*S_)   // 8192

// ---------------- device-global scratch (allocation-free rule) ----------------
__device__ __half g_hidh[M_*E_];                     // hidden rounded once
__device__ __half g_wqh[E3_*E_];                     // qkv_w^T rounded [N][K]
__device__ __half g_woh[E_*E_];                      // wo_w^T rounded  [N][K]
__device__ __half g_qh[BH_*S_*D_];                   // q rounded (pre-scaled 0.125)
__device__ __half g_kh[BH_*S_*D_];                   // k rounded
__device__ __half g_vh[BH_*S_*D_];                   // v rounded
__device__ __half g_ah[M_*E_];                       // attn out rounded

// ---------------- helpers ----------------
__device__ __forceinline__ void ldsm4(uint32_t* r, uint32_t addr) {
    asm volatile("ldmatrix.sync.aligned.m8n8.x4.shared.b16 {%0,%1,%2,%3}, [%4];"
                 : "=r"(r[0]), "=r"(r[1]), "=r"(r[2]), "=r"(r[3]) : "r"(addr));
}
__device__ __forceinline__ void ldsm4t(uint32_t* r, uint32_t addr) {
    asm volatile("ldmatrix.sync.aligned.m8n8.x4.trans.shared.b16 {%0,%1,%2,%3}, [%4];"
                 : "=r"(r[0]), "=r"(r[1]), "=r"(r[2]), "=r"(r[3]) : "r"(addr));
}
__device__ __forceinline__ void mma16816(float* c, const uint32_t* a, const uint32_t* b) {
    asm volatile("mma.sync.aligned.m16n8k16.row.col.f32.f16.f16.f32 "
                 "{%0,%1,%2,%3}, {%4,%5,%6,%7}, {%8,%9}, {%0,%1,%2,%3};"
                 : "+f"(c[0]), "+f"(c[1]), "+f"(c[2]), "+f"(c[3])
                 : "r"(a[0]), "r"(a[1]), "r"(a[2]), "r"(a[3]),
                   "r"(b[0]), "r"(b[1]));
}
__device__ __forceinline__ void cpasync16(uint32_t dst, const void* src) {
    asm volatile("cp.async.cg.shared.global [%0], [%1], 16;" :: "r"(dst), "l"(src));
}
#define CP_COMMIT() asm volatile("cp.async.commit_group;")
#define CP_WAIT(N)  asm volatile("cp.async.wait_group %0;" :: "n"(N))

// ---------------- round kernels ----------------
__global__ void round4(const float* __restrict__ x, __half* __restrict__ hi, int n)
{
    int i = (blockIdx.x * blockDim.x + threadIdx.x) * 4;
    if (i >= n) return;
    float4 v = *(const float4*)(x + i);
    __half2 h0 = __floats2half2_rn(v.x, v.y);
    __half2 h1 = __floats2half2_rn(v.z, v.w);
    uint2 hh;
    hh.x = *reinterpret_cast<uint32_t*>(&h0);
    hh.y = *reinterpret_cast<uint32_t*>(&h1);
    *(uint2*)(hi + i) = hh;
}

// W [K][N] f32 -> Th [N][K] f16 (rounded once)
__global__ void tround(const float* __restrict__ W,
                       __half* __restrict__ Th, int K, int N)
{
    __shared__ float t[32][33];
    const int tx = threadIdx.x, ty = threadIdx.y;
    const int n0 = blockIdx.x * 32, k0 = blockIdx.y * 32;
#pragma unroll
    for (int j = 0; j < 4; j++)
        t[ty + j * 8][tx] = W[(size_t)(k0 + ty + j * 8) * N + n0 + tx];
    __syncthreads();
#pragma unroll
    for (int j = 0; j < 4; j++) {
        float v = t[tx][ty + j * 8];
        int n = n0 + ty + j * 8, k = k0 + tx;
        Th[(size_t)n * K + k] = __float2half_rn(v);
    }
}

// ---------------- pipelined tensor-core GEMM: C = Ah @ Bh^T + bias -----------
// R12 shape: 256 threads / 8 warps, 32x64 warp tiles (128x128 block), regs 128.
// Stage 32KB: Ah +0 | Bh +16K.
// EPI=1: scatter q/k/v rounded [b,h,s,d] (q scaled 0.125).  EPI=0: fp32 C.
#define GSTG 32768u
template<int EPI>
__global__ __launch_bounds__(256, 2)
void mma_gemm(const __half* __restrict__ Ah, const __half* __restrict__ Bth,
              const float* __restrict__ bias, float* __restrict__ C,
              int M, int N, int K)
{
    extern __shared__ char sm[];
    const uint32_t sb = (uint32_t)__cvta_generic_to_shared(sm);
    const int tid = threadIdx.x, lane = tid & 31, wid = tid >> 5;
    const int wm = wid >> 1, wn = wid & 1;
    const int bm = blockIdx.y * 128, bn = blockIdx.x * 128;

    float acc[2][8][4];
#pragma unroll
    for (int mi = 0; mi < 2; mi++)
#pragma unroll
        for (int nb = 0; nb < 8; nb++)
#pragma unroll
            for (int q = 0; q < 4; q++) acc[mi][nb][q] = 0.f;

    const int lr = (lane & 7) + ((lane >> 3) & 1) * 8;
    const int l_row0 = tid >> 3, l_ch = tid & 7;

    auto issue_stage = [&](int st, int kt) {
#pragma unroll
        for (int i = 0; i < 4; i++) {
            int row = l_row0 + i * 32;
            uint32_t soff = (uint32_t)st * GSTG + row * 128 + ((l_ch ^ (row & 7)) << 4);
            size_t ga = (size_t)(bm + row) * K + kt + l_ch * 8;
            size_t gb = (size_t)(bn + row) * K + kt + l_ch * 8;
            cpasync16(sb + soff,         Ah + ga);
            cpasync16(sb + 16384 + soff, Bth + gb);
        }
        CP_COMMIT();
    };

    issue_stage(0, 0);

    int t = 0;
    for (int kt = 0; kt < K; kt += 64, t++) {
        const int cur = t & 1;
        const bool more = (kt + 64 < K);
        if (more) { issue_stage(cur ^ 1, kt + 64); CP_WAIT(1); }
        else      { CP_WAIT(0); }
        __syncthreads();

        const uint32_t cb = sb + (uint32_t)cur * GSTG;
#pragma unroll
        for (int kk = 0; kk < 4; kk++) {
            const int lc = kk * 2 + (lane >> 4);
            uint32_t afh[2][4];
#pragma unroll
            for (int mi = 0; mi < 2; mi++) {
                int r = wm * 32 + mi * 16 + lr;
                uint32_t ad = cb + r * 128 + ((lc ^ (r & 7)) << 4);
                ldsm4(afh[mi], ad);
            }
            uint32_t bfh[8][2], t4[4];
#pragma unroll
            for (int g = 0; g < 4; g++) {
                int r = wn * 64 + g * 16 + lr;
                uint32_t ad = cb + 16384 + r * 128 + ((lc ^ (r & 7)) << 4);
                ldsm4(t4, ad);
                bfh[2*g][0] = t4[0]; bfh[2*g][1] = t4[2];
                bfh[2*g+1][0] = t4[1]; bfh[2*g+1][1] = t4[3];
            }
#pragma unroll
            for (int mi = 0; mi < 2; mi++)
#pragma unroll
                for (int nb = 0; nb < 8; nb++)
                    mma16816(acc[mi][nb], afh[mi], bfh[nb]);
        }
        __syncthreads();
    }

    // epilogue
#pragma unroll
    for (int mi = 0; mi < 2; mi++) {
        const int rbase = bm + wm * 32 + mi * 16 + (lane >> 2);
#pragma unroll
        for (int nb = 0; nb < 8; nb++) {
            const int cc = bn + wn * 64 + nb * 8 + (lane & 3) * 2;
            const float b0 = bias[cc], b1 = bias[cc + 1];
#pragma unroll
            for (int hr = 0; hr < 2; hr++) {
                const int r = rbase + hr * 8;
                float v0 = acc[mi][nb][hr * 2 + 0] + b0;
                float v1 = acc[mi][nb][hr * 2 + 1] + b1;
                if (EPI == 1) {
                    const int bb = r >> 11, si = r & 2047;
                    const int sec = cc >> 10, win = cc & 1023;
                    const int hh = win >> 6, dd = win & 63;
                    size_t off = (((size_t)bb * H_ + hh) * S_ + si) * D_ + dd;
                    __half* dst;
                    if (sec == 0) { v0 *= 0.125f; v1 *= 0.125f; dst = g_qh; }
                    else if (sec == 1) dst = g_kh;
                    else dst = g_vh;
                    __half2 h2 = __floats2half2_rn(v0, v1);
                    *(__half2*)(dst + off) = h2;
                } else {
                    float2 v; v.x = v0; v.y = v1;
                    *(float2*)(C + (size_t)r * N + cc) = v;
                }
            }
        }
    }
}

// ---------------- flash attention: 4 warps / 128 queries, 32 q per warp ------
// R13 shape (measured winner).  Per k16: 4 K-ldsm feed 16 mma; V shared across mi.
// smem: Qh 0 (16K) | stages at 16K: {Kh 0..8K, Vh 8K..16K} x2 | Mf at 48K
#define ASTAGE 16384
#define A_STG0 16384
#define A_MF   (A_STG0 + 2*ASTAGE)
#define ATTN_SMEM (A_MF + 2*64*4)

__global__ __launch_bounds__(128, 2)
void attn_mma(const int* __restrict__ mask)
{
    extern __shared__ char sm[];
    const uint32_t sb = (uint32_t)__cvta_generic_to_shared(sm);
    float* Mf = (float*)(sm + A_MF);   // [2][64]
    const int tid = threadIdx.x, lane = tid & 31, w = tid >> 5;
    const int qb = blockIdx.x * 128, bh = blockIdx.y;
    const int b = bh >> 4, h = bh & 15;
    const size_t base = (size_t)bh * S_ * D_;
    const int lr = (lane & 7) + ((lane >> 3) & 1) * 8;
    const int* mrow = mask + b * S_;

    auto issue_kv = [&](int st, int kt) {
        for (int i = tid; i < 512; i += 128) {
            int row = i >> 3, ch = i & 7;
            uint32_t soff = A_STG0 + (uint32_t)st * ASTAGE + row * 128 + ((ch ^ (row & 7)) << 4);
            size_t g = base + (size_t)(kt + row) * D_ + ch * 8;
            cpasync16(sb + soff,         g_kh + g);
            cpasync16(sb + soff + 8192,  g_vh + g);
        }
        if (tid < 64) Mf[st * 64 + tid] = mrow[kt + tid] ? 1.0f : 0.0f;
        CP_COMMIT();
    };

    issue_kv(0, 0);

    // stage Q tile (128 rows, rounded)
    for (int i = tid; i < 1024; i += 128) {
        int row = i >> 3, ch = i & 7;
        uint32_t soff = row * 128 + ((ch ^ (row & 7)) << 4);
        size_t g = base + (size_t)(qb + row) * D_ + ch * 8;
        *(uint4*)(sm + soff) = *(const uint4*)(g_qh + g);
    }
    __syncthreads();

    uint32_t qfh[2][4][4];   // [mi][kk]
#pragma unroll
    for (int mi = 0; mi < 2; mi++)
#pragma unroll
        for (int kk = 0; kk < 4; kk++) {
            int r = w * 32 + mi * 16 + lr;
            int c = kk * 2 + (lane >> 4);
            uint32_t ad = sb + r * 128 + ((c ^ (r & 7)) << 4);
            ldsm4(qfh[mi][kk], ad);
        }

    float O[2][8][4];
    float m_[2][2], l_[2][2];
#pragma unroll
    for (int mi = 0; mi < 2; mi++) {
#pragma unroll
        for (int nb = 0; nb < 8; nb++)
#pragma unroll
            for (int q = 0; q < 4; q++) O[mi][nb][q] = 0.f;
        m_[mi][0] = -1e30f; m_[mi][1] = -1e30f;
        l_[mi][0] = 0.f;    l_[mi][1] = 0.f;
    }

    for (int t = 0; t < S_ / 64; t++) {
        const int cur = t & 1;
        const bool more = (t + 1 < S_ / 64);
        if (more) { issue_kv(cur ^ 1, (t + 1) * 64); CP_WAIT(1); }
        else      { CP_WAIT(0); }
        __syncthreads();

        const uint32_t kb = sb + A_STG0 + (uint32_t)cur * ASTAGE;
        const float* mf = Mf + cur * 64;

        // S = Qh Kh^T   (Q pre-scaled by 0.125)
        float S[2][8][4];
#pragma unroll
        for (int mi = 0; mi < 2; mi++)
#pragma unroll
            for (int nb = 0; nb < 8; nb++)
#pragma unroll
                for (int q = 0; q < 4; q++) S[mi][nb][q] = 0.f;
#pragma unroll
        for (int kk = 0; kk < 4; kk++) {
            const int lc = kk * 2 + (lane >> 4);
            uint32_t bfh[8][2], t4[4];
#pragma unroll
            for (int g = 0; g < 4; g++) {
                int r = g * 16 + lr;
                uint32_t ad = kb + r * 128 + ((lc ^ (r & 7)) << 4);
                ldsm4(t4, ad);
                bfh[2*g][0] = t4[0]; bfh[2*g][1] = t4[2];
                bfh[2*g+1][0] = t4[1]; bfh[2*g+1][1] = t4[3];
            }
#pragma unroll
            for (int mi = 0; mi < 2; mi++)
#pragma unroll
                for (int nb = 0; nb < 8; nb++)
                    mma16816(S[mi][nb], qfh[mi][kk], bfh[nb]);
        }

        // mask + online softmax (column masks shared across mi)
        float mk0[8], mk1[8];
#pragma unroll
        for (int nb = 0; nb < 8; nb++) {
            int c = nb * 8 + (lane & 3) * 2;
            mk0[nb] = mf[c]; mk1[nb] = mf[c + 1];
        }
#pragma unroll
        for (int mi = 0; mi < 2; mi++) {
            float mx0 = -1e30f, mx1 = -1e30f;
#pragma unroll
            for (int nb = 0; nb < 8; nb++) {
                S[mi][nb][0] = (mk0[nb] != 0.f) ? S[mi][nb][0] : -1e30f;
                S[mi][nb][1] = (mk1[nb] != 0.f) ? S[mi][nb][1] : -1e30f;
                S[mi][nb][2] = (mk0[nb] != 0.f) ? S[mi][nb][2] : -1e30f;
                S[mi][nb][3] = (mk1[nb] != 0.f) ? S[mi][nb][3] : -1e30f;
                mx0 = fmaxf(mx0, fmaxf(S[mi][nb][0], S[mi][nb][1]));
                mx1 = fmaxf(mx1, fmaxf(S[mi][nb][2], S[mi][nb][3]));
            }
            mx0 = fmaxf(mx0, __shfl_xor_sync(0xffffffffu, mx0, 1));
            mx0 = fmaxf(mx0, __shfl_xor_sync(0xffffffffu, mx0, 2));
            mx1 = fmaxf(mx1, __shfl_xor_sync(0xffffffffu, mx1, 1));
            mx1 = fmaxf(mx1, __shfl_xor_sync(0xffffffffu, mx1, 2));
            const float mn0 = fmaxf(m_[mi][0], mx0), mn1 = fmaxf(m_[mi][1], mx1);
            const float a0 = __expf(m_[mi][0] - mn0), a1 = __expf(m_[mi][1] - mn1);
            m_[mi][0] = mn0; m_[mi][1] = mn1;
            float s0 = 0.f, s1 = 0.f;
#pragma unroll
            for (int nb = 0; nb < 8; nb++) {
                float p0 = __expf(S[mi][nb][0] - mn0) * mk0[nb];
                float p1 = __expf(S[mi][nb][1] - mn0) * mk1[nb];
                float p2 = __expf(S[mi][nb][2] - mn1) * mk0[nb];
                float p3 = __expf(S[mi][nb][3] - mn1) * mk1[nb];
                S[mi][nb][0] = p0; S[mi][nb][1] = p1; S[mi][nb][2] = p2; S[mi][nb][3] = p3;
                s0 += p0 + p1; s1 += p2 + p3;
            }
            s0 += __shfl_xor_sync(0xffffffffu, s0, 1);
            s0 += __shfl_xor_sync(0xffffffffu, s0, 2);
            s1 += __shfl_xor_sync(0xffffffffu, s1, 1);
            s1 += __shfl_xor_sync(0xffffffffu, s1, 2);
            l_[mi][0] = l_[mi][0] * a0 + s0;
            l_[mi][1] = l_[mi][1] * a1 + s1;
#pragma unroll
            for (int nb = 0; nb < 8; nb++) {
                O[mi][nb][0] *= a0; O[mi][nb][1] *= a0;
                O[mi][nb][2] *= a1; O[mi][nb][3] *= a1;
            }
        }

        // O += Ph Vh   (P rounded once to f16; V frags shared across mi)
#pragma unroll
        for (int kk = 0; kk < 4; kk++) {
            uint32_t ph[2][4];
#pragma unroll
            for (int mi = 0; mi < 2; mi++) {
                __half2 t0 = __floats2half2_rn(S[mi][2*kk][0],   S[mi][2*kk][1]);
                __half2 t1 = __floats2half2_rn(S[mi][2*kk][2],   S[mi][2*kk][3]);
                __half2 t2 = __floats2half2_rn(S[mi][2*kk+1][0], S[mi][2*kk+1][1]);
                __half2 t3 = __floats2half2_rn(S[mi][2*kk+1][2], S[mi][2*kk+1][3]);
                ph[mi][0] = *reinterpret_cast<uint32_t*>(&t0);
                ph[mi][1] = *reinterpret_cast<uint32_t*>(&t1);
                ph[mi][2] = *reinterpret_cast<uint32_t*>(&t2);
                ph[mi][3] = *reinterpret_cast<uint32_t*>(&t3);
            }
            uint32_t vfh[8][2], t4[4];
#pragma unroll
            for (int g = 0; g < 4; g++) {
                int r = kk * 16 + lr;
                int c = g * 2 + (lane >> 4);
                uint32_t ad = kb + 8192 + r * 128 + ((c ^ (r & 7)) << 4);
                ldsm4t(t4, ad);
                vfh[2*g][0] = t4[0]; vfh[2*g][1] = t4[1];
                vfh[2*g+1][0] = t4[2]; vfh[2*g+1][1] = t4[3];
            }
#pragma unroll
            for (int mi = 0; mi < 2; mi++)
#pragma unroll
                for (int nb = 0; nb < 8; nb++)
                    mma16816(O[mi][nb], ph[mi], vfh[nb]);
        }
        __syncthreads();
    }

    // epilogue: normalize, round once, store attn [b,s,e]
#pragma unroll
    for (int mi = 0; mi < 2; mi++) {
        const float inv0 = 1.0f / l_[mi][0], inv1 = 1.0f / l_[mi][1];
        const int s0r = qb + w * 32 + mi * 16 + (lane >> 2);
#pragma unroll
        for (int nb = 0; nb < 8; nb++) {
            const int d = nb * 8 + (lane & 3) * 2;
            size_t off = ((size_t)b * S_ + s0r) * E_ + h * 64 + d;
            __half2 h2 = __floats2half2_rn(O[mi][nb][0] * inv0, O[mi][nb][1] * inv0);
            *(__half2*)(g_ah + off) = h2;
            off += (size_t)8 * E_;
            h2 = __floats2half2_rn(O[mi][nb][2] * inv1, O[mi][nb][3] * inv1);
            *(__half2*)(g_ah + off) = h2;
        }
    }
}

// ---------------------------------------------------------------------------
extern "C" void kernel_launch(void* const* d_in, const int* in_sizes, int n_in,
                              void* d_out, int out_size)
{
    const float* hidden = (const float*)d_in[0];
    const float* qkv_w  = (const float*)d_in[1];
    const float* qkv_b  = (const float*)d_in[2];
    const float* wo_w   = (const float*)d_in[3];
    const float* wo_b   = (const float*)d_in[4];
    const int*   mask   = (const int*)d_in[5];
    float* out = (float*)d_out;

    __half *hidh, *wqh, *woh, *ah;
    cudaGetSymbolAddress((void**)&hidh, g_hidh);
    cudaGetSymbolAddress((void**)&wqh,  g_wqh);
    cudaGetSymbolAddress((void**)&woh,  g_woh);
    cudaGetSymbolAddress((void**)&ah,   g_ah);

    cudaFuncSetAttribute(mma_gemm<1>, cudaFuncAttributeMaxDynamicSharedMemorySize, (int)(2*GSTG));
    cudaFuncSetAttribute(mma_gemm<0>, cudaFuncAttributeMaxDynamicSharedMemorySize, (int)(2*GSTG));
    cudaFuncSetAttribute(attn_mma,    cudaFuncAttributeMaxDynamicSharedMemorySize, ATTN_SMEM);

    // 1) roundings
    round4<<<(M_ * E_) / 4 / 256, 256>>>(hidden, hidh, M_ * E_);
    tround<<<dim3(E3_ / 32, E_ / 32), dim3(32, 8)>>>(qkv_w, wqh, E_, E3_);
    tround<<<dim3(E_ / 32, E_ / 32),  dim3(32, 8)>>>(wo_w,  woh, E_, E_);

    // 2) QKV projection (1-term f16, R12 GEMM shape)
    mma_gemm<1><<<dim3(E3_ / 128, M_ / 128), 256, 2*GSTG>>>(
        hidh, wqh, qkv_b, nullptr, M_, E3_, E_);

    // 3) attention (R13 shape: 32 q per warp)
    attn_mma<<<dim3(S_ / 128, BH_), 128, ATTN_SMEM>>>(mask);

    // 4) output projection (1-term f16, R12 GEMM shape)
    mma_gemm<0><<<dim3(E_ / 128, M_ / 128), 256, 2*GSTG>>>(
        ah, woh, wo_b, out, M_, E_, E_);
}

// round 15
// speedup vs baseline: 3.2982x; 1.2070x over previous
#include <cuda_runtime.h>
#include <cuda_fp16.h>
#include <math.h>
#include <stdint.h>

#define B_ 4
#define S_ 2048
#define H_ 16
#define D_ 64
#define E_ 1024
#define E3_ 3072
#define BH_ (B_*H_)
#define M_ (B_*S_)   // 8192

// ---------------- device-global scratch (allocation-free rule) ----------------
__device__ __half g_hidh[M_*E_];                     // hidden rounded once
__device__ __half g_wqh[E3_*E_];                     // qkv_w^T rounded [N][K]
__device__ __half g_woh[E_*E_];                      // wo_w^T rounded  [N][K]
__device__ __half g_qh[BH_*S_*D_];                   // q rounded (pre-scaled 0.125)
__device__ __half g_kh[BH_*S_*D_];                   // k rounded
__device__ __half g_vh[BH_*S_*D_];                   // v rounded
__device__ __half g_ah[M_*E_];                       // attn out rounded
__device__ int    g_idx[B_*(S_+64)];                 // compacted valid-key indices
__device__ int    g_cnt[B_];                         // valid-key counts

// ---------------- helpers ----------------
__device__ __forceinline__ void ldsm4(uint32_t* r, uint32_t addr) {
    asm volatile("ldmatrix.sync.aligned.m8n8.x4.shared.b16 {%0,%1,%2,%3}, [%4];"
                 : "=r"(r[0]), "=r"(r[1]), "=r"(r[2]), "=r"(r[3]) : "r"(addr));
}
__device__ __forceinline__ void ldsm4t(uint32_t* r, uint32_t addr) {
    asm volatile("ldmatrix.sync.aligned.m8n8.x4.trans.shared.b16 {%0,%1,%2,%3}, [%4];"
                 : "=r"(r[0]), "=r"(r[1]), "=r"(r[2]), "=r"(r[3]) : "r"(addr));
}
__device__ __forceinline__ void mma16816(float* c, const uint32_t* a, const uint32_t* b) {
    asm volatile("mma.sync.aligned.m16n8k16.row.col.f32.f16.f16.f32 "
                 "{%0,%1,%2,%3}, {%4,%5,%6,%7}, {%8,%9}, {%0,%1,%2,%3};"
                 : "+f"(c[0]), "+f"(c[1]), "+f"(c[2]), "+f"(c[3])
                 : "r"(a[0]), "r"(a[1]), "r"(a[2]), "r"(a[3]),
                   "r"(b[0]), "r"(b[1]));
}
__device__ __forceinline__ void cpasync16(uint32_t dst, const void* src) {
    asm volatile("cp.async.cg.shared.global [%0], [%1], 16;" :: "r"(dst), "l"(src));
}
#define CP_COMMIT() asm volatile("cp.async.commit_group;")
#define CP_WAIT(N)  asm volatile("cp.async.wait_group %0;" :: "n"(N))

// ---------------- round kernels ----------------
__global__ void round4(const float* __restrict__ x, __half* __restrict__ hi, int n)
{
    int i = (blockIdx.x * blockDim.x + threadIdx.x) * 4;
    if (i >= n) return;
    float4 v = *(const float4*)(x + i);
    __half2 h0 = __floats2half2_rn(v.x, v.y);
    __half2 h1 = __floats2half2_rn(v.z, v.w);
    uint2 hh;
    hh.x = *reinterpret_cast<uint32_t*>(&h0);
    hh.y = *reinterpret_cast<uint32_t*>(&h1);
    *(uint2*)(hi + i) = hh;
}

// W [K][N] f32 -> Th [N][K] f16 (rounded once)
__global__ void tround(const float* __restrict__ W,
                       __half* __restrict__ Th, int K, int N)
{
    __shared__ float t[32][33];
    const int tx = threadIdx.x, ty = threadIdx.y;
    const int n0 = blockIdx.x * 32, k0 = blockIdx.y * 32;
#pragma unroll
    for (int j = 0; j < 4; j++)
        t[ty + j * 8][tx] = W[(size_t)(k0 + ty + j * 8) * N + n0 + tx];
    __syncthreads();
#pragma unroll
    for (int j = 0; j < 4; j++) {
        float v = t[tx][ty + j * 8];
        int n = n0 + ty + j * 8, k = k0 + tx;
        Th[(size_t)n * K + k] = __float2half_rn(v);
    }
}

// ---------------- mask compaction: ordered indices of valid keys -------------
// One block per batch, 1024 threads, 2 elements each; block-wide exclusive scan.
__global__ __launch_bounds__(1024)
void build_idx(const int* __restrict__ mask)
{
    __shared__ int wsum[32];
    __shared__ int totn;
    const int b = blockIdx.x, t = threadIdx.x;
    const int lane = t & 31, wid = t >> 5;
    int v0 = (mask[b * S_ + 2 * t]     != 0) ? 1 : 0;
    int v1 = (mask[b * S_ + 2 * t + 1] != 0) ? 1 : 0;
    int s = v0 + v1;
    int x = s;
#pragma unroll
    for (int o = 1; o < 32; o <<= 1) {
        int y = __shfl_up_sync(0xffffffffu, x, o);
        if (lane >= o) x += y;
    }
    if (lane == 31) wsum[wid] = x;
    __syncthreads();
    if (wid == 0) {
        int w = wsum[lane];
#pragma unroll
        for (int o = 1; o < 32; o <<= 1) {
            int y = __shfl_up_sync(0xffffffffu, w, o);
            if (lane >= o) w += y;
        }
        wsum[lane] = w;
        if (lane == 31) totn = w;
    }
    __syncthreads();
    int excl = x - s + (wid > 0 ? wsum[wid - 1] : 0);
    int* idx = g_idx + b * (S_ + 64);
    if (v0) idx[excl] = 2 * t;
    if (v1) idx[excl + v0] = 2 * t + 1;
    __syncthreads();
    const int n = totn;
    if (t == 0) g_cnt[b] = n;
    const int npad = (n + 63) & ~63;
    for (int i = n + t; i < npad; i += 1024) idx[i] = 0;
}

// ---------------- pipelined tensor-core GEMM: C = Ah @ Bh^T + bias -----------
// 256 threads / 8 warps, 32x64 warp tiles (128x128 block), regs 128.
#define GSTG 32768u
template<int EPI>
__global__ __launch_bounds__(256, 2)
void mma_gemm(const __half* __restrict__ Ah, const __half* __restrict__ Bth,
              const float* __restrict__ bias, float* __restrict__ C,
              int M, int N, int K)
{
    extern __shared__ char sm[];
    const uint32_t sb = (uint32_t)__cvta_generic_to_shared(sm);
    const int tid = threadIdx.x, lane = tid & 31, wid = tid >> 5;
    const int wm = wid >> 1, wn = wid & 1;
    const int bm = blockIdx.y * 128, bn = blockIdx.x * 128;

    float acc[2][8][4];
#pragma unroll
    for (int mi = 0; mi < 2; mi++)
#pragma unroll
        for (int nb = 0; nb < 8; nb++)
#pragma unroll
            for (int q = 0; q < 4; q++) acc[mi][nb][q] = 0.f;

    const int lr = (lane & 7) + ((lane >> 3) & 1) * 8;
    const int l_row0 = tid >> 3, l_ch = tid & 7;

    auto issue_stage = [&](int st, int kt) {
#pragma unroll
        for (int i = 0; i < 4; i++) {
            int row = l_row0 + i * 32;
            uint32_t soff = (uint32_t)st * GSTG + row * 128 + ((l_ch ^ (row & 7)) << 4);
            size_t ga = (size_t)(bm + row) * K + kt + l_ch * 8;
            size_t gb = (size_t)(bn + row) * K + kt + l_ch * 8;
            cpasync16(sb + soff,         Ah + ga);
            cpasync16(sb + 16384 + soff, Bth + gb);
        }
        CP_COMMIT();
    };

    issue_stage(0, 0);

    int t = 0;
    for (int kt = 0; kt < K; kt += 64, t++) {
        const int cur = t & 1;
        const bool more = (kt + 64 < K);
        if (more) { issue_stage(cur ^ 1, kt + 64); CP_WAIT(1); }
        else      { CP_WAIT(0); }
        __syncthreads();

        const uint32_t cb = sb + (uint32_t)cur * GSTG;
#pragma unroll
        for (int kk = 0; kk < 4; kk++) {
            const int lc = kk * 2 + (lane >> 4);
            uint32_t afh[2][4];
#pragma unroll
            for (int mi = 0; mi < 2; mi++) {
                int r = wm * 32 + mi * 16 + lr;
                uint32_t ad = cb + r * 128 + ((lc ^ (r & 7)) << 4);
                ldsm4(afh[mi], ad);
            }
            uint32_t bfh[8][2], t4[4];
#pragma unroll
            for (int g = 0; g < 4; g++) {
                int r = wn * 64 + g * 16 + lr;
                uint32_t ad = cb + 16384 + r * 128 + ((lc ^ (r & 7)) << 4);
                ldsm4(t4, ad);
                bfh[2*g][0] = t4[0]; bfh[2*g][1] = t4[2];
                bfh[2*g+1][0] = t4[1]; bfh[2*g+1][1] = t4[3];
            }
#pragma unroll
            for (int mi = 0; mi < 2; mi++)
#pragma unroll
                for (int nb = 0; nb < 8; nb++)
                    mma16816(acc[mi][nb], afh[mi], bfh[nb]);
        }
        __syncthreads();
    }

    // epilogue
#pragma unroll
    for (int mi = 0; mi < 2; mi++) {
        const int rbase = bm + wm * 32 + mi * 16 + (lane >> 2);
#pragma unroll
        for (int nb = 0; nb < 8; nb++) {
            const int cc = bn + wn * 64 + nb * 8 + (lane & 3) * 2;
            const float b0 = bias[cc], b1 = bias[cc + 1];
#pragma unroll
            for (int hr = 0; hr < 2; hr++) {
                const int r = rbase + hr * 8;
                float v0 = acc[mi][nb][hr * 2 + 0] + b0;
                float v1 = acc[mi][nb][hr * 2 + 1] + b1;
                if (EPI == 1) {
                    const int bb = r >> 11, si = r & 2047;
                    const int sec = cc >> 10, win = cc & 1023;
                    const int hh = win >> 6, dd = win & 63;
                    size_t off = (((size_t)bb * H_ + hh) * S_ + si) * D_ + dd;
                    __half* dst;
                    if (sec == 0) { v0 *= 0.125f; v1 *= 0.125f; dst = g_qh; }
                    else if (sec == 1) dst = g_kh;
                    else dst = g_vh;
                    __half2 h2 = __floats2half2_rn(v0, v1);
                    *(__half2*)(dst + off) = h2;
                } else {
                    float2 v; v.x = v0; v.y = v1;
                    *(float2*)(C + (size_t)r * N + cc) = v;
                }
            }
        }
    }
}

// ---------------- flash attention over COMPACTED keys ------------------------
// 4 warps / 128 queries, 32 q per warp.  K/V gathered via g_idx; only
// ceil(n_valid/64) tiles.  Mf marks real vs padding columns.
#define ASTAGE 16384
#define A_STG0 16384
#define A_MF   (A_STG0 + 2*ASTAGE)
#define ATTN_SMEM (A_MF + 2*64*4)

__global__ __launch_bounds__(128, 2)
void attn_mma()
{
    extern __shared__ char sm[];
    const uint32_t sb = (uint32_t)__cvta_generic_to_shared(sm);
    float* Mf = (float*)(sm + A_MF);   // [2][64]
    const int tid = threadIdx.x, lane = tid & 31, w = tid >> 5;
    const int qb = blockIdx.x * 128, bh = blockIdx.y;
    const int b = bh >> 4, h = bh & 15;
    const size_t base = (size_t)bh * S_ * D_;
    const int lr = (lane & 7) + ((lane >> 3) & 1) * 8;
    const int* idxb = g_idx + b * (S_ + 64);
    const int nvalid = g_cnt[b];
    const int ntiles = (nvalid + 63) >> 6;

    auto issue_kv = [&](int st, int kt) {
        for (int i = tid; i < 512; i += 128) {
            int row = i >> 3, ch = i & 7;
            int src = idxb[kt + row];
            uint32_t soff = A_STG0 + (uint32_t)st * ASTAGE + row * 128 + ((ch ^ (row & 7)) << 4);
            size_t g = base + (size_t)src * D_ + ch * 8;
            cpasync16(sb + soff,         g_kh + g);
            cpasync16(sb + soff + 8192,  g_vh + g);
        }
        if (tid < 64) Mf[st * 64 + tid] = (kt + tid < nvalid) ? 1.0f : 0.0f;
        CP_COMMIT();
    };

    issue_kv(0, 0);

    // stage Q tile (128 rows, rounded)
    for (int i = tid; i < 1024; i += 128) {
        int row = i >> 3, ch = i & 7;
        uint32_t soff = row * 128 + ((ch ^ (row & 7)) << 4);
        size_t g = base + (size_t)(qb + row) * D_ + ch * 8;
        *(uint4*)(sm + soff) = *(const uint4*)(g_qh + g);
    }
    __syncthreads();

    uint32_t qfh[2][4][4];   // [mi][kk]
#pragma unroll
    for (int mi = 0; mi < 2; mi++)
#pragma unroll
        for (int kk = 0; kk < 4; kk++) {
            int r = w * 32 + mi * 16 + lr;
            int c = kk * 2 + (lane >> 4);
            uint32_t ad = sb + r * 128 + ((c ^ (r & 7)) << 4);
            ldsm4(qfh[mi][kk], ad);
        }

    float O[2][8][4];
    float m_[2][2], l_[2][2];
#pragma unroll
    for (int mi = 0; mi < 2; mi++) {
#pragma unroll
        for (int nb = 0; nb < 8; nb++)
#pragma unroll
            for (int q = 0; q < 4; q++) O[mi][nb][q] = 0.f;
        m_[mi][0] = -1e30f; m_[mi][1] = -1e30f;
        l_[mi][0] = 0.f;    l_[mi][1] = 0.f;
    }

    for (int t = 0; t < ntiles; t++) {
        const int cur = t & 1;
        const bool more = (t + 1 < ntiles);
        if (more) { issue_kv(cur ^ 1, (t + 1) * 64); CP_WAIT(1); }
        else      { CP_WAIT(0); }
        __syncthreads();

        const uint32_t kb = sb + A_STG0 + (uint32_t)cur * ASTAGE;
        const float* mf = Mf + cur * 64;

        // S = Qh Kh^T   (Q pre-scaled by 0.125)
        float S[2][8][4];
#pragma unroll
        for (int mi = 0; mi < 2; mi++)
#pragma unroll
            for (int nb = 0; nb < 8; nb++)
#pragma unroll
                for (int q = 0; q < 4; q++) S[mi][nb][q] = 0.f;
#pragma unroll
        for (int kk = 0; kk < 4; kk++) {
            const int lc = kk * 2 + (lane >> 4);
            uint32_t bfh[8][2], t4[4];
#pragma unroll
            for (int g = 0; g < 4; g++) {
                int r = g * 16 + lr;
                uint32_t ad = kb + r * 128 + ((lc ^ (r & 7)) << 4);
                ldsm4(t4, ad);
                bfh[2*g][0] = t4[0]; bfh[2*g][1] = t4[2];
                bfh[2*g+1][0] = t4[1]; bfh[2*g+1][1] = t4[3];
            }
#pragma unroll
            for (int mi = 0; mi < 2; mi++)
#pragma unroll
                for (int nb = 0; nb < 8; nb++)
                    mma16816(S[mi][nb], qfh[mi][kk], bfh[nb]);
        }

        // mask (padding only) + online softmax
        float mk0[8], mk1[8];
#pragma unroll
        for (int nb = 0; nb < 8; nb++) {
            int c = nb * 8 + (lane & 3) * 2;
            mk0[nb] = mf[c]; mk1[nb] = mf[c + 1];
        }
#pragma unroll
        for (int mi = 0; mi < 2; mi++) {
            float mx0 = -1e30f, mx1 = -1e30f;
#pragma unroll
            for (int nb = 0; nb < 8; nb++) {
                S[mi][nb][0] = (mk0[nb] != 0.f) ? S[mi][nb][0] : -1e30f;
                S[mi][nb][1] = (mk1[nb] != 0.f) ? S[mi][nb][1] : -1e30f;
                S[mi][nb][2] = (mk0[nb] != 0.f) ? S[mi][nb][2] : -1e30f;
                S[mi][nb][3] = (mk1[nb] != 0.f) ? S[mi][nb][3] : -1e30f;
                mx0 = fmaxf(mx0, fmaxf(S[mi][nb][0], S[mi][nb][1]));
                mx1 = fmaxf(mx1, fmaxf(S[mi][nb][2], S[mi][nb][3]));
            }
            mx0 = fmaxf(mx0, __shfl_xor_sync(0xffffffffu, mx0, 1));
            mx0 = fmaxf(mx0, __shfl_xor_sync(0xffffffffu, mx0, 2));
            mx1 = fmaxf(mx1, __shfl_xor_sync(0xffffffffu, mx1, 1));
            mx1 = fmaxf(mx1, __shfl_xor_sync(0xffffffffu, mx1, 2));
            const float mn0 = fmaxf(m_[mi][0], mx0), mn1 = fmaxf(m_[mi][1], mx1);
            const float a0 = __expf(m_[mi][0] - mn0), a1 = __expf(m_[mi][1] - mn1);
            m_[mi][0] = mn0; m_[mi][1] = mn1;
            float s0 = 0.f, s1 = 0.f;
#pragma unroll
            for (int nb = 0; nb < 8; nb++) {
                float p0 = __expf(S[mi][nb][0] - mn0) * mk0[nb];
                float p1 = __expf(S[mi][nb][1] - mn0) * mk1[nb];
                float p2 = __expf(S[mi][nb][2] - mn1) * mk0[nb];
                float p3 = __expf(S[mi][nb][3] - mn1) * mk1[nb];
                S[mi][nb][0] = p0; S[mi][nb][1] = p1; S[mi][nb][2] = p2; S[mi][nb][3] = p3;
                s0 += p0 + p1; s1 += p2 + p3;
            }
            s0 += __shfl_xor_sync(0xffffffffu, s0, 1);
            s0 += __shfl_xor_sync(0xffffffffu, s0, 2);
            s1 += __shfl_xor_sync(0xffffffffu, s1, 1);
            s1 += __shfl_xor_sync(0xffffffffu, s1, 2);
            l_[mi][0] = l_[mi][0] * a0 + s0;
            l_[mi][1] = l_[mi][1] * a1 + s1;
#pragma unroll
            for (int nb = 0; nb < 8; nb++) {
                O[mi][nb][0] *= a0; O[mi][nb][1] *= a0;
                O[mi][nb][2] *= a1; O[mi][nb][3] *= a1;
            }
        }

        // O += Ph Vh   (P rounded once to f16; V frags shared across mi)
#pragma unroll
        for (int kk = 0; kk < 4; kk++) {
            uint32_t ph[2][4];
#pragma unroll
            for (int mi = 0; mi < 2; mi++) {
                __half2 t0 = __floats2half2_rn(S[mi][2*kk][0],   S[mi][2*kk][1]);
                __half2 t1 = __floats2half2_rn(S[mi][2*kk][2],   S[mi][2*kk][3]);
                __half2 t2 = __floats2half2_rn(S[mi][2*kk+1][0], S[mi][2*kk+1][1]);
                __half2 t3 = __floats2half2_rn(S[mi][2*kk+1][2], S[mi][2*kk+1][3]);
                ph[mi][0] = *reinterpret_cast<uint32_t*>(&t0);
                ph[mi][1] = *reinterpret_cast<uint32_t*>(&t1);
                ph[mi][2] = *reinterpret_cast<uint32_t*>(&t2);
                ph[mi][3] = *reinterpret_cast<uint32_t*>(&t3);
            }
            uint32_t vfh[8][2], t4[4];
#pragma unroll
            for (int g = 0; g < 4; g++) {
                int r = kk * 16 + lr;
                int c = g * 2 + (lane >> 4);
                uint32_t ad = kb + 8192 + r * 128 + ((c ^ (r & 7)) << 4);
                ldsm4t(t4, ad);
                vfh[2*g][0] = t4[0]; vfh[2*g][1] = t4[1];
                vfh[2*g+1][0] = t4[2]; vfh[2*g+1][1] = t4[3];
            }
#pragma unroll
            for (int mi = 0; mi < 2; mi++)
#pragma unroll
                for (int nb = 0; nb < 8; nb++)
                    mma16816(O[mi][nb], ph[mi], vfh[nb]);
        }
        __syncthreads();
    }

    // epilogue: normalize, round once, store attn [b,s,e]
#pragma unroll
    for (int mi = 0; mi < 2; mi++) {
        const float inv0 = 1.0f / l_[mi][0], inv1 = 1.0f / l_[mi][1];
        const int s0r = qb + w * 32 + mi * 16 + (lane >> 2);
#pragma unroll
        for (int nb = 0; nb < 8; nb++) {
            const int d = nb * 8 + (lane & 3) * 2;
            size_t off = ((size_t)b * S_ + s0r) * E_ + h * 64 + d;
            __half2 h2 = __floats2half2_rn(O[mi][nb][0] * inv0, O[mi][nb][1] * inv0);
            *(__half2*)(g_ah + off) = h2;
            off += (size_t)8 * E_;
            h2 = __floats2half2_rn(O[mi][nb][2] * inv1, O[mi][nb][3] * inv1);
            *(__half2*)(g_ah + off) = h2;
        }
    }
}

// ---------------------------------------------------------------------------
extern "C" void kernel_launch(void* const* d_in, const int* in_sizes, int n_in,
                              void* d_out, int out_size)
{
    const float* hidden = (const float*)d_in[0];
    const float* qkv_w  = (const float*)d_in[1];
    const float* qkv_b  = (const float*)d_in[2];
    const float* wo_w   = (const float*)d_in[3];
    const float* wo_b   = (const float*)d_in[4];
    const int*   mask   = (const int*)d_in[5];
    float* out = (float*)d_out;

    __half *hidh, *wqh, *woh, *ah;
    cudaGetSymbolAddress((void**)&hidh, g_hidh);
    cudaGetSymbolAddress((void**)&wqh,  g_wqh);
    cudaGetSymbolAddress((void**)&woh,  g_woh);
    cudaGetSymbolAddress((void**)&ah,   g_ah);

    cudaFuncSetAttribute(mma_gemm<1>, cudaFuncAttributeMaxDynamicSharedMemorySize, (int)(2*GSTG));
    cudaFuncSetAttribute(mma_gemm<0>, cudaFuncAttributeMaxDynamicSharedMemorySize, (int)(2*GSTG));
    cudaFuncSetAttribute(attn_mma,    cudaFuncAttributeMaxDynamicSharedMemorySize, ATTN_SMEM);

    // 1) roundings + mask compaction
    round4<<<(M_ * E_) / 4 / 256, 256>>>(hidden, hidh, M_ * E_);
    tround<<<dim3(E3_ / 32, E_ / 32), dim3(32, 8)>>>(qkv_w, wqh, E_, E3_);
    tround<<<dim3(E_ / 32, E_ / 32),  dim3(32, 8)>>>(wo_w,  woh, E_, E_);
    build_idx<<<B_, 1024>>>(mask);

    // 2) QKV projection (1-term f16)
    mma_gemm<1><<<dim3(E3_ / 128, M_ / 128), 256, 2*GSTG>>>(
        hidh, wqh, qkv_b, nullptr, M_, E3_, E_);

    // 3) attention over compacted keys
    attn_mma<<<dim3(S_ / 128, BH_), 128, ATTN_SMEM>>>();

    // 4) output projection (1-term f16)
    mma_gemm<0><<<dim3(E_ / 128, M_ / 128), 256, 2*GSTG>>>(
        ah, woh, wo_b, out, M_, E_, E_);
}

// round 16
// speedup vs baseline: 3.5976x; 1.0908x over previous
#include <cuda_runtime.h>
#include <cuda_fp16.h>
#include <math.h>
#include <stdint.h>

#define B_ 4
#define S_ 2048
#define H_ 16
#define D_ 64
#define E_ 1024
#define E3_ 3072
#define BH_ (B_*H_)
#define M_ (B_*S_)   // 8192
#define IDXP (S_+128)

// ---------------- device-global scratch (allocation-free rule) ----------------
__device__ __half g_hidh[M_*E_];                     // hidden rounded once
__device__ __half g_wqh[E3_*E_];                     // qkv_w^T rounded [N][K]
__device__ __half g_woh[E_*E_];                      // wo_w^T rounded  [N][K]
__device__ __half g_qh[BH_*S_*D_];                   // q rounded (pre-scaled 0.125)
__device__ __half g_kh[BH_*S_*D_];                   // k rounded (valid rows only)
__device__ __half g_vh[BH_*S_*D_];                   // v rounded (valid rows only)
__device__ __half g_ah[M_*E_];                       // attn out rounded
__device__ int    g_idx[B_*IDXP];                    // compacted valid-key indices (-1 pad)
__device__ int    g_cnt[B_];                         // valid-key counts

// ---------------- helpers ----------------
__device__ __forceinline__ void ldsm4(uint32_t* r, uint32_t addr) {
    asm volatile("ldmatrix.sync.aligned.m8n8.x4.shared.b16 {%0,%1,%2,%3}, [%4];"
                 : "=r"(r[0]), "=r"(r[1]), "=r"(r[2]), "=r"(r[3]) : "r"(addr));
}
__device__ __forceinline__ void ldsm4t(uint32_t* r, uint32_t addr) {
    asm volatile("ldmatrix.sync.aligned.m8n8.x4.trans.shared.b16 {%0,%1,%2,%3}, [%4];"
                 : "=r"(r[0]), "=r"(r[1]), "=r"(r[2]), "=r"(r[3]) : "r"(addr));
}
__device__ __forceinline__ void mma16816(float* c, const uint32_t* a, const uint32_t* b) {
    asm volatile("mma.sync.aligned.m16n8k16.row.col.f32.f16.f16.f32 "
                 "{%0,%1,%2,%3}, {%4,%5,%6,%7}, {%8,%9}, {%0,%1,%2,%3};"
                 : "+f"(c[0]), "+f"(c[1]), "+f"(c[2]), "+f"(c[3])
                 : "r"(a[0]), "r"(a[1]), "r"(a[2]), "r"(a[3]),
                   "r"(b[0]), "r"(b[1]));
}
__device__ __forceinline__ void cpasync16(uint32_t dst, const void* src) {
    asm volatile("cp.async.cg.shared.global [%0], [%1], 16;" :: "r"(dst), "l"(src));
}
#define CP_COMMIT() asm volatile("cp.async.commit_group;")
#define CP_WAIT(N)  asm volatile("cp.async.wait_group %0;" :: "n"(N))

// ---------------- round kernels ----------------
__global__ void round4(const float* __restrict__ x, __half* __restrict__ hi, int n)
{
    int i = (blockIdx.x * blockDim.x + threadIdx.x) * 4;
    if (i >= n) return;
    float4 v = *(const float4*)(x + i);
    __half2 h0 = __floats2half2_rn(v.x, v.y);
    __half2 h1 = __floats2half2_rn(v.z, v.w);
    uint2 hh;
    hh.x = *reinterpret_cast<uint32_t*>(&h0);
    hh.y = *reinterpret_cast<uint32_t*>(&h1);
    *(uint2*)(hi + i) = hh;
}

// W [K][N] f32 -> Th [N][K] f16 (rounded once)
__global__ void tround(const float* __restrict__ W,
                       __half* __restrict__ Th, int K, int N)
{
    __shared__ float t[32][33];
    const int tx = threadIdx.x, ty = threadIdx.y;
    const int n0 = blockIdx.x * 32, k0 = blockIdx.y * 32;
#pragma unroll
    for (int j = 0; j < 4; j++)
        t[ty + j * 8][tx] = W[(size_t)(k0 + ty + j * 8) * N + n0 + tx];
    __syncthreads();
#pragma unroll
    for (int j = 0; j < 4; j++) {
        float v = t[tx][ty + j * 8];
        int n = n0 + ty + j * 8, k = k0 + tx;
        Th[(size_t)n * K + k] = __float2half_rn(v);
    }
}

// ---------------- mask compaction (pad to 128 with -1) -----------------------
__global__ __launch_bounds__(1024)
void build_idx(const int* __restrict__ mask)
{
    __shared__ int wsum[32];
    __shared__ int totn;
    const int b = blockIdx.x, t = threadIdx.x;
    const int lane = t & 31, wid = t >> 5;
    int v0 = (mask[b * S_ + 2 * t]     != 0) ? 1 : 0;
    int v1 = (mask[b * S_ + 2 * t + 1] != 0) ? 1 : 0;
    int s = v0 + v1;
    int x = s;
#pragma unroll
    for (int o = 1; o < 32; o <<= 1) {
        int y = __shfl_up_sync(0xffffffffu, x, o);
        if (lane >= o) x += y;
    }
    if (lane == 31) wsum[wid] = x;
    __syncthreads();
    if (wid == 0) {
        int w = wsum[lane];
#pragma unroll
        for (int o = 1; o < 32; o <<= 1) {
            int y = __shfl_up_sync(0xffffffffu, w, o);
            if (lane >= o) w += y;
        }
        wsum[lane] = w;
        if (lane == 31) totn = w;
    }
    __syncthreads();
    int excl = x - s + (wid > 0 ? wsum[wid - 1] : 0);
    int* idx = g_idx + b * IDXP;
    if (v0) idx[excl] = 2 * t;
    if (v1) idx[excl + v0] = 2 * t + 1;
    __syncthreads();
    const int n = totn;
    if (t == 0) g_cnt[b] = n;
    const int npad = (n + 127) & ~127;
    for (int i = n + t; i < npad; i += 1024) idx[i] = -1;
}

// ---------------- pipelined tensor-core GEMM ---------------------------------
// 256 threads / 8 warps, 32x64 warp tiles (128x128 block), 2-stage cp.async.
// EPI=0: plain fp32 C + bias (out-proj)
// EPI=2: Q projection  (all rows, dst g_qh scaled 0.125)
// EPI=3: KV projection (gathered rows via g_idx, scatter k/v, skip pad rows)
#define GSTG 32768u
template<int EPI>
__global__ __launch_bounds__(256, 2)
void mma_gemm(const __half* __restrict__ Ah, const __half* __restrict__ Bth,
              const float* __restrict__ bias, float* __restrict__ C,
              int M, int N, int K)
{
    extern __shared__ char sm[];
    const uint32_t sb = (uint32_t)__cvta_generic_to_shared(sm);
    const int tid = threadIdx.x, lane = tid & 31, wid = tid >> 5;
    const int wm = wid >> 1, wn = wid & 1;
    const int bn = blockIdx.x * 128;

    int bm = 0, batch = 0;
    const int* idxb = nullptr;
    if (EPI == 3) {
        batch = blockIdx.y >> 4;
        const int mblk = blockIdx.y & 15;
        const int cnt = g_cnt[batch];
        if (mblk * 128 >= ((cnt + 127) & ~127)) return;   // dead CTA
        idxb = g_idx + batch * IDXP + mblk * 128;
    } else {
        bm = blockIdx.y * 128;
    }

    const int l_row0 = tid >> 3, l_ch = tid & 7;
    int rowabs[4];
    if (EPI == 3) {
#pragma unroll
        for (int i = 0; i < 4; i++) {
            int ix = idxb[l_row0 + i * 32];
            rowabs[i] = batch * S_ + (ix < 0 ? 0 : ix);
        }
    }

    float acc[2][8][4];
#pragma unroll
    for (int mi = 0; mi < 2; mi++)
#pragma unroll
        for (int nb = 0; nb < 8; nb++)
#pragma unroll
            for (int q = 0; q < 4; q++) acc[mi][nb][q] = 0.f;

    const int lr = (lane & 7) + ((lane >> 3) & 1) * 8;

    auto issue_stage = [&](int st, int kt) {
#pragma unroll
        for (int i = 0; i < 4; i++) {
            int row = l_row0 + i * 32;
            uint32_t soff = (uint32_t)st * GSTG + row * 128 + ((l_ch ^ (row & 7)) << 4);
            size_t ga = (EPI == 3)
                ? (size_t)rowabs[i] * K + kt + l_ch * 8
                : (size_t)(bm + row) * K + kt + l_ch * 8;
            size_t gb = (size_t)(bn + row) * K + kt + l_ch * 8;
            cpasync16(sb + soff,         Ah + ga);
            cpasync16(sb + 16384 + soff, Bth + gb);
        }
        CP_COMMIT();
    };

    issue_stage(0, 0);

    int t = 0;
    for (int kt = 0; kt < K; kt += 64, t++) {
        const int cur = t & 1;
        const bool more = (kt + 64 < K);
        if (more) { issue_stage(cur ^ 1, kt + 64); CP_WAIT(1); }
        else      { CP_WAIT(0); }
        __syncthreads();

        const uint32_t cb = sb + (uint32_t)cur * GSTG;
#pragma unroll
        for (int kk = 0; kk < 4; kk++) {
            const int lc = kk * 2 + (lane >> 4);
            uint32_t afh[2][4];
#pragma unroll
            for (int mi = 0; mi < 2; mi++) {
                int r = wm * 32 + mi * 16 + lr;
                uint32_t ad = cb + r * 128 + ((lc ^ (r & 7)) << 4);
                ldsm4(afh[mi], ad);
            }
            uint32_t bfh[8][2], t4[4];
#pragma unroll
            for (int g = 0; g < 4; g++) {
                int r = wn * 64 + g * 16 + lr;
                uint32_t ad = cb + 16384 + r * 128 + ((lc ^ (r & 7)) << 4);
                ldsm4(t4, ad);
                bfh[2*g][0] = t4[0]; bfh[2*g][1] = t4[2];
                bfh[2*g+1][0] = t4[1]; bfh[2*g+1][1] = t4[3];
            }
#pragma unroll
            for (int mi = 0; mi < 2; mi++)
#pragma unroll
                for (int nb = 0; nb < 8; nb++)
                    mma16816(acc[mi][nb], afh[mi], bfh[nb]);
        }
        __syncthreads();
    }

    // epilogue
#pragma unroll
    for (int mi = 0; mi < 2; mi++) {
        const int rloc = wm * 32 + mi * 16 + (lane >> 2);
#pragma unroll
        for (int nb = 0; nb < 8; nb++) {
            const int cc = bn + wn * 64 + nb * 8 + (lane & 3) * 2;
            const float b0 = bias[cc], b1 = bias[cc + 1];
#pragma unroll
            for (int hr = 0; hr < 2; hr++) {
                const int rl = rloc + hr * 8;
                float v0 = acc[mi][nb][hr * 2 + 0] + b0;
                float v1 = acc[mi][nb][hr * 2 + 1] + b1;
                if (EPI == 2) {
                    const int r = bm + rl;
                    const int bb = r >> 11, si = r & 2047;
                    const int hh = cc >> 6, dd = cc & 63;
                    v0 *= 0.125f; v1 *= 0.125f;
                    __half2 h2 = __floats2half2_rn(v0, v1);
                    size_t off = (((size_t)bb * H_ + hh) * S_ + si) * D_ + dd;
                    *(__half2*)(g_qh + off) = h2;
                } else if (EPI == 3) {
                    const int ix = idxb[rl];
                    if (ix >= 0) {
                        const int sec = cc >> 10, win = cc & 1023;
                        const int hh = win >> 6, dd = win & 63;
                        __half* dst = sec ? g_vh : g_kh;
                        __half2 h2 = __floats2half2_rn(v0, v1);
                        size_t off = (((size_t)batch * H_ + hh) * S_ + ix) * D_ + dd;
                        *(__half2*)(dst + off) = h2;
                    }
                } else {
                    const int r = bm + rl;
                    float2 v; v.x = v0; v.y = v1;
                    *(float2*)(C + (size_t)r * N + cc) = v;
                }
            }
        }
    }
}

// ---------------- flash attention over COMPACTED keys ------------------------
#define ASTAGE 16384
#define A_STG0 16384
#define A_MF   (A_STG0 + 2*ASTAGE)
#define ATTN_SMEM (A_MF + 2*64*4)

__global__ __launch_bounds__(128, 2)
void attn_mma()
{
    extern __shared__ char sm[];
    const uint32_t sb = (uint32_t)__cvta_generic_to_shared(sm);
    float* Mf = (float*)(sm + A_MF);   // [2][64]
    const int tid = threadIdx.x, lane = tid & 31, w = tid >> 5;
    const int qb = blockIdx.x * 128, bh = blockIdx.y;
    const int b = bh >> 4, h = bh & 15;
    const size_t base = (size_t)bh * S_ * D_;
    const int lr = (lane & 7) + ((lane >> 3) & 1) * 8;
    const int* idxb = g_idx + b * IDXP;
    const int nvalid = g_cnt[b];
    const int ntiles = (nvalid + 63) >> 6;

    auto issue_kv = [&](int st, int kt) {
        for (int i = tid; i < 512; i += 128) {
            int row = i >> 3, ch = i & 7;
            int src = idxb[kt + row];
            src = src < 0 ? 0 : src;
            uint32_t soff = A_STG0 + (uint32_t)st * ASTAGE + row * 128 + ((ch ^ (row & 7)) << 4);
            size_t g = base + (size_t)src * D_ + ch * 8;
            cpasync16(sb + soff,         g_kh + g);
            cpasync16(sb + soff + 8192,  g_vh + g);
        }
        if (tid < 64) Mf[st * 64 + tid] = (kt + tid < nvalid) ? 1.0f : 0.0f;
        CP_COMMIT();
    };

    issue_kv(0, 0);

    for (int i = tid; i < 1024; i += 128) {
        int row = i >> 3, ch = i & 7;
        uint32_t soff = row * 128 + ((ch ^ (row & 7)) << 4);
        size_t g = base + (size_t)(qb + row) * D_ + ch * 8;
        *(uint4*)(sm + soff) = *(const uint4*)(g_qh + g);
    }
    __syncthreads();

    uint32_t qfh[2][4][4];
#pragma unroll
    for (int mi = 0; mi < 2; mi++)
#pragma unroll
        for (int kk = 0; kk < 4; kk++) {
            int r = w * 32 + mi * 16 + lr;
            int c = kk * 2 + (lane >> 4);
            uint32_t ad = sb + r * 128 + ((c ^ (r & 7)) << 4);
            ldsm4(qfh[mi][kk], ad);
        }

    float O[2][8][4];
    float m_[2][2], l_[2][2];
#pragma unroll
    for (int mi = 0; mi < 2; mi++) {
#pragma unroll
        for (int nb = 0; nb < 8; nb++)
#pragma unroll
            for (int q = 0; q < 4; q++) O[mi][nb][q] = 0.f;
        m_[mi][0] = -1e30f; m_[mi][1] = -1e30f;
        l_[mi][0] = 0.f;    l_[mi][1] = 0.f;
    }

    for (int t = 0; t < ntiles; t++) {
        const int cur = t & 1;
        const bool more = (t + 1 < ntiles);
        if (more) { issue_kv(cur ^ 1, (t + 1) * 64); CP_WAIT(1); }
        else      { CP_WAIT(0); }
        __syncthreads();

        const uint32_t kb = sb + A_STG0 + (uint32_t)cur * ASTAGE;
        const float* mf = Mf + cur * 64;

        float S[2][8][4];
#pragma unroll
        for (int mi = 0; mi < 2; mi++)
#pragma unroll
            for (int nb = 0; nb < 8; nb++)
#pragma unroll
                for (int q = 0; q < 4; q++) S[mi][nb][q] = 0.f;
#pragma unroll
        for (int kk = 0; kk < 4; kk++) {
            const int lc = kk * 2 + (lane >> 4);
            uint32_t bfh[8][2], t4[4];
#pragma unroll
            for (int g = 0; g < 4; g++) {
                int r = g * 16 + lr;
                uint32_t ad = kb + r * 128 + ((lc ^ (r & 7)) << 4);
                ldsm4(t4, ad);
                bfh[2*g][0] = t4[0]; bfh[2*g][1] = t4[2];
                bfh[2*g+1][0] = t4[1]; bfh[2*g+1][1] = t4[3];
            }
#pragma unroll
            for (int mi = 0; mi < 2; mi++)
#pragma unroll
                for (int nb = 0; nb < 8; nb++)
                    mma16816(S[mi][nb], qfh[mi][kk], bfh[nb]);
        }

        float mk0[8], mk1[8];
#pragma unroll
        for (int nb = 0; nb < 8; nb++) {
            int c = nb * 8 + (lane & 3) * 2;
            mk0[nb] = mf[c]; mk1[nb] = mf[c + 1];
        }
#pragma unroll
        for (int mi = 0; mi < 2; mi++) {
            float mx0 = -1e30f, mx1 = -1e30f;
#pragma unroll
            for (int nb = 0; nb < 8; nb++) {
                S[mi][nb][0] = (mk0[nb] != 0.f) ? S[mi][nb][0] : -1e30f;
                S[mi][nb][1] = (mk1[nb] != 0.f) ? S[mi][nb][1] : -1e30f;
                S[mi][nb][2] = (mk0[nb] != 0.f) ? S[mi][nb][2] : -1e30f;
                S[mi][nb][3] = (mk1[nb] != 0.f) ? S[mi][nb][3] : -1e30f;
                mx0 = fmaxf(mx0, fmaxf(S[mi][nb][0], S[mi][nb][1]));
                mx1 = fmaxf(mx1, fmaxf(S[mi][nb][2], S[mi][nb][3]));
            }
            mx0 = fmaxf(mx0, __shfl_xor_sync(0xffffffffu, mx0, 1));
            mx0 = fmaxf(mx0, __shfl_xor_sync(0xffffffffu, mx0, 2));
            mx1 = fmaxf(mx1, __shfl_xor_sync(0xffffffffu, mx1, 1));
            mx1 = fmaxf(mx1, __shfl_xor_sync(0xffffffffu, mx1, 2));
            const float mn0 = fmaxf(m_[mi][0], mx0), mn1 = fmaxf(m_[mi][1], mx1);
            const float a0 = __expf(m_[mi][0] - mn0), a1 = __expf(m_[mi][1] - mn1);
            m_[mi][0] = mn0; m_[mi][1] = mn1;
            float s0 = 0.f, s1 = 0.f;
#pragma unroll
            for (int nb = 0; nb < 8; nb++) {
                float p0 = __expf(S[mi][nb][0] - mn0) * mk0[nb];
                float p1 = __expf(S[mi][nb][1] - mn0) * mk1[nb];
                float p2 = __expf(S[mi][nb][2] - mn1) * mk0[nb];
                float p3 = __expf(S[mi][nb][3] - mn1) * mk1[nb];
                S[mi][nb][0] = p0; S[mi][nb][1] = p1; S[mi][nb][2] = p2; S[mi][nb][3] = p3;
                s0 += p0 + p1; s1 += p2 + p3;
            }
            s0 += __shfl_xor_sync(0xffffffffu, s0, 1);
            s0 += __shfl_xor_sync(0xffffffffu, s0, 2);
            s1 += __shfl_xor_sync(0xffffffffu, s1, 1);
            s1 += __shfl_xor_sync(0xffffffffu, s1, 2);
            l_[mi][0] = l_[mi][0] * a0 + s0;
            l_[mi][1] = l_[mi][1] * a1 + s1;
#pragma unroll
            for (int nb = 0; nb < 8; nb++) {
                O[mi][nb][0] *= a0; O[mi][nb][1] *= a0;
                O[mi][nb][2] *= a1; O[mi][nb][3] *= a1;
            }
        }

#pragma unroll
        for (int kk = 0; kk < 4; kk++) {
            uint32_t ph[2][4];
#pragma unroll
            for (int mi = 0; mi < 2; mi++) {
                __half2 t0 = __floats2half2_rn(S[mi][2*kk][0],   S[mi][2*kk][1]);
                __half2 t1 = __floats2half2_rn(S[mi][2*kk][2],   S[mi][2*kk][3]);
                __half2 t2 = __floats2half2_rn(S[mi][2*kk+1][0], S[mi][2*kk+1][1]);
                __half2 t3 = __floats2half2_rn(S[mi][2*kk+1][2], S[mi][2*kk+1][3]);
                ph[mi][0] = *reinterpret_cast<uint32_t*>(&t0);
                ph[mi][1] = *reinterpret_cast<uint32_t*>(&t1);
                ph[mi][2] = *reinterpret_cast<uint32_t*>(&t2);
                ph[mi][3] = *reinterpret_cast<uint32_t*>(&t3);
            }
            uint32_t vfh[8][2], t4[4];
#pragma unroll
            for (int g = 0; g < 4; g++) {
                int r = kk * 16 + lr;
                int c = g * 2 + (lane >> 4);
                uint32_t ad = kb + 8192 + r * 128 + ((c ^ (r & 7)) << 4);
                ldsm4t(t4, ad);
                vfh[2*g][0] = t4[0]; vfh[2*g][1] = t4[1];
                vfh[2*g+1][0] = t4[2]; vfh[2*g+1][1] = t4[3];
            }
#pragma unroll
            for (int mi = 0; mi < 2; mi++)
#pragma unroll
                for (int nb = 0; nb < 8; nb++)
                    mma16816(O[mi][nb], ph[mi], vfh[nb]);
        }
        __syncthreads();
    }

#pragma unroll
    for (int mi = 0; mi < 2; mi++) {
        const float inv0 = 1.0f / l_[mi][0], inv1 = 1.0f / l_[mi][1];
        const int s0r = qb + w * 32 + mi * 16 + (lane >> 2);
#pragma unroll
        for (int nb = 0; nb < 8; nb++) {
            const int d = nb * 8 + (lane & 3) * 2;
            size_t off = ((size_t)b * S_ + s0r) * E_ + h * 64 + d;
            __half2 h2 = __floats2half2_rn(O[mi][nb][0] * inv0, O[mi][nb][1] * inv0);
            *(__half2*)(g_ah + off) = h2;
            off += (size_t)8 * E_;
            h2 = __floats2half2_rn(O[mi][nb][2] * inv1, O[mi][nb][3] * inv1);
            *(__half2*)(g_ah + off) = h2;
        }
    }
}

// ---------------------------------------------------------------------------
extern "C" void kernel_launch(void* const* d_in, const int* in_sizes, int n_in,
                              void* d_out, int out_size)
{
    const float* hidden = (const float*)d_in[0];
    const float* qkv_w  = (const float*)d_in[1];
    const float* qkv_b  = (const float*)d_in[2];
    const float* wo_w   = (const float*)d_in[3];
    const float* wo_b   = (const float*)d_in[4];
    const int*   mask   = (const int*)d_in[5];
    float* out = (float*)d_out;

    __half *hidh, *wqh, *woh, *ah;
    cudaGetSymbolAddress((void**)&hidh, g_hidh);
    cudaGetSymbolAddress((void**)&wqh,  g_wqh);
    cudaGetSymbolAddress((void**)&woh,  g_woh);
    cudaGetSymbolAddress((void**)&ah,   g_ah);

    cudaFuncSetAttribute(mma_gemm<0>, cudaFuncAttributeMaxDynamicSharedMemorySize, (int)(2*GSTG));
    cudaFuncSetAttribute(mma_gemm<2>, cudaFuncAttributeMaxDynamicSharedMemorySize, (int)(2*GSTG));
    cudaFuncSetAttribute(mma_gemm<3>, cudaFuncAttributeMaxDynamicSharedMemorySize, (int)(2*GSTG));
    cudaFuncSetAttribute(attn_mma,    cudaFuncAttributeMaxDynamicSharedMemorySize, ATTN_SMEM);

    // 1) roundings + mask compaction
    round4<<<(M_ * E_) / 4 / 256, 256>>>(hidden, hidh, M_ * E_);
    tround<<<dim3(E3_ / 32, E_ / 32), dim3(32, 8)>>>(qkv_w, wqh, E_, E3_);
    tround<<<dim3(E_ / 32, E_ / 32),  dim3(32, 8)>>>(wo_w,  woh, E_, E_);
    build_idx<<<B_, 1024>>>(mask);

    // 2a) Q projection: all rows, N=1024
    mma_gemm<2><<<dim3(E_ / 128, M_ / 128), 256, 2*GSTG>>>(
        hidh, wqh, qkv_b, nullptr, M_, E_, E_);

    // 2b) KV projection: gathered valid rows only, N=2048
    mma_gemm<3><<<dim3(2048 / 128, B_ * 16), 256, 2*GSTG>>>(
        hidh, wqh + (size_t)E_ * E_, qkv_b + E_, nullptr, M_, 2048, E_);

    // 3) attention over compacted keys
    attn_mma<<<dim3(S_ / 128, BH_), 128, ATTN_SMEM>>>();

    // 4) output projection (1-term f16)
    mma_gemm<0><<<dim3(E_ / 128, M_ / 128), 256, 2*GSTG>>>(
        ah, woh, wo_b, out, M_, E_, E_);
}

// round 17
// speedup vs baseline: 3.6655x; 1.0189x over previous
#include <cuda_runtime.h>
#include <cuda_fp16.h>
#include <math.h>
#include <stdint.h>

#define B_ 4
#define S_ 2048
#define H_ 16
#define D_ 64
#define E_ 1024
#define E3_ 3072
#define BH_ (B_*H_)
#define M_ (B_*S_)   // 8192
#define IDXP (S_+128)

// ---------------- device-global scratch (allocation-free rule) ----------------
__device__ __half g_hidh[M_*E_];                     // hidden rounded once
__device__ __half g_wqh[E3_*E_];                     // qkv_w^T rounded [N][K]
__device__ __half g_woh[E_*E_];                      // wo_w^T rounded  [N][K]
__device__ __half g_qh[BH_*S_*D_];                   // q rounded (pre-scaled 0.125)
__device__ __half g_kh[BH_*S_*D_];                   // k rounded (valid rows only)
__device__ __half g_vh[BH_*S_*D_];                   // v rounded (valid rows only)
__device__ __half g_ah[M_*E_];                       // attn out rounded
__device__ int    g_idx[B_*IDXP];                    // compacted valid-key indices (-1 pad)
__device__ int    g_cnt[B_];                         // valid-key counts

// ---------------- helpers ----------------
__device__ __forceinline__ void ldsm4(uint32_t* r, uint32_t addr) {
    asm volatile("ldmatrix.sync.aligned.m8n8.x4.shared.b16 {%0,%1,%2,%3}, [%4];"
                 : "=r"(r[0]), "=r"(r[1]), "=r"(r[2]), "=r"(r[3]) : "r"(addr));
}
__device__ __forceinline__ void ldsm4t(uint32_t* r, uint32_t addr) {
    asm volatile("ldmatrix.sync.aligned.m8n8.x4.trans.shared.b16 {%0,%1,%2,%3}, [%4];"
                 : "=r"(r[0]), "=r"(r[1]), "=r"(r[2]), "=r"(r[3]) : "r"(addr));
}
__device__ __forceinline__ void mma16816(float* c, const uint32_t* a, const uint32_t* b) {
    asm volatile("mma.sync.aligned.m16n8k16.row.col.f32.f16.f16.f32 "
                 "{%0,%1,%2,%3}, {%4,%5,%6,%7}, {%8,%9}, {%0,%1,%2,%3};"
                 : "+f"(c[0]), "+f"(c[1]), "+f"(c[2]), "+f"(c[3])
                 : "r"(a[0]), "r"(a[1]), "r"(a[2]), "r"(a[3]),
                   "r"(b[0]), "r"(b[1]));
}
__device__ __forceinline__ void cpasync16(uint32_t dst, const void* src) {
    asm volatile("cp.async.cg.shared.global [%0], [%1], 16;" :: "r"(dst), "l"(src));
}
#define CP_COMMIT() asm volatile("cp.async.commit_group;")
#define CP_WAIT(N)  asm volatile("cp.async.wait_group %0;" :: "n"(N))

// ---------------- round kernels ----------------
__global__ void round4(const float* __restrict__ x, __half* __restrict__ hi, int n)
{
    int i = (blockIdx.x * blockDim.x + threadIdx.x) * 4;
    if (i >= n) return;
    float4 v = *(const float4*)(x + i);
    __half2 h0 = __floats2half2_rn(v.x, v.y);
    __half2 h1 = __floats2half2_rn(v.z, v.w);
    uint2 hh;
    hh.x = *reinterpret_cast<uint32_t*>(&h0);
    hh.y = *reinterpret_cast<uint32_t*>(&h1);
    *(uint2*)(hi + i) = hh;
}

// W [K][N] f32 -> Th [N][K] f16 (rounded once)
__global__ void tround(const float* __restrict__ W,
                       __half* __restrict__ Th, int K, int N)
{
    __shared__ float t[32][33];
    const int tx = threadIdx.x, ty = threadIdx.y;
    const int n0 = blockIdx.x * 32, k0 = blockIdx.y * 32;
#pragma unroll
    for (int j = 0; j < 4; j++)
        t[ty + j * 8][tx] = W[(size_t)(k0 + ty + j * 8) * N + n0 + tx];
    __syncthreads();
#pragma unroll
    for (int j = 0; j < 4; j++) {
        float v = t[tx][ty + j * 8];
        int n = n0 + ty + j * 8, k = k0 + tx;
        Th[(size_t)n * K + k] = __float2half_rn(v);
    }
}

// ---------------- mask compaction (pad to 128 with -1) -----------------------
__global__ __launch_bounds__(1024)
void build_idx(const int* __restrict__ mask)
{
    __shared__ int wsum[32];
    __shared__ int totn;
    const int b = blockIdx.x, t = threadIdx.x;
    const int lane = t & 31, wid = t >> 5;
    int v0 = (mask[b * S_ + 2 * t]     != 0) ? 1 : 0;
    int v1 = (mask[b * S_ + 2 * t + 1] != 0) ? 1 : 0;
    int s = v0 + v1;
    int x = s;
#pragma unroll
    for (int o = 1; o < 32; o <<= 1) {
        int y = __shfl_up_sync(0xffffffffu, x, o);
        if (lane >= o) x += y;
    }
    if (lane == 31) wsum[wid] = x;
    __syncthreads();
    if (wid == 0) {
        int w = wsum[lane];
#pragma unroll
        for (int o = 1; o < 32; o <<= 1) {
            int y = __shfl_up_sync(0xffffffffu, w, o);
            if (lane >= o) w += y;
        }
        wsum[lane] = w;
        if (lane == 31) totn = w;
    }
    __syncthreads();
    int excl = x - s + (wid > 0 ? wsum[wid - 1] : 0);
    int* idx = g_idx + b * IDXP;
    if (v0) idx[excl] = 2 * t;
    if (v1) idx[excl + v0] = 2 * t + 1;
    __syncthreads();
    const int n = totn;
    if (t == 0) g_cnt[b] = n;
    const int npad = (n + 127) & ~127;
    for (int i = n + t; i < npad; i += 1024) idx[i] = -1;
}

// ---------------- pipelined tensor-core GEMM ---------------------------------
// 256 threads / 8 warps, 32x64 warp tiles (128x128 block), 2-stage cp.async.
// EPI=0: plain fp32 C + bias (out-proj)
// EPI=4: merged QKV projection over N=3072:
//        bn<1024  -> Q path  (dense rows, all 8192; store g_qh scaled 0.125)
//        bn>=1024 -> KV path (gathered rows via g_idx; scatter k/v; pad skip)
#define GSTG 32768u
template<int EPI>
__global__ __launch_bounds__(256, 2)
void mma_gemm(const __half* __restrict__ Ah, const __half* __restrict__ Bth,
              const float* __restrict__ bias, float* __restrict__ C,
              int M, int N, int K)
{
    extern __shared__ char sm[];
    const uint32_t sb = (uint32_t)__cvta_generic_to_shared(sm);
    const int tid = threadIdx.x, lane = tid & 31, wid = tid >> 5;
    const int wm = wid >> 1, wn = wid & 1;
    const int bn = blockIdx.x * 128;

    int bm = 0, batch = 0;
    bool gather = false;
    const int* idxb = nullptr;
    if (EPI == 4) {
        if (bn < 1024) {
            bm = blockIdx.y * 128;
        } else {
            gather = true;
            batch = blockIdx.y >> 4;
            const int mblk = blockIdx.y & 15;
            const int cnt = g_cnt[batch];
            if (mblk * 128 >= ((cnt + 127) & ~127)) return;   // dead CTA
            idxb = g_idx + batch * IDXP + mblk * 128;
        }
    } else {
        bm = blockIdx.y * 128;
    }

    const int l_row0 = tid >> 3, l_ch = tid & 7;
    int rowabs[4];
#pragma unroll
    for (int i = 0; i < 4; i++) {
        if (gather) {
            int ix = idxb[l_row0 + i * 32];
            rowabs[i] = batch * S_ + (ix < 0 ? 0 : ix);
        } else {
            rowabs[i] = bm + l_row0 + i * 32;
        }
    }

    float acc[2][8][4];
#pragma unroll
    for (int mi = 0; mi < 2; mi++)
#pragma unroll
        for (int nb = 0; nb < 8; nb++)
#pragma unroll
            for (int q = 0; q < 4; q++) acc[mi][nb][q] = 0.f;

    const int lr = (lane & 7) + ((lane >> 3) & 1) * 8;

    auto issue_stage = [&](int st, int kt) {
#pragma unroll
        for (int i = 0; i < 4; i++) {
            int row = l_row0 + i * 32;
            uint32_t soff = (uint32_t)st * GSTG + row * 128 + ((l_ch ^ (row & 7)) << 4);
            size_t ga = (size_t)rowabs[i] * K + kt + l_ch * 8;
            size_t gb = (size_t)(bn + row) * K + kt + l_ch * 8;
            cpasync16(sb + soff,         Ah + ga);
            cpasync16(sb + 16384 + soff, Bth + gb);
        }
        CP_COMMIT();
    };

    issue_stage(0, 0);

    int t = 0;
    for (int kt = 0; kt < K; kt += 64, t++) {
        const int cur = t & 1;
        const bool more = (kt + 64 < K);
        if (more) { issue_stage(cur ^ 1, kt + 64); CP_WAIT(1); }
        else      { CP_WAIT(0); }
        __syncthreads();

        const uint32_t cb = sb + (uint32_t)cur * GSTG;
#pragma unroll
        for (int kk = 0; kk < 4; kk++) {
            const int lc = kk * 2 + (lane >> 4);
            uint32_t afh[2][4];
#pragma unroll
            for (int mi = 0; mi < 2; mi++) {
                int r = wm * 32 + mi * 16 + lr;
                uint32_t ad = cb + r * 128 + ((lc ^ (r & 7)) << 4);
                ldsm4(afh[mi], ad);
            }
            uint32_t bfh[8][2], t4[4];
#pragma unroll
            for (int g = 0; g < 4; g++) {
                int r = wn * 64 + g * 16 + lr;
                uint32_t ad = cb + 16384 + r * 128 + ((lc ^ (r & 7)) << 4);
                ldsm4(t4, ad);
                bfh[2*g][0] = t4[0]; bfh[2*g][1] = t4[2];
                bfh[2*g+1][0] = t4[1]; bfh[2*g+1][1] = t4[3];
            }
#pragma unroll
            for (int mi = 0; mi < 2; mi++)
#pragma unroll
                for (int nb = 0; nb < 8; nb++)
                    mma16816(acc[mi][nb], afh[mi], bfh[nb]);
        }
        __syncthreads();
    }

    // epilogue
#pragma unroll
    for (int mi = 0; mi < 2; mi++) {
        const int rloc = wm * 32 + mi * 16 + (lane >> 2);
#pragma unroll
        for (int nb = 0; nb < 8; nb++) {
            const int cc = bn + wn * 64 + nb * 8 + (lane & 3) * 2;
            const float b0 = bias[cc], b1 = bias[cc + 1];
#pragma unroll
            for (int hr = 0; hr < 2; hr++) {
                const int rl = rloc + hr * 8;
                float v0 = acc[mi][nb][hr * 2 + 0] + b0;
                float v1 = acc[mi][nb][hr * 2 + 1] + b1;
                if (EPI == 4) {
                    if (bn < 1024) {            // Q path
                        const int r = bm + rl;
                        const int bb = r >> 11, si = r & 2047;
                        const int hh = cc >> 6, dd = cc & 63;
                        v0 *= 0.125f; v1 *= 0.125f;
                        __half2 h2 = __floats2half2_rn(v0, v1);
                        size_t off = (((size_t)bb * H_ + hh) * S_ + si) * D_ + dd;
                        *(__half2*)(g_qh + off) = h2;
                    } else {                    // KV path
                        const int ix = idxb[rl];
                        if (ix >= 0) {
                            const int win0 = cc - 1024;
                            const int sec = win0 >> 10, win = win0 & 1023;
                            const int hh = win >> 6, dd = win & 63;
                            __half* dst = sec ? g_vh : g_kh;
                            __half2 h2 = __floats2half2_rn(v0, v1);
                            size_t off = (((size_t)batch * H_ + hh) * S_ + ix) * D_ + dd;
                            *(__half2*)(dst + off) = h2;
                        }
                    }
                } else {
                    const int r = bm + rl;
                    float2 v; v.x = v0; v.y = v1;
                    *(float2*)(C + (size_t)r * N + cc) = v;
                }
            }
        }
    }
}

// ---------------- flash attention over COMPACTED keys ------------------------
#define ASTAGE 16384
#define A_STG0 16384
#define A_MF   (A_STG0 + 2*ASTAGE)
#define ATTN_SMEM (A_MF + 2*64*4)

__global__ __launch_bounds__(128, 2)
void attn_mma()
{
    extern __shared__ char sm[];
    const uint32_t sb = (uint32_t)__cvta_generic_to_shared(sm);
    float* Mf = (float*)(sm + A_MF);   // [2][64]
    const int tid = threadIdx.x, lane = tid & 31, w = tid >> 5;
    const int qb = blockIdx.x * 128, bh = blockIdx.y;
    const int b = bh >> 4, h = bh & 15;
    const size_t base = (size_t)bh * S_ * D_;
    const int lr = (lane & 7) + ((lane >> 3) & 1) * 8;
    const int* idxb = g_idx + b * IDXP;
    const int nvalid = g_cnt[b];
    const int ntiles = (nvalid + 63) >> 6;

    auto issue_kv = [&](int st, int kt) {
        for (int i = tid; i < 512; i += 128) {
            int row = i >> 3, ch = i & 7;
            int src = idxb[kt + row];
            src = src < 0 ? 0 : src;
            uint32_t soff = A_STG0 + (uint32_t)st * ASTAGE + row * 128 + ((ch ^ (row & 7)) << 4);
            size_t g = base + (size_t)src * D_ + ch * 8;
            cpasync16(sb + soff,         g_kh + g);
            cpasync16(sb + soff + 8192,  g_vh + g);
        }
        if (tid < 64) Mf[st * 64 + tid] = (kt + tid < nvalid) ? 1.0f : 0.0f;
        CP_COMMIT();
    };

    issue_kv(0, 0);

    for (int i = tid; i < 1024; i += 128) {
        int row = i >> 3, ch = i & 7;
        uint32_t soff = row * 128 + ((ch ^ (row & 7)) << 4);
        size_t g = base + (size_t)(qb + row) * D_ + ch * 8;
        *(uint4*)(sm + soff) = *(const uint4*)(g_qh + g);
    }
    __syncthreads();

    uint32_t qfh[2][4][4];
#pragma unroll
    for (int mi = 0; mi < 2; mi++)
#pragma unroll
        for (int kk = 0; kk < 4; kk++) {
            int r = w * 32 + mi * 16 + lr;
            int c = kk * 2 + (lane >> 4);
            uint32_t ad = sb + r * 128 + ((c ^ (r & 7)) << 4);
            ldsm4(qfh[mi][kk], ad);
        }

    float O[2][8][4];
    float m_[2][2], l_[2][2];
#pragma unroll
    for (int mi = 0; mi < 2; mi++) {
#pragma unroll
        for (int nb = 0; nb < 8; nb++)
#pragma unroll
            for (int q = 0; q < 4; q++) O[mi][nb][q] = 0.f;
        m_[mi][0] = -1e30f; m_[mi][1] = -1e30f;
        l_[mi][0] = 0.f;    l_[mi][1] = 0.f;
    }

    for (int t = 0; t < ntiles; t++) {
        const int cur = t & 1;
        const bool more = (t + 1 < ntiles);
        if (more) { issue_kv(cur ^ 1, (t + 1) * 64); CP_WAIT(1); }
        else      { CP_WAIT(0); }
        __syncthreads();

        const uint32_t kb = sb + A_STG0 + (uint32_t)cur * ASTAGE;
        const float* mf = Mf + cur * 64;

        float S[2][8][4];
#pragma unroll
        for (int mi = 0; mi < 2; mi++)
#pragma unroll
            for (int nb = 0; nb < 8; nb++)
#pragma unroll
                for (int q = 0; q < 4; q++) S[mi][nb][q] = 0.f;
#pragma unroll
        for (int kk = 0; kk < 4; kk++) {
            const int lc = kk * 2 + (lane >> 4);
            uint32_t bfh[8][2], t4[4];
#pragma unroll
            for (int g = 0; g < 4; g++) {
                int r = g * 16 + lr;
                uint32_t ad = kb + r * 128 + ((lc ^ (r & 7)) << 4);
                ldsm4(t4, ad);
                bfh[2*g][0] = t4[0]; bfh[2*g][1] = t4[2];
                bfh[2*g+1][0] = t4[1]; bfh[2*g+1][1] = t4[3];
            }
#pragma unroll
            for (int mi = 0; mi < 2; mi++)
#pragma unroll
                for (int nb = 0; nb < 8; nb++)
                    mma16816(S[mi][nb], qfh[mi][kk], bfh[nb]);
        }

        float mk0[8], mk1[8];
#pragma unroll
        for (int nb = 0; nb < 8; nb++) {
            int c = nb * 8 + (lane & 3) * 2;
            mk0[nb] = mf[c]; mk1[nb] = mf[c + 1];
        }
#pragma unroll
        for (int mi = 0; mi < 2; mi++) {
            float mx0 = -1e30f, mx1 = -1e30f;
#pragma unroll
            for (int nb = 0; nb < 8; nb++) {
                S[mi][nb][0] = (mk0[nb] != 0.f) ? S[mi][nb][0] : -1e30f;
                S[mi][nb][1] = (mk1[nb] != 0.f) ? S[mi][nb][1] : -1e30f;
                S[mi][nb][2] = (mk0[nb] != 0.f) ? S[mi][nb][2] : -1e30f;
                S[mi][nb][3] = (mk1[nb] != 0.f) ? S[mi][nb][3] : -1e30f;
                mx0 = fmaxf(mx0, fmaxf(S[mi][nb][0], S[mi][nb][1]));
                mx1 = fmaxf(mx1, fmaxf(S[mi][nb][2], S[mi][nb][3]));
            }
            mx0 = fmaxf(mx0, __shfl_xor_sync(0xffffffffu, mx0, 1));
            mx0 = fmaxf(mx0, __shfl_xor_sync(0xffffffffu, mx0, 2));
            mx1 = fmaxf(mx1, __shfl_xor_sync(0xffffffffu, mx1, 1));
            mx1 = fmaxf(mx1, __shfl_xor_sync(0xffffffffu, mx1, 2));
            const float mn0 = fmaxf(m_[mi][0], mx0), mn1 = fmaxf(m_[mi][1], mx1);
            const float a0 = __expf(m_[mi][0] - mn0), a1 = __expf(m_[mi][1] - mn1);
            m_[mi][0] = mn0; m_[mi][1] = mn1;
            float s0 = 0.f, s1 = 0.f;
#pragma unroll
            for (int nb = 0; nb < 8; nb++) {
                float p0 = __expf(S[mi][nb][0] - mn0) * mk0[nb];
                float p1 = __expf(S[mi][nb][1] - mn0) * mk1[nb];
                float p2 = __expf(S[mi][nb][2] - mn1) * mk0[nb];
                float p3 = __expf(S[mi][nb][3] - mn1) * mk1[nb];
                S[mi][nb][0] = p0; S[mi][nb][1] = p1; S[mi][nb][2] = p2; S[mi][nb][3] = p3;
                s0 += p0 + p1; s1 += p2 + p3;
            }
            s0 += __shfl_xor_sync(0xffffffffu, s0, 1);
            s0 += __shfl_xor_sync(0xffffffffu, s0, 2);
            s1 += __shfl_xor_sync(0xffffffffu, s1, 1);
            s1 += __shfl_xor_sync(0xffffffffu, s1, 2);
            l_[mi][0] = l_[mi][0] * a0 + s0;
            l_[mi][1] = l_[mi][1] * a1 + s1;
#pragma unroll
            for (int nb = 0; nb < 8; nb++) {
                O[mi][nb][0] *= a0; O[mi][nb][1] *= a0;
                O[mi][nb][2] *= a1; O[mi][nb][3] *= a1;
            }
        }

#pragma unroll
        for (int kk = 0; kk < 4; kk++) {
            uint32_t ph[2][4];
#pragma unroll
            for (int mi = 0; mi < 2; mi++) {
                __half2 t0 = __floats2half2_rn(S[mi][2*kk][0],   S[mi][2*kk][1]);
                __half2 t1 = __floats2half2_rn(S[mi][2*kk][2],   S[mi][2*kk][3]);
                __half2 t2 = __floats2half2_rn(S[mi][2*kk+1][0], S[mi][2*kk+1][1]);
                __half2 t3 = __floats2half2_rn(S[mi][2*kk+1][2], S[mi][2*kk+1][3]);
                ph[mi][0] = *reinterpret_cast<uint32_t*>(&t0);
                ph[mi][1] = *reinterpret_cast<uint32_t*>(&t1);
                ph[mi][2] = *reinterpret_cast<uint32_t*>(&t2);
                ph[mi][3] = *reinterpret_cast<uint32_t*>(&t3);
            }
            uint32_t vfh[8][2], t4[4];
#pragma unroll
            for (int g = 0; g < 4; g++) {
                int r = kk * 16 + lr;
                int c = g * 2 + (lane >> 4);
                uint32_t ad = kb + 8192 + r * 128 + ((c ^ (r & 7)) << 4);
                ldsm4t(t4, ad);
                vfh[2*g][0] = t4[0]; vfh[2*g][1] = t4[1];
                vfh[2*g+1][0] = t4[2]; vfh[2*g+1][1] = t4[3];
            }
#pragma unroll
            for (int mi = 0; mi < 2; mi++)
#pragma unroll
                for (int nb = 0; nb < 8; nb++)
                    mma16816(O[mi][nb], ph[mi], vfh[nb]);
        }
        __syncthreads();
    }

#pragma unroll
    for (int mi = 0; mi < 2; mi++) {
        const float inv0 = 1.0f / l_[mi][0], inv1 = 1.0f / l_[mi][1];
        const int s0r = qb + w * 32 + mi * 16 + (lane >> 2);
#pragma unroll
        for (int nb = 0; nb < 8; nb++) {
            const int d = nb * 8 + (lane & 3) * 2;
            size_t off = ((size_t)b * S_ + s0r) * E_ + h * 64 + d;
            __half2 h2 = __floats2half2_rn(O[mi][nb][0] * inv0, O[mi][nb][1] * inv0);
            *(__half2*)(g_ah + off) = h2;
            off += (size_t)8 * E_;
            h2 = __floats2half2_rn(O[mi][nb][2] * inv1, O[mi][nb][3] * inv1);
            *(__half2*)(g_ah + off) = h2;
        }
    }
}

// ---------------------------------------------------------------------------
extern "C" void kernel_launch(void* const* d_in, const int* in_sizes, int n_in,
                              void* d_out, int out_size)
{
    const float* hidden = (const float*)d_in[0];
    const float* qkv_w  = (const float*)d_in[1];
    const float* qkv_b  = (const float*)d_in[2];
    const float* wo_w   = (const float*)d_in[3];
    const float* wo_b   = (const float*)d_in[4];
    const int*   mask   = (const int*)d_in[5];
    float* out = (float*)d_out;

    __half *hidh, *wqh, *woh, *ah;
    cudaGetSymbolAddress((void**)&hidh, g_hidh);
    cudaGetSymbolAddress((void**)&wqh,  g_wqh);
    cudaGetSymbolAddress((void**)&woh,  g_woh);
    cudaGetSymbolAddress((void**)&ah,   g_ah);

    cudaFuncSetAttribute(mma_gemm<0>, cudaFuncAttributeMaxDynamicSharedMemorySize, (int)(2*GSTG));
    cudaFuncSetAttribute(mma_gemm<4>, cudaFuncAttributeMaxDynamicSharedMemorySize, (int)(2*GSTG));
    cudaFuncSetAttribute(attn_mma,    cudaFuncAttributeMaxDynamicSharedMemorySize, ATTN_SMEM);

    // 1) roundings + mask compaction
    round4<<<(M_ * E_) / 4 / 256, 256>>>(hidden, hidh, M_ * E_);
    tround<<<dim3(E3_ / 32, E_ / 32), dim3(32, 8)>>>(qkv_w, wqh, E_, E3_);
    tround<<<dim3(E_ / 32, E_ / 32),  dim3(32, 8)>>>(wo_w,  woh, E_, E_);
    build_idx<<<B_, 1024>>>(mask);

    // 2) merged QKV projection: Q dense + KV gathered, one launch
    mma_gemm<4><<<dim3(E3_ / 128, 64), 256, 2*GSTG>>>(
        hidh, wqh, qkv_b, nullptr, M_, E3_, E_);

    // 3) attention over compacted keys
    attn_mma<<<dim3(S_ / 128, BH_), 128, ATTN_SMEM>>>();

    // 4) output projection (1-term f16)
    mma_gemm<0><<<dim3(E_ / 128, M_ / 128), 256, 2*GSTG>>>(
        ah, woh, wo_b, out, M_, E_, E_);
}